// round 11
// baseline (speedup 1.0000x reference)
#include <cuda_runtime.h>
#include <cuda_bf16.h>
#include <math.h>
#include <stdint.h>

// ---------------- problem constants ----------------
#define BB   2
#define SS   2048
#define HIDN 2048
#define NH   16
#define NKVH 8
#define DH   128
#define KVD  1024
#define WIN  128
#define TOPK 675
#define MTOT (BB * SS)
#define KDIM 2048
#define NQKV 4096

// ---------------- scratch ----------------
__device__ double g_meanp[8 * BB * HIDN];
__device__ float  g_mean[BB * HIDN];
__device__ double g_mnorm[BB];
__device__ float  g_score[BB * SS];
__device__ int    g_lm[BB * SS];

__device__ __nv_bfloat16 g_xh[MTOT * HIDN], g_xl[MTOT * HIDN];
__device__ __nv_bfloat16 g_qh[MTOT * HIDN], g_ql[MTOT * HIDN];
__device__ __nv_bfloat16 g_kh[MTOT * KVD],  g_kl[MTOT * KVD];
__device__ __nv_bfloat16 g_vh[MTOT * KVD],  g_vl[MTOT * KVD];
__device__ __nv_bfloat16 g_ah[MTOT * HIDN], g_al[MTOT * HIDN];
__device__ __nv_bfloat16 g_wch[NQKV * KDIM], g_wcl[NQKV * KDIM];
__device__ __nv_bfloat16 g_woh[HIDN * KDIM], g_wol[HIDN * KDIM];

// ---------------- PTX helpers ----------------
__device__ __forceinline__ uint32_t s2u(const void* p) {
    uint32_t a;
    asm("{ .reg .u64 t; cvta.to.shared.u64 t, %1; cvt.u32.u64 %0, t; }" : "=r"(a) : "l"(p));
    return a;
}
#define CP16(saddr, gptr) \
    asm volatile("cp.async.cg.shared.global [%0], [%1], 16;" :: "r"(saddr), "l"(gptr))
#define CP_COMMIT() asm volatile("cp.async.commit_group;" ::: "memory")
#define CP_WAIT(n)  asm volatile("cp.async.wait_group %0;" :: "n"(n) : "memory")

#define LDSM4(r0, r1, r2, r3, addr) \
    asm volatile("ldmatrix.sync.aligned.m8n8.x4.shared.b16 {%0,%1,%2,%3}, [%4];" \
                 : "=r"(r0), "=r"(r1), "=r"(r2), "=r"(r3) : "r"(addr))
#define LDSM4T(r0, r1, r2, r3, addr) \
    asm volatile("ldmatrix.sync.aligned.m8n8.x4.trans.shared.b16 {%0,%1,%2,%3}, [%4];" \
                 : "=r"(r0), "=r"(r1), "=r"(r2), "=r"(r3) : "r"(addr))

#define MMA16816(D, a0, a1, a2, a3, b0, b1) \
    asm volatile("mma.sync.aligned.m16n8k16.row.col.f32.bf16.bf16.f32 " \
                 "{%0,%1,%2,%3}, {%4,%5,%6,%7}, {%8,%9}, {%0,%1,%2,%3};" \
                 : "+f"((D)[0]), "+f"((D)[1]), "+f"((D)[2]), "+f"((D)[3]) \
                 : "r"(a0), "r"(a1), "r"(a2), "r"(a3), "r"(b0), "r"(b1))

__device__ __forceinline__ uint32_t pack_bf16(float lo, float hi) {
    uint32_t r;
    asm("cvt.rn.bf16x2.f32 %0, %1, %2;" : "=r"(r) : "f"(hi), "f"(lo));
    return r;
}
__device__ __forceinline__ void store_split2(__nv_bfloat16* Hp, __nv_bfloat16* Lp,
                                             float v0, float v1) {
    __nv_bfloat16 h0 = __float2bfloat16(v0), h1 = __float2bfloat16(v1);
    __nv_bfloat16 l0 = __float2bfloat16(v0 - __bfloat162float(h0));
    __nv_bfloat16 l1 = __float2bfloat16(v1 - __bfloat162float(h1));
    *(__nv_bfloat162*)Hp = __halves2bfloat162(h0, h1);
    *(__nv_bfloat162*)Lp = __halves2bfloat162(l0, l1);
}

// ---------------- mean stage 1 ----------------
__global__ void meanp_kernel(const float* __restrict__ x) {
    int f = blockIdx.x * 256 + threadIdx.x;
    int b = blockIdx.y, ch = blockIdx.z;
    const float* p = x + ((size_t)b * SS + (size_t)ch * 256) * HIDN + f;
    double a0 = 0, a1 = 0;
    for (int s = 0; s < 256; s += 2) {
        a0 += (double)p[(size_t)s * HIDN];
        a1 += (double)p[(size_t)(s + 1) * HIDN];
    }
    g_meanp[((size_t)ch * BB + b) * HIDN + f] = a0 + a1;
}

// ---------------- mean stage 2 fused with ||mean|| ----------------
__global__ void meanf_mnorm_kernel() {
    int b = blockIdx.x, tid = threadIdx.x;
    __shared__ double red[8];
    double acc = 0;
    for (int f = tid; f < HIDN; f += 256) {
        double t = 0;
        for (int ch = 0; ch < 8; ch++) t += g_meanp[((size_t)ch * BB + b) * HIDN + f];
        float m = (float)(t / (double)SS);
        g_mean[b * HIDN + f] = m;
        acc += (double)m * (double)m;
    }
    for (int off = 16; off > 0; off >>= 1)
        acc += __shfl_down_sync(0xffffffffu, acc, off);
    if ((tid & 31) == 0) red[tid >> 5] = acc;
    __syncthreads();
    if (tid == 0) {
        double t = 0;
        for (int w = 0; w < 8; w++) t += red[w];
        g_mnorm[b] = sqrt(t);
    }
}

// ---------------- score ----------------
__global__ void score_kernel(const float* __restrict__ x) {
    int row = blockIdx.x, b = blockIdx.y, tid = threadIdx.x;
    __shared__ double redn[8], redd[8];
    size_t roff = ((size_t)b * SS + row) * HIDN;
    const float* xr = x + roff;
    const float* mr = g_mean + b * HIDN;
    double n2 = 0, dt = 0;
    for (int c = tid; c < HIDN; c += 256) {
        float xv = xr[c];
        n2 += (double)xv * (double)xv;
        dt += (double)xv * (double)mr[c];
    }
    for (int off = 16; off > 0; off >>= 1) {
        n2 += __shfl_down_sync(0xffffffffu, n2, off);
        dt += __shfl_down_sync(0xffffffffu, dt, off);
    }
    if ((tid & 31) == 0) { redn[tid >> 5] = n2; redd[tid >> 5] = dt; }
    __syncthreads();
    if (tid == 0) {
        double tn = 0, td = 0;
        for (int w = 0; w < 8; w++) { tn += redn[w]; td += redd[w]; }
        double nrm = sqrt(tn);
        double div = -td / (nrm * g_mnorm[b] + 1e-6);
        g_score[b * SS + row] = (float)(0.7 * nrm + 0.3 * div);
    }
}

// ---------------- exact top-k (bitonic) + dilation ----------------
__global__ void topk_kernel() {
    int b = blockIdx.x, tid = threadIdx.x;
    __shared__ unsigned long long sd[SS];
    __shared__ unsigned char l0[SS], l1[SS];
    for (int i = tid; i < SS; i += 1024) {
        unsigned fb = __float_as_uint(g_score[b * SS + i]);
        unsigned key = (fb & 0x80000000u) ? ~fb : (fb | 0x80000000u);
        sd[i] = ((unsigned long long)key << 32) | (0xFFFFFFFFu - (unsigned)i);
    }
    __syncthreads();
    for (int k2 = 2; k2 <= SS; k2 <<= 1) {
        for (int j = k2 >> 1; j > 0; j >>= 1) {
            for (int i = tid; i < SS; i += 1024) {
                int ixj = i ^ j;
                if (ixj > i) {
                    bool asc = ((i & k2) == 0);
                    unsigned long long a = sd[i], c = sd[ixj];
                    if ((a > c) == asc) { sd[i] = c; sd[ixj] = a; }
                }
            }
            __syncthreads();
        }
    }
    unsigned long long kth = sd[SS - TOPK];
    __syncthreads();
    for (int i = tid; i < SS; i += 1024) {
        unsigned fb = __float_as_uint(g_score[b * SS + i]);
        unsigned key = (fb & 0x80000000u) ? ~fb : (fb | 0x80000000u);
        unsigned long long comp = ((unsigned long long)key << 32) | (0xFFFFFFFFu - (unsigned)i);
        l0[i] = (comp >= kth) ? 1 : 0;
    }
    __syncthreads();
    for (int i = tid; i < SS; i += 1024) {
        unsigned char v = l0[i];
        if (i > 0)      v |= l0[i - 1];
        if (i < SS - 1) v |= l0[i + 1];
        l1[i] = v;
    }
    __syncthreads();
    for (int i = tid; i < SS; i += 1024) {
        unsigned char v = l1[i];
        if (i > 0)      v |= l1[i - 1];
        if (i < SS - 1) v |= l1[i + 1];
        g_lm[b * SS + i] = (int)v;
    }
}

// ---------------- split fp32 -> (bf16 hi, bf16 lo) ----------------
__global__ void xsplit_kernel(const float* __restrict__ X,
                              __nv_bfloat16* __restrict__ Xh,
                              __nv_bfloat16* __restrict__ Xl) {
    int i = (blockIdx.x * 256 + threadIdx.x) * 4;
#pragma unroll
    for (int j = 0; j < 4; j++) {
        float v = X[i + j];
        __nv_bfloat16 h = __float2bfloat16(v);
        Xh[i + j] = h;
        Xl[i + j] = __float2bfloat16(v - __bfloat162float(h));
    }
}

// ---------------- fused transpose+split for all 4 weights; idle blocks zero out --
__global__ void wsplit_all_kernel(const float* __restrict__ W0, const float* __restrict__ W1,
                                  const float* __restrict__ W2, const float* __restrict__ W3,
                                  __nv_bfloat16* __restrict__ wch, __nv_bfloat16* __restrict__ wcl,
                                  __nv_bfloat16* __restrict__ woh, __nv_bfloat16* __restrict__ wol,
                                  float* __restrict__ out_zero)
{
    __shared__ float t[32][33];
    int z = blockIdx.z;
    const float* W; __nv_bfloat16 *Th, *Tl; int N;
    if (z == 0)      { W = W0; Th = wch;                          Tl = wcl;                          N = 2048; }
    else if (z == 1) { W = W1; Th = wch + (size_t)2048 * KDIM;    Tl = wcl + (size_t)2048 * KDIM;    N = 1024; }
    else if (z == 2) { W = W2; Th = wch + (size_t)3072 * KDIM;    Tl = wcl + (size_t)3072 * KDIM;    N = 1024; }
    else             { W = W3; Th = woh;                          Tl = wol;                          N = 2048; }
    int n0 = blockIdx.x * 32, k0 = blockIdx.y * 32;
    int tid1 = threadIdx.y * 32 + threadIdx.x;
    if (n0 >= N) {
        size_t id = ((((size_t)(z - 1) * (KDIM / 32) + blockIdx.y) * 32 + (blockIdx.x - 32)) * 256
                     + tid1) * 8;
        float4 zz = make_float4(0.f, 0.f, 0.f, 0.f);
        *(float4*)(out_zero + id)     = zz;
        *(float4*)(out_zero + id + 4) = zz;
        return;
    }
    int tx = threadIdx.x, ty = threadIdx.y;
#pragma unroll
    for (int i = 0; i < 32; i += 8)
        t[ty + i][tx] = W[(size_t)(k0 + ty + i) * N + n0 + tx];
    __syncthreads();
#pragma unroll
    for (int i = 0; i < 32; i += 8) {
        float v = t[tx][ty + i];
        __nv_bfloat16 h = __float2bfloat16(v);
        __nv_bfloat16 l = __float2bfloat16(v - __bfloat162float(h));
        size_t o = (size_t)(n0 + ty + i) * KDIM + k0 + tx;
        Th[o] = h;
        Tl[o] = l;
    }
}

// ---------------- mma.sync split GEMM (128x128, 3-stage) -----------
// MODE 0: fp32 atomicAdd (split-K via blockIdx.z). MODE 1: split bf16, QKV-routed.
// mbase: row offset (batch pipelining).
#define GBK 64
#define TILEB 16384u
#define BUFB  32768u
#define GEMM_SMEM_BYTES (3 * 32768 + 1024)

template<int NST>
__device__ __forceinline__ void load_tiles_async(
    int tid, int s, int m0, int n0, int koff,
    const __nv_bfloat16* __restrict__ Ah, const __nv_bfloat16* __restrict__ Al,
    const __nv_bfloat16* __restrict__ Bh, const __nv_bfloat16* __restrict__ Bl,
    uint32_t bufA)
{
    constexpr int SEGL = NST / 3;
    int seg = s / SEGL;
    int kk  = (s % SEGL) * GBK + koff;
    const __nv_bfloat16* Ap = (seg == 1) ? Al : Ah;
    const __nv_bfloat16* Bp = (seg == 2) ? Bl : Bh;
    uint32_t bufB = bufA + TILEB;
#pragma unroll
    for (int j = 0; j < 4; j++) {
        int id = tid + j * 256;
        int row = id >> 3, c = id & 7;
        uint32_t sw = (uint32_t)((row >> 3) * 1024 + (row & 7) * 128 + ((c ^ (row & 7)) << 4));
        CP16(bufA + sw, (const void*)(Ap + (size_t)(m0 + row) * KDIM + kk + c * 8));
        CP16(bufB + sw, (const void*)(Bp + (size_t)(n0 + row) * KDIM + kk + c * 8));
    }
}

template<int MODE, int NST>
__global__ void __launch_bounds__(256) gemm_kernel(
    const __nv_bfloat16* __restrict__ Ah, const __nv_bfloat16* __restrict__ Al,
    const __nv_bfloat16* __restrict__ Bh, const __nv_bfloat16* __restrict__ Bl,
    float* __restrict__ Cf,
    __nv_bfloat16* __restrict__ qh, __nv_bfloat16* __restrict__ ql,
    __nv_bfloat16* __restrict__ kh, __nv_bfloat16* __restrict__ kl,
    __nv_bfloat16* __restrict__ vh, __nv_bfloat16* __restrict__ vl,
    int mbase)
{
    extern __shared__ char dsm[];
    uint32_t tbase = (s2u(dsm) + 1023u) & ~1023u;

    int tid = threadIdx.x, lane = tid & 31, wid = tid >> 5;
    int wm = wid >> 2, wn = wid & 3;
    int m0 = blockIdx.y * 128 + mbase, n0 = blockIdx.x * 128;
    int koff = (int)blockIdx.z * ((NST / 3) * GBK);

    int aR = lane & 15, aC = lane >> 4;
    int bR = ((lane >> 4) << 3) + (lane & 7);
    int bC = (lane >> 3) & 1;

    uint32_t aOff[4]; int aSw[4];
#pragma unroll
    for (int f = 0; f < 4; f++) {
        int r = wm * 64 + f * 16 + aR;
        aOff[f] = (uint32_t)((r >> 3) * 1024 + (r & 7) * 128);
        aSw[f]  = r & 7;
    }
    uint32_t bOff[2]; int bSw[2];
#pragma unroll
    for (int g = 0; g < 2; g++) {
        int r = wn * 32 + g * 16 + bR;
        bOff[g] = (uint32_t)((r >> 3) * 1024 + (r & 7) * 128);
        bSw[g]  = r & 7;
    }

    float acc[4][4][4];
#pragma unroll
    for (int f = 0; f < 4; f++)
#pragma unroll
        for (int n8 = 0; n8 < 4; n8++)
#pragma unroll
            for (int e = 0; e < 4; e++) acc[f][n8][e] = 0.0f;

    load_tiles_async<NST>(tid, 0, m0, n0, koff, Ah, Al, Bh, Bl, tbase);
    CP_COMMIT();
    load_tiles_async<NST>(tid, 1, m0, n0, koff, Ah, Al, Bh, Bl, tbase + BUFB);
    CP_COMMIT();

    int bidx = 0, pre = 2;
    for (int s = 0; s < NST; s++) {
        if (s == NST - 1) { CP_WAIT(0); } else { CP_WAIT(1); }
        __syncthreads();
        if (s + 2 < NST) {
            load_tiles_async<NST>(tid, s + 2, m0, n0, koff, Ah, Al, Bh, Bl,
                                  tbase + (uint32_t)pre * BUFB);
            CP_COMMIT();
        }

        uint32_t bufA = tbase + (uint32_t)bidx * BUFB;
        uint32_t bufB = bufA + TILEB;
#pragma unroll
        for (int k16 = 0; k16 < 4; k16++) {
            int ca = k16 * 2 + aC, cb = k16 * 2 + bC;
            uint32_t a[4][4], b[2][4];
#pragma unroll
            for (int f = 0; f < 4; f++)
                LDSM4(a[f][0], a[f][1], a[f][2], a[f][3],
                      bufA + aOff[f] + (uint32_t)((ca ^ aSw[f]) << 4));
#pragma unroll
            for (int g = 0; g < 2; g++)
                LDSM4(b[g][0], b[g][1], b[g][2], b[g][3],
                      bufB + bOff[g] + (uint32_t)((cb ^ bSw[g]) << 4));
#pragma unroll
            for (int f = 0; f < 4; f++)
#pragma unroll
                for (int n8 = 0; n8 < 4; n8++) {
                    int g = n8 >> 1, p = (n8 & 1) * 2;
                    MMA16816(acc[f][n8], a[f][0], a[f][1], a[f][2], a[f][3],
                             b[g][p], b[g][p + 1]);
                }
        }
        if (++bidx == 3) bidx = 0;
        if (++pre == 3) pre = 0;
    }

    int row0 = m0 + wm * 64 + (lane >> 2);
    int col0 = wn * 32 + (lane & 3) * 2;
    if (MODE == 0) {
#pragma unroll
        for (int f = 0; f < 4; f++)
#pragma unroll
            for (int n8 = 0; n8 < 4; n8++) {
                int r = row0 + f * 16, c = n0 + col0 + n8 * 8;
                atomicAdd(Cf + (size_t)r * HIDN + c,           acc[f][n8][0]);
                atomicAdd(Cf + (size_t)r * HIDN + c + 1,       acc[f][n8][1]);
                atomicAdd(Cf + (size_t)(r + 8) * HIDN + c,     acc[f][n8][2]);
                atomicAdd(Cf + (size_t)(r + 8) * HIDN + c + 1, acc[f][n8][3]);
            }
    } else {
        __nv_bfloat16 *Hp, *Lp; int Nout, cb;
        if (n0 < 2048)      { Hp = qh; Lp = ql; Nout = HIDN; cb = n0 + col0; }
        else if (n0 < 3072) { Hp = kh; Lp = kl; Nout = KVD;  cb = n0 - 2048 + col0; }
        else                { Hp = vh; Lp = vl; Nout = KVD;  cb = n0 - 3072 + col0; }
#pragma unroll
        for (int f = 0; f < 4; f++)
#pragma unroll
            for (int n8 = 0; n8 < 4; n8++) {
                int r = row0 + f * 16, c = cb + n8 * 8;
                store_split2(Hp + (size_t)r * Nout + c, Lp + (size_t)r * Nout + c,
                             acc[f][n8][0], acc[f][n8][1]);
                store_split2(Hp + (size_t)(r + 8) * Nout + c, Lp + (size_t)(r + 8) * Nout + c,
                             acc[f][n8][2], acc[f][n8][3]);
            }
    }
}

// ---------------- split-bf16 mma flash attention, GQA head-paired, LPT order ----
// Per-batch launch: b passed as param, grid = (NKVH, SS/64).
#define SM_QH 0u
#define SM_QL 32768u
#define SM_KV 65536u
#define SM_LM 196608u
#define ATT_SMEM (196608 + 512 + 1024)
#define NEGINF __int_as_float(0xff800000)

__device__ __forceinline__ void att_load_kv(
    int tid, uint32_t base, int bsel, int k0,
    const __nv_bfloat16* __restrict__ khb, const __nv_bfloat16* __restrict__ klb,
    const __nv_bfloat16* __restrict__ vhb, const __nv_bfloat16* __restrict__ vlb,
    const int* __restrict__ lmb)
{
    uint32_t kb = base + SM_KV + (uint32_t)bsel * 65536u;
#pragma unroll
    for (int i = 0; i < 4; i++) {
        int id = tid + i * 256;
        int r = id >> 4, c16 = id & 15, sub = c16 >> 3, c = c16 & 7;
        uint32_t sw = (uint32_t)(sub * 8192 + (r >> 3) * 1024 + (r & 7) * 128 + ((c ^ (r & 7)) << 4));
        size_t so = (size_t)(k0 + r) * KVD + sub * 64 + c * 8;
        CP16(kb + sw,          (const void*)(khb + so));
        CP16(kb + 16384u + sw, (const void*)(klb + so));
        CP16(kb + 32768u + sw, (const void*)(vhb + so));
        CP16(kb + 49152u + sw, (const void*)(vlb + so));
    }
    if (tid < 16)
        CP16(base + SM_LM + (uint32_t)bsel * 256u + (uint32_t)tid * 16u,
             (const void*)(lmb + k0 + tid * 4));
}

__global__ void __launch_bounds__(256) attn_mma_kernel(
    const __nv_bfloat16* __restrict__ qh_g, const __nv_bfloat16* __restrict__ ql_g,
    const __nv_bfloat16* __restrict__ kh_g, const __nv_bfloat16* __restrict__ kl_g,
    const __nv_bfloat16* __restrict__ vh_g, const __nv_bfloat16* __restrict__ vl_g,
    const int* __restrict__ lm,
    __nv_bfloat16* __restrict__ ah_g, __nv_bfloat16* __restrict__ al_g,
    int b)
{
    extern __shared__ char dsm[];
    uint32_t base = (s2u(dsm) + 1023u) & ~1023u;
    uint32_t pad  = base - s2u(dsm);

    int tid = threadIdx.x, lane = tid & 31, wid = tid >> 5;
    int kvh = blockIdx.x;
    int qt = (int)gridDim.y - 1 - (int)blockIdx.y;     // LPT: big tiles first
    int q0 = qt * 64;

    const __nv_bfloat16* khb = kh_g + ((size_t)b * SS) * KVD + kvh * DH;
    const __nv_bfloat16* klb = kl_g + ((size_t)b * SS) * KVD + kvh * DH;
    const __nv_bfloat16* vhb = vh_g + ((size_t)b * SS) * KVD + kvh * DH;
    const __nv_bfloat16* vlb = vl_g + ((size_t)b * SS) * KVD + kvh * DH;
    const int* lmb = lm + b * SS;

#pragma unroll
    for (int i = 0; i < 8; i++) {
        int id = tid + i * 256;
        int r = id >> 4, c16 = id & 15, sub = c16 >> 3, c = c16 & 7;
        uint32_t sw = (uint32_t)(sub * 16384 + (r >> 3) * 1024 + (r & 7) * 128 + ((c ^ (r & 7)) << 4));
        size_t so = ((size_t)(b * SS + q0 + (r & 63))) * HIDN
                  + (size_t)(kvh * 2 + (r >> 6)) * DH + sub * 64 + c * 8;
        CP16(base + SM_QH + sw, (const void*)(qh_g + so));
        CP16(base + SM_QL + sw, (const void*)(ql_g + so));
    }
    CP_COMMIT();
    att_load_kv(tid, base, 0, 0, khb, klb, vhb, vlb, lmb);
    CP_COMMIT();

    float m0r = NEGINF, m1r = NEGINF, l0r = 0.0f, l1r = 0.0f;
    float oacc[16][4];
#pragma unroll
    for (int jo = 0; jo < 16; jo++)
#pragma unroll
        for (int e = 0; e < 4; e++) oacc[jo][e] = 0.0f;

    const float scale = 0.08838834764831845f;
    int strip = wid & 3;
    int qg0 = q0 + strip * 16 + (lane >> 2);
    int qg1 = qg0 + 8;
    int qmaxw = q0 + strip * 16 + 15;

    int aR = wid * 16 + (lane & 15);
    uint32_t aOff = (uint32_t)((aR >> 3) * 1024 + (aR & 7) * 128);
    int aSw = aR & 7;
    int bRr = ((lane >> 4) << 3) + (lane & 7);
    int rV0 = (lane & 7) + ((lane >> 3) & 1) * 8;

    CP_WAIT(1);
    __syncthreads();
    uint32_t qfh[8][4], qfl[8][4];
#pragma unroll
    for (int k16 = 0; k16 < 8; k16++) {
        int sub = k16 >> 2;
        int ca = (k16 & 3) * 2 + (lane >> 4);
        uint32_t aaddr = (uint32_t)(sub * 16384) + aOff + (uint32_t)((ca ^ aSw) << 4);
        LDSM4(qfh[k16][0], qfh[k16][1], qfh[k16][2], qfh[k16][3], base + SM_QH + aaddr);
        LDSM4(qfl[k16][0], qfl[k16][1], qfl[k16][2], qfl[k16][3], base + SM_QL + aaddr);
    }

    int nkt = qt + 1;
    for (int kt = 0; kt < nkt; kt++) {
        int k0 = kt * 64, bsel = kt & 1;
        CP_WAIT(0);
        __syncthreads();
        if (kt + 1 < nkt) {
            att_load_kv(tid, base, bsel ^ 1, (kt + 1) * 64, khb, klb, vhb, vlb, lmb);
            CP_COMMIT();
        }

        uint32_t kvb = base + SM_KV + (uint32_t)bsel * 65536u;
        const int* lms = (const int*)(dsm + pad + SM_LM + bsel * 256);
        int kmax = qmaxw - k0;
        int jmax = min(7, kmax >> 3);
        int gmax = jmax >> 1;

        float sacc[8][4];
#pragma unroll
        for (int j = 0; j < 8; j++)
#pragma unroll
            for (int e = 0; e < 4; e++) sacc[j][e] = 0.0f;

        uint32_t kh_s = kvb, kl_s = kvb + 16384u;
#pragma unroll
        for (int k16 = 0; k16 < 8; k16++) {
            int sub = k16 >> 2;
            int cb = (k16 & 3) * 2 + ((lane >> 3) & 1);
            uint32_t bhm[4][4], blm[4][4];
#pragma unroll
            for (int g = 0; g < 4; g++) {
                if (g <= gmax) {
                    int r = g * 16 + bRr;
                    uint32_t off = (uint32_t)(sub * 8192 + (r >> 3) * 1024 + (r & 7) * 128 +
                                              ((cb ^ (r & 7)) << 4));
                    LDSM4(bhm[g][0], bhm[g][1], bhm[g][2], bhm[g][3], kh_s + off);
                    LDSM4(blm[g][0], blm[g][1], blm[g][2], blm[g][3], kl_s + off);
                }
            }
#pragma unroll
            for (int j = 0; j < 8; j++) {
                if (j <= jmax) {
                    int g = j >> 1, p = (j & 1) * 2;
                    MMA16816(sacc[j], qfh[k16][0], qfh[k16][1], qfh[k16][2], qfh[k16][3],
                             bhm[g][p], bhm[g][p + 1]);
                    MMA16816(sacc[j], qfl[k16][0], qfl[k16][1], qfl[k16][2], qfl[k16][3],
                             bhm[g][p], bhm[g][p + 1]);
                    MMA16816(sacc[j], qfh[k16][0], qfh[k16][1], qfh[k16][2], qfh[k16][3],
                             blm[g][p], blm[g][p + 1]);
                }
            }
        }

        float tmax0 = NEGINF, tmax1 = NEGINF;
        int colb = (lane & 3) * 2;
#pragma unroll
        for (int j = 0; j < 8; j++) {
            if (j <= jmax) {
                int kk0 = j * 8 + colb, kk1 = kk0 + 1;
                int kg0 = k0 + kk0, kg1 = kg0 + 1;
                int lmv0 = lms[kk0], lmv1 = lms[kk1];
                float sv;
                bool ok;
                ok = (kg0 <= qg0) && (((qg0 - kg0) < WIN) || lmv0);
                sv = ok ? sacc[j][0] * scale : NEGINF; sacc[j][0] = sv; tmax0 = fmaxf(tmax0, sv);
                ok = (kg1 <= qg0) && (((qg0 - kg1) < WIN) || lmv1);
                sv = ok ? sacc[j][1] * scale : NEGINF; sacc[j][1] = sv; tmax0 = fmaxf(tmax0, sv);
                ok = (kg0 <= qg1) && (((qg1 - kg0) < WIN) || lmv0);
                sv = ok ? sacc[j][2] * scale : NEGINF; sacc[j][2] = sv; tmax1 = fmaxf(tmax1, sv);
                ok = (kg1 <= qg1) && (((qg1 - kg1) < WIN) || lmv1);
                sv = ok ? sacc[j][3] * scale : NEGINF; sacc[j][3] = sv; tmax1 = fmaxf(tmax1, sv);
            }
        }
        tmax0 = fmaxf(tmax0, __shfl_xor_sync(0xffffffffu, tmax0, 1));
        tmax0 = fmaxf(tmax0, __shfl_xor_sync(0xffffffffu, tmax0, 2));
        tmax1 = fmaxf(tmax1, __shfl_xor_sync(0xffffffffu, tmax1, 1));
        tmax1 = fmaxf(tmax1, __shfl_xor_sync(0xffffffffu, tmax1, 2));

        float mn0 = fmaxf(m0r, tmax0), mn1 = fmaxf(m1r, tmax1);
        float alp0 = (m0r == mn0) ? 1.0f : __expf(m0r - mn0);
        float alp1 = (m1r == mn1) ? 1.0f : __expf(m1r - mn1);

        uint32_t ph[8][2], pl[8][2];
        float rs0 = 0.0f, rs1 = 0.0f;
#pragma unroll
        for (int j = 0; j < 8; j++) {
            if (j <= jmax) {
                float p0 = (sacc[j][0] == NEGINF) ? 0.0f : __expf(sacc[j][0] - mn0);
                float p1 = (sacc[j][1] == NEGINF) ? 0.0f : __expf(sacc[j][1] - mn0);
                float p2 = (sacc[j][2] == NEGINF) ? 0.0f : __expf(sacc[j][2] - mn1);
                float p3 = (sacc[j][3] == NEGINF) ? 0.0f : __expf(sacc[j][3] - mn1);
                rs0 += p0 + p1; rs1 += p2 + p3;
                float h0 = __bfloat162float(__float2bfloat16(p0));
                float h1 = __bfloat162float(__float2bfloat16(p1));
                float h2 = __bfloat162float(__float2bfloat16(p2));
                float h3 = __bfloat162float(__float2bfloat16(p3));
                ph[j][0] = pack_bf16(h0, h1);
                ph[j][1] = pack_bf16(h2, h3);
                pl[j][0] = pack_bf16(p0 - h0, p1 - h1);
                pl[j][1] = pack_bf16(p2 - h2, p3 - h3);
            } else {
                ph[j][0] = ph[j][1] = pl[j][0] = pl[j][1] = 0u;
            }
        }
        rs0 += __shfl_xor_sync(0xffffffffu, rs0, 1);
        rs0 += __shfl_xor_sync(0xffffffffu, rs0, 2);
        rs1 += __shfl_xor_sync(0xffffffffu, rs1, 1);
        rs1 += __shfl_xor_sync(0xffffffffu, rs1, 2);

        l0r = l0r * alp0 + rs0;
        l1r = l1r * alp1 + rs1;
        m0r = mn0; m1r = mn1;
#pragma unroll
        for (int jo = 0; jo < 16; jo++) {
            oacc[jo][0] *= alp0; oacc[jo][1] *= alp0;
            oacc[jo][2] *= alp1; oacc[jo][3] *= alp1;
        }

        uint32_t vh_s = kvb + 32768u, vl_s = kvb + 49152u;
#pragma unroll
        for (int t = 0; t < 4; t++) {
            if (t <= gmax) {
                uint32_t a0h = ph[2 * t][0], a1h = ph[2 * t][1];
                uint32_t a2h = ph[2 * t + 1][0], a3h = ph[2 * t + 1][1];
                uint32_t a0l = pl[2 * t][0], a1l = pl[2 * t][1];
                uint32_t a2l = pl[2 * t + 1][0], a3l = pl[2 * t + 1][1];
                int r = t * 16 + rV0;
                int rsw = r & 7;
                uint32_t rbase = (uint32_t)((r >> 3) * 1024 + rsw * 128);
#pragma unroll
                for (int gg = 0; gg < 8; gg++) {
                    int sub = gg >> 2;
                    int c = (gg & 3) * 2 + (lane >> 4);
                    uint32_t off = (uint32_t)(sub * 8192) + rbase + (uint32_t)((c ^ rsw) << 4);
                    uint32_t v0, v1, v2, v3, w0, w1, w2, w3;
                    LDSM4T(v0, v1, v2, v3, vh_s + off);
                    LDSM4T(w0, w1, w2, w3, vl_s + off);
                    MMA16816(oacc[gg * 2],     a0h, a1h, a2h, a3h, v0, v1);
                    MMA16816(oacc[gg * 2],     a0l, a1l, a2l, a3l, v0, v1);
                    MMA16816(oacc[gg * 2],     a0h, a1h, a2h, a3h, w0, w1);
                    MMA16816(oacc[gg * 2 + 1], a0h, a1h, a2h, a3h, v2, v3);
                    MMA16816(oacc[gg * 2 + 1], a0l, a1l, a2l, a3l, v2, v3);
                    MMA16816(oacc[gg * 2 + 1], a0h, a1h, a2h, a3h, w2, w3);
                }
            }
        }
    }

    float inv0 = 1.0f / l0r, inv1 = 1.0f / l1r;
    int h_w = kvh * 2 + (wid >> 2);
    size_t r0 = (size_t)(b * SS + qg0) * HIDN + (size_t)h_w * DH + (lane & 3) * 2;
    size_t r1 = (size_t)(b * SS + qg1) * HIDN + (size_t)h_w * DH + (lane & 3) * 2;
#pragma unroll
    for (int jo = 0; jo < 16; jo++) {
        int cofs = jo * 8;
        store_split2(ah_g + r0 + cofs, al_g + r0 + cofs, oacc[jo][0] * inv0, oacc[jo][1] * inv0);
        store_split2(ah_g + r1 + cofs, al_g + r1 + cofs, oacc[jo][2] * inv1, oacc[jo][3] * inv1);
    }
}

// ---------------- launch: batch-pipelined across two streams ----------------
extern "C" void kernel_launch(void* const* d_in, const int* in_sizes, int n_in,
                              void* d_out, int out_size)
{
    (void)in_sizes; (void)n_in; (void)out_size;
    const float* x  = (const float*)d_in[0];
    const float* Wq = (const float*)d_in[1];
    const float* Wk = (const float*)d_in[2];
    const float* Wv = (const float*)d_in[3];
    const float* Wo = (const float*)d_in[4];
    float* out = (float*)d_out;

    void *lmp, *xh, *xl, *qh, *ql, *kh, *kl, *vh, *vl, *ah, *al;
    void *wch, *wcl, *woh, *wol;
    cudaGetSymbolAddress(&lmp, g_lm);
    cudaGetSymbolAddress(&xh, g_xh);   cudaGetSymbolAddress(&xl, g_xl);
    cudaGetSymbolAddress(&qh, g_qh);   cudaGetSymbolAddress(&ql, g_ql);
    cudaGetSymbolAddress(&kh, g_kh);   cudaGetSymbolAddress(&kl, g_kl);
    cudaGetSymbolAddress(&vh, g_vh);   cudaGetSymbolAddress(&vl, g_vl);
    cudaGetSymbolAddress(&ah, g_ah);   cudaGetSymbolAddress(&al, g_al);
    cudaGetSymbolAddress(&wch, g_wch); cudaGetSymbolAddress(&wcl, g_wcl);
    cudaGetSymbolAddress(&woh, g_woh); cudaGetSymbolAddress(&wol, g_wol);

    static cudaStream_t s_side = nullptr;
    static cudaEvent_t e_fork = nullptr, e_xsp = nullptr,
                       e_q0 = nullptr, e_q1 = nullptr,
                       e_a0 = nullptr, e_a1 = nullptr;
    if (s_side == nullptr) {
        cudaStreamCreateWithFlags(&s_side, cudaStreamNonBlocking);
        cudaEventCreateWithFlags(&e_fork, cudaEventDisableTiming);
        cudaEventCreateWithFlags(&e_xsp,  cudaEventDisableTiming);
        cudaEventCreateWithFlags(&e_q0,   cudaEventDisableTiming);
        cudaEventCreateWithFlags(&e_q1,   cudaEventDisableTiming);
        cudaEventCreateWithFlags(&e_a0,   cudaEventDisableTiming);
        cudaEventCreateWithFlags(&e_a1,   cudaEventDisableTiming);
    }

    cudaFuncSetAttribute((const void*)gemm_kernel<0, 48>, cudaFuncAttributeMaxDynamicSharedMemorySize, GEMM_SMEM_BYTES);
    cudaFuncSetAttribute((const void*)gemm_kernel<1, 96>, cudaFuncAttributeMaxDynamicSharedMemorySize, GEMM_SMEM_BYTES);
    cudaFuncSetAttribute((const void*)attn_mma_kernel,    cudaFuncAttributeMaxDynamicSharedMemorySize, ATT_SMEM);

    // ---- fork: xsplit + TLS chain on side stream ----
    cudaEventRecord(e_fork, 0);
    cudaStreamWaitEvent(s_side, e_fork, 0);

    xsplit_kernel<<<(MTOT * HIDN) / 1024, 256, 0, s_side>>>(x, (__nv_bfloat16*)xh, (__nv_bfloat16*)xl);
    cudaEventRecord(e_xsp, s_side);
    meanp_kernel      <<<dim3(HIDN / 256, BB, 8), 256, 0, s_side>>>(x);
    meanf_mnorm_kernel<<<BB, 256, 0, s_side>>>();
    score_kernel      <<<dim3(SS, BB), 256, 0, s_side>>>(x);
    topk_kernel       <<<BB, 1024, 0, s_side>>>();
    // (side stream continues with attention below — in-order after topk)

    // ---- main stream: weight prep (concurrent with xsplit/TLS) ----
    wsplit_all_kernel<<<dim3(64, KDIM / 32, 4), dim3(32, 8)>>>(
        Wq, Wk, Wv, Wo,
        (__nv_bfloat16*)wch, (__nv_bfloat16*)wcl,
        (__nv_bfloat16*)woh, (__nv_bfloat16*)wol, out);

    // ---- QKV projection, batch-split (needs xsplit) ----
    cudaStreamWaitEvent(0, e_xsp, 0);
    gemm_kernel<1, 96><<<dim3(NQKV / 128, 16), 256, GEMM_SMEM_BYTES>>>(
        (const __nv_bfloat16*)xh, (const __nv_bfloat16*)xl,
        (__nv_bfloat16*)wch, (__nv_bfloat16*)wcl,
        nullptr,
        (__nv_bfloat16*)qh, (__nv_bfloat16*)ql,
        (__nv_bfloat16*)kh, (__nv_bfloat16*)kl,
        (__nv_bfloat16*)vh, (__nv_bfloat16*)vl, 0);
    cudaEventRecord(e_q0, 0);
    gemm_kernel<1, 96><<<dim3(NQKV / 128, 16), 256, GEMM_SMEM_BYTES>>>(
        (const __nv_bfloat16*)xh, (const __nv_bfloat16*)xl,
        (__nv_bfloat16*)wch, (__nv_bfloat16*)wcl,
        nullptr,
        (__nv_bfloat16*)qh, (__nv_bfloat16*)ql,
        (__nv_bfloat16*)kh, (__nv_bfloat16*)kl,
        (__nv_bfloat16*)vh, (__nv_bfloat16*)vl, 2048);
    cudaEventRecord(e_q1, 0);

    // ---- attention on side stream, batch-split; overlaps QKV_b1 / Wo_b0 ----
    cudaStreamWaitEvent(s_side, e_q0, 0);
    attn_mma_kernel<<<dim3(NKVH, SS / 64), 256, ATT_SMEM, s_side>>>(
        (const __nv_bfloat16*)qh, (const __nv_bfloat16*)ql,
        (const __nv_bfloat16*)kh, (const __nv_bfloat16*)kl,
        (const __nv_bfloat16*)vh, (const __nv_bfloat16*)vl,
        (const int*)lmp, (__nv_bfloat16*)ah, (__nv_bfloat16*)al, 0);
    cudaEventRecord(e_a0, s_side);
    cudaStreamWaitEvent(s_side, e_q1, 0);
    attn_mma_kernel<<<dim3(NKVH, SS / 64), 256, ATT_SMEM, s_side>>>(
        (const __nv_bfloat16*)qh, (const __nv_bfloat16*)ql,
        (const __nv_bfloat16*)kh, (const __nv_bfloat16*)kl,
        (const __nv_bfloat16*)vh, (const __nv_bfloat16*)vl,
        (const int*)lmp, (__nv_bfloat16*)ah, (__nv_bfloat16*)al, 1);
    cudaEventRecord(e_a1, s_side);

    // ---- output projection on main stream, batch-split, split-K2 atomics ----
    cudaStreamWaitEvent(0, e_a0, 0);
    gemm_kernel<0, 48><<<dim3(HIDN / 128, 16, 2), 256, GEMM_SMEM_BYTES>>>(
        (const __nv_bfloat16*)ah, (const __nv_bfloat16*)al,
        (const __nv_bfloat16*)woh, (const __nv_bfloat16*)wol,
        out, nullptr, nullptr, nullptr, nullptr, nullptr, nullptr, 0);
    cudaStreamWaitEvent(0, e_a1, 0);
    gemm_kernel<0, 48><<<dim3(HIDN / 128, 16, 2), 256, GEMM_SMEM_BYTES>>>(
        (const __nv_bfloat16*)ah, (const __nv_bfloat16*)al,
        (const __nv_bfloat16*)woh, (const __nv_bfloat16*)wol,
        out, nullptr, nullptr, nullptr, nullptr, nullptr, nullptr, 2048);
}

// round 13
// speedup vs baseline: 1.0570x; 1.0570x over previous
#include <cuda_runtime.h>
#include <cuda_bf16.h>
#include <math.h>
#include <stdint.h>

// ---------------- problem constants ----------------
#define BB   2
#define SS   2048
#define HIDN 2048
#define NH   16
#define NKVH 8
#define DH   128
#define KVD  1024
#define WIN  128
#define TOPK 675
#define MTOT (BB * SS)
#define KDIM 2048
#define NQKV 4096

// ---------------- scratch ----------------
__device__ double g_meanp[8 * BB * HIDN];
__device__ float  g_mean[BB * HIDN];
__device__ double g_mnorm[BB];
__device__ float  g_score[BB * SS];
__device__ int    g_lm[BB * SS];

__device__ __nv_bfloat16 g_xh[MTOT * HIDN], g_xl[MTOT * HIDN];
__device__ __nv_bfloat16 g_qh[MTOT * HIDN], g_ql[MTOT * HIDN];
__device__ __nv_bfloat16 g_kh[MTOT * KVD],  g_kl[MTOT * KVD];
__device__ __nv_bfloat16 g_vh[MTOT * KVD],  g_vl[MTOT * KVD];
__device__ __nv_bfloat16 g_ah[MTOT * HIDN], g_al[MTOT * HIDN];
__device__ __nv_bfloat16 g_wch[NQKV * KDIM], g_wcl[NQKV * KDIM];
__device__ __nv_bfloat16 g_woh[HIDN * KDIM], g_wol[HIDN * KDIM];

// ---------------- PTX helpers ----------------
__device__ __forceinline__ uint32_t s2u(const void* p) {
    uint32_t a;
    asm("{ .reg .u64 t; cvta.to.shared.u64 t, %1; cvt.u32.u64 %0, t; }" : "=r"(a) : "l"(p));
    return a;
}
#define CP16(saddr, gptr) \
    asm volatile("cp.async.cg.shared.global [%0], [%1], 16;" :: "r"(saddr), "l"(gptr))
#define CP_COMMIT() asm volatile("cp.async.commit_group;" ::: "memory")
#define CP_WAIT(n)  asm volatile("cp.async.wait_group %0;" :: "n"(n) : "memory")

#define LDSM4(r0, r1, r2, r3, addr) \
    asm volatile("ldmatrix.sync.aligned.m8n8.x4.shared.b16 {%0,%1,%2,%3}, [%4];" \
                 : "=r"(r0), "=r"(r1), "=r"(r2), "=r"(r3) : "r"(addr))
#define LDSM4T(r0, r1, r2, r3, addr) \
    asm volatile("ldmatrix.sync.aligned.m8n8.x4.trans.shared.b16 {%0,%1,%2,%3}, [%4];" \
                 : "=r"(r0), "=r"(r1), "=r"(r2), "=r"(r3) : "r"(addr))

#define MMA16816(D, a0, a1, a2, a3, b0, b1) \
    asm volatile("mma.sync.aligned.m16n8k16.row.col.f32.bf16.bf16.f32 " \
                 "{%0,%1,%2,%3}, {%4,%5,%6,%7}, {%8,%9}, {%0,%1,%2,%3};" \
                 : "+f"((D)[0]), "+f"((D)[1]), "+f"((D)[2]), "+f"((D)[3]) \
                 : "r"(a0), "r"(a1), "r"(a2), "r"(a3), "r"(b0), "r"(b1))

#define REDV2(ptr, v0, v1) \
    asm volatile("red.global.add.v2.f32 [%0], {%1, %2};" \
                 :: "l"(ptr), "f"(v0), "f"(v1) : "memory")

__device__ __forceinline__ uint32_t pack_bf16(float lo, float hi) {
    uint32_t r;
    asm("cvt.rn.bf16x2.f32 %0, %1, %2;" : "=r"(r) : "f"(hi), "f"(lo));
    return r;
}
__device__ __forceinline__ void store_split2(__nv_bfloat16* Hp, __nv_bfloat16* Lp,
                                             float v0, float v1) {
    __nv_bfloat16 h0 = __float2bfloat16(v0), h1 = __float2bfloat16(v1);
    __nv_bfloat16 l0 = __float2bfloat16(v0 - __bfloat162float(h0));
    __nv_bfloat16 l1 = __float2bfloat16(v1 - __bfloat162float(h1));
    *(__nv_bfloat162*)Hp = __halves2bfloat162(h0, h1);
    *(__nv_bfloat162*)Lp = __halves2bfloat162(l0, l1);
}

// ---------------- mean stage 1 ----------------
__global__ void meanp_kernel(const float* __restrict__ x) {
    int f = blockIdx.x * 256 + threadIdx.x;
    int b = blockIdx.y, ch = blockIdx.z;
    const float* p = x + ((size_t)b * SS + (size_t)ch * 256) * HIDN + f;
    double a0 = 0, a1 = 0;
    for (int s = 0; s < 256; s += 2) {
        a0 += (double)p[(size_t)s * HIDN];
        a1 += (double)p[(size_t)(s + 1) * HIDN];
    }
    g_meanp[((size_t)ch * BB + b) * HIDN + f] = a0 + a1;
}

// ---------------- mean stage 2 fused with ||mean|| ----------------
__global__ void meanf_mnorm_kernel() {
    int b = blockIdx.x, tid = threadIdx.x;
    __shared__ double red[8];
    double acc = 0;
    for (int f = tid; f < HIDN; f += 256) {
        double t = 0;
        for (int ch = 0; ch < 8; ch++) t += g_meanp[((size_t)ch * BB + b) * HIDN + f];
        float m = (float)(t / (double)SS);
        g_mean[b * HIDN + f] = m;
        acc += (double)m * (double)m;
    }
    for (int off = 16; off > 0; off >>= 1)
        acc += __shfl_down_sync(0xffffffffu, acc, off);
    if ((tid & 31) == 0) red[tid >> 5] = acc;
    __syncthreads();
    if (tid == 0) {
        double t = 0;
        for (int w = 0; w < 8; w++) t += red[w];
        g_mnorm[b] = sqrt(t);
    }
}

// ---------------- score ----------------
__global__ void score_kernel(const float* __restrict__ x) {
    int row = blockIdx.x, b = blockIdx.y, tid = threadIdx.x;
    __shared__ double redn[8], redd[8];
    size_t roff = ((size_t)b * SS + row) * HIDN;
    const float* xr = x + roff;
    const float* mr = g_mean + b * HIDN;
    double n2 = 0, dt = 0;
    for (int c = tid; c < HIDN; c += 256) {
        float xv = xr[c];
        n2 += (double)xv * (double)xv;
        dt += (double)xv * (double)mr[c];
    }
    for (int off = 16; off > 0; off >>= 1) {
        n2 += __shfl_down_sync(0xffffffffu, n2, off);
        dt += __shfl_down_sync(0xffffffffu, dt, off);
    }
    if ((tid & 31) == 0) { redn[tid >> 5] = n2; redd[tid >> 5] = dt; }
    __syncthreads();
    if (tid == 0) {
        double tn = 0, td = 0;
        for (int w = 0; w < 8; w++) { tn += redn[w]; td += redd[w]; }
        double nrm = sqrt(tn);
        double div = -td / (nrm * g_mnorm[b] + 1e-6);
        g_score[b * SS + row] = (float)(0.7 * nrm + 0.3 * div);
    }
}

// ---------------- exact top-k (bitonic) + dilation ----------------
__global__ void topk_kernel() {
    int b = blockIdx.x, tid = threadIdx.x;
    __shared__ unsigned long long sd[SS];
    __shared__ unsigned char l0[SS], l1[SS];
    for (int i = tid; i < SS; i += 1024) {
        unsigned fb = __float_as_uint(g_score[b * SS + i]);
        unsigned key = (fb & 0x80000000u) ? ~fb : (fb | 0x80000000u);
        sd[i] = ((unsigned long long)key << 32) | (0xFFFFFFFFu - (unsigned)i);
    }
    __syncthreads();
    for (int k2 = 2; k2 <= SS; k2 <<= 1) {
        for (int j = k2 >> 1; j > 0; j >>= 1) {
            for (int i = tid; i < SS; i += 1024) {
                int ixj = i ^ j;
                if (ixj > i) {
                    bool asc = ((i & k2) == 0);
                    unsigned long long a = sd[i], c = sd[ixj];
                    if ((a > c) == asc) { sd[i] = c; sd[ixj] = a; }
                }
            }
            __syncthreads();
        }
    }
    unsigned long long kth = sd[SS - TOPK];
    __syncthreads();
    for (int i = tid; i < SS; i += 1024) {
        unsigned fb = __float_as_uint(g_score[b * SS + i]);
        unsigned key = (fb & 0x80000000u) ? ~fb : (fb | 0x80000000u);
        unsigned long long comp = ((unsigned long long)key << 32) | (0xFFFFFFFFu - (unsigned)i);
        l0[i] = (comp >= kth) ? 1 : 0;
    }
    __syncthreads();
    for (int i = tid; i < SS; i += 1024) {
        unsigned char v = l0[i];
        if (i > 0)      v |= l0[i - 1];
        if (i < SS - 1) v |= l0[i + 1];
        l1[i] = v;
    }
    __syncthreads();
    for (int i = tid; i < SS; i += 1024) {
        unsigned char v = l1[i];
        if (i > 0)      v |= l1[i - 1];
        if (i < SS - 1) v |= l1[i + 1];
        g_lm[b * SS + i] = (int)v;
    }
}

// ---------------- split fp32 -> (bf16 hi, bf16 lo) ----------------
__global__ void xsplit_kernel(const float* __restrict__ X,
                              __nv_bfloat16* __restrict__ Xh,
                              __nv_bfloat16* __restrict__ Xl) {
    int i = (blockIdx.x * 256 + threadIdx.x) * 4;
#pragma unroll
    for (int j = 0; j < 4; j++) {
        float v = X[i + j];
        __nv_bfloat16 h = __float2bfloat16(v);
        Xh[i + j] = h;
        Xl[i + j] = __float2bfloat16(v - __bfloat162float(h));
    }
}

// ---------------- transpose+split: QKV weights (main stream, z in 0..2) --------
__global__ void wsplit_qkv_kernel(const float* __restrict__ W0, const float* __restrict__ W1,
                                  const float* __restrict__ W2,
                                  __nv_bfloat16* __restrict__ wch, __nv_bfloat16* __restrict__ wcl)
{
    __shared__ float t[32][33];
    int z = blockIdx.z;
    const float* W; __nv_bfloat16 *Th, *Tl; int N;
    if (z == 0)      { W = W0; Th = wch;                       Tl = wcl;                       N = 2048; }
    else if (z == 1) { W = W1; Th = wch + (size_t)2048 * KDIM; Tl = wcl + (size_t)2048 * KDIM; N = 1024; }
    else             { W = W2; Th = wch + (size_t)3072 * KDIM; Tl = wcl + (size_t)3072 * KDIM; N = 1024; }
    int n0 = blockIdx.x * 32, k0 = blockIdx.y * 32;
    if (n0 >= N) return;
    int tx = threadIdx.x, ty = threadIdx.y;
#pragma unroll
    for (int i = 0; i < 32; i += 8)
        t[ty + i][tx] = W[(size_t)(k0 + ty + i) * N + n0 + tx];
    __syncthreads();
#pragma unroll
    for (int i = 0; i < 32; i += 8) {
        float v = t[tx][ty + i];
        __nv_bfloat16 h = __float2bfloat16(v);
        __nv_bfloat16 l = __float2bfloat16(v - __bfloat162float(h));
        size_t o = (size_t)(n0 + ty + i) * KDIM + k0 + tx;
        Th[o] = h;
        Tl[o] = l;
    }
}

// ---------------- transpose+split: Wo + zero out (side stream) ------------------
// zero coverage: grid 64x64, 256 thr, 8 floats/thr = 64*64*256*8 = 8,388,608
//              = MTOT*HIDN exactly (verified).
__global__ void wsplit_wo_kernel(const float* __restrict__ W3,
                                 __nv_bfloat16* __restrict__ woh, __nv_bfloat16* __restrict__ wol,
                                 float* __restrict__ out_zero)
{
    __shared__ float t[32][33];
    int n0 = blockIdx.x * 32, k0 = blockIdx.y * 32;
    int tid1 = threadIdx.y * 32 + threadIdx.x;
    {
        size_t id = (((size_t)blockIdx.y * 64 + blockIdx.x) * 256 + tid1) * 8;
        float4 zz = make_float4(0.f, 0.f, 0.f, 0.f);
        *(float4*)(out_zero + id)     = zz;
        *(float4*)(out_zero + id + 4) = zz;
    }
    int tx = threadIdx.x, ty = threadIdx.y;
#pragma unroll
    for (int i = 0; i < 32; i += 8)
        t[ty + i][tx] = W3[(size_t)(k0 + ty + i) * HIDN + n0 + tx];
    __syncthreads();
#pragma unroll
    for (int i = 0; i < 32; i += 8) {
        float v = t[tx][ty + i];
        __nv_bfloat16 h = __float2bfloat16(v);
        __nv_bfloat16 l = __float2bfloat16(v - __bfloat162float(h));
        size_t o = (size_t)(n0 + ty + i) * KDIM + k0 + tx;
        woh[o] = h;
        wol[o] = l;
    }
}

// ---------------- mma.sync split GEMM (128x128, 3-stage) -----------
// MODE 0: fp32 red.v2 split-K (blockIdx.z). MODE 1: split bf16, QKV-routed.
#define GBK 64
#define TILEB 16384u
#define BUFB  32768u
#define GEMM_SMEM_BYTES (3 * 32768 + 1024)

template<int NST>
__device__ __forceinline__ void load_tiles_async(
    int tid, int s, int m0, int n0, int koff,
    const __nv_bfloat16* __restrict__ Ah, const __nv_bfloat16* __restrict__ Al,
    const __nv_bfloat16* __restrict__ Bh, const __nv_bfloat16* __restrict__ Bl,
    uint32_t bufA)
{
    constexpr int SEGL = NST / 3;
    int seg = s / SEGL;
    int kk  = (s % SEGL) * GBK + koff;
    const __nv_bfloat16* Ap = (seg == 1) ? Al : Ah;
    const __nv_bfloat16* Bp = (seg == 2) ? Bl : Bh;
    uint32_t bufB = bufA + TILEB;
#pragma unroll
    for (int j = 0; j < 4; j++) {
        int id = tid + j * 256;
        int row = id >> 3, c = id & 7;
        uint32_t sw = (uint32_t)((row >> 3) * 1024 + (row & 7) * 128 + ((c ^ (row & 7)) << 4));
        CP16(bufA + sw, (const void*)(Ap + (size_t)(m0 + row) * KDIM + kk + c * 8));
        CP16(bufB + sw, (const void*)(Bp + (size_t)(n0 + row) * KDIM + kk + c * 8));
    }
}

template<int MODE, int NST>
__global__ void __launch_bounds__(256) gemm_kernel(
    const __nv_bfloat16* __restrict__ Ah, const __nv_bfloat16* __restrict__ Al,
    const __nv_bfloat16* __restrict__ Bh, const __nv_bfloat16* __restrict__ Bl,
    float* __restrict__ Cf,
    __nv_bfloat16* __restrict__ qh, __nv_bfloat16* __restrict__ ql,
    __nv_bfloat16* __restrict__ kh, __nv_bfloat16* __restrict__ kl,
    __nv_bfloat16* __restrict__ vh, __nv_bfloat16* __restrict__ vl)
{
    extern __shared__ char dsm[];
    uint32_t tbase = (s2u(dsm) + 1023u) & ~1023u;

    int tid = threadIdx.x, lane = tid & 31, wid = tid >> 5;
    int wm = wid >> 2, wn = wid & 3;
    int m0 = blockIdx.y * 128, n0 = blockIdx.x * 128;
    int koff = (int)blockIdx.z * ((NST / 3) * GBK);

    int aR = lane & 15, aC = lane >> 4;
    int bR = ((lane >> 4) << 3) + (lane & 7);
    int bC = (lane >> 3) & 1;

    uint32_t aOff[4]; int aSw[4];
#pragma unroll
    for (int f = 0; f < 4; f++) {
        int r = wm * 64 + f * 16 + aR;
        aOff[f] = (uint32_t)((r >> 3) * 1024 + (r & 7) * 128);
        aSw[f]  = r & 7;
    }
    uint32_t bOff[2]; int bSw[2];
#pragma unroll
    for (int g = 0; g < 2; g++) {
        int r = wn * 32 + g * 16 + bR;
        bOff[g] = (uint32_t)((r >> 3) * 1024 + (r & 7) * 128);
        bSw[g]  = r & 7;
    }

    float acc[4][4][4];
#pragma unroll
    for (int f = 0; f < 4; f++)
#pragma unroll
        for (int n8 = 0; n8 < 4; n8++)
#pragma unroll
            for (int e = 0; e < 4; e++) acc[f][n8][e] = 0.0f;

    load_tiles_async<NST>(tid, 0, m0, n0, koff, Ah, Al, Bh, Bl, tbase);
    CP_COMMIT();
    load_tiles_async<NST>(tid, 1, m0, n0, koff, Ah, Al, Bh, Bl, tbase + BUFB);
    CP_COMMIT();

    int bidx = 0, pre = 2;
    for (int s = 0; s < NST; s++) {
        if (s == NST - 1) { CP_WAIT(0); } else { CP_WAIT(1); }
        __syncthreads();
        if (s + 2 < NST) {
            load_tiles_async<NST>(tid, s + 2, m0, n0, koff, Ah, Al, Bh, Bl,
                                  tbase + (uint32_t)pre * BUFB);
            CP_COMMIT();
        }

        uint32_t bufA = tbase + (uint32_t)bidx * BUFB;
        uint32_t bufB = bufA + TILEB;
#pragma unroll
        for (int k16 = 0; k16 < 4; k16++) {
            int ca = k16 * 2 + aC, cb = k16 * 2 + bC;
            uint32_t a[4][4], b[2][4];
#pragma unroll
            for (int f = 0; f < 4; f++)
                LDSM4(a[f][0], a[f][1], a[f][2], a[f][3],
                      bufA + aOff[f] + (uint32_t)((ca ^ aSw[f]) << 4));
#pragma unroll
            for (int g = 0; g < 2; g++)
                LDSM4(b[g][0], b[g][1], b[g][2], b[g][3],
                      bufB + bOff[g] + (uint32_t)((cb ^ bSw[g]) << 4));
#pragma unroll
            for (int f = 0; f < 4; f++)
#pragma unroll
                for (int n8 = 0; n8 < 4; n8++) {
                    int g = n8 >> 1, p = (n8 & 1) * 2;
                    MMA16816(acc[f][n8], a[f][0], a[f][1], a[f][2], a[f][3],
                             b[g][p], b[g][p + 1]);
                }
        }
        if (++bidx == 3) bidx = 0;
        if (++pre == 3) pre = 0;
    }

    int row0 = m0 + wm * 64 + (lane >> 2);
    int col0 = wn * 32 + (lane & 3) * 2;
    if (MODE == 0) {
        // split-K accumulate: 2 commutative vector adds per element pair onto 0
#pragma unroll
        for (int f = 0; f < 4; f++)
#pragma unroll
            for (int n8 = 0; n8 < 4; n8++) {
                int r = row0 + f * 16, c = n0 + col0 + n8 * 8;
                REDV2(Cf + (size_t)r * HIDN + c,       acc[f][n8][0], acc[f][n8][1]);
                REDV2(Cf + (size_t)(r + 8) * HIDN + c, acc[f][n8][2], acc[f][n8][3]);
            }
    } else {
        __nv_bfloat16 *Hp, *Lp; int Nout, cb;
        if (n0 < 2048)      { Hp = qh; Lp = ql; Nout = HIDN; cb = n0 + col0; }
        else if (n0 < 3072) { Hp = kh; Lp = kl; Nout = KVD;  cb = n0 - 2048 + col0; }
        else                { Hp = vh; Lp = vl; Nout = KVD;  cb = n0 - 3072 + col0; }
#pragma unroll
        for (int f = 0; f < 4; f++)
#pragma unroll
            for (int n8 = 0; n8 < 4; n8++) {
                int r = row0 + f * 16, c = cb + n8 * 8;
                store_split2(Hp + (size_t)r * Nout + c, Lp + (size_t)r * Nout + c,
                             acc[f][n8][0], acc[f][n8][1]);
                store_split2(Hp + (size_t)(r + 8) * Nout + c, Lp + (size_t)(r + 8) * Nout + c,
                             acc[f][n8][2], acc[f][n8][3]);
            }
    }
}

// ---------------- split-bf16 mma flash attention, GQA head-paired, LPT order ----
#define SM_QH 0u
#define SM_QL 32768u
#define SM_KV 65536u
#define SM_LM 196608u
#define ATT_SMEM (196608 + 512 + 1024)
#define NEGINF __int_as_float(0xff800000)

__device__ __forceinline__ void att_load_kv(
    int tid, uint32_t base, int bsel, int k0,
    const __nv_bfloat16* __restrict__ khb, const __nv_bfloat16* __restrict__ klb,
    const __nv_bfloat16* __restrict__ vhb, const __nv_bfloat16* __restrict__ vlb,
    const int* __restrict__ lmb)
{
    uint32_t kb = base + SM_KV + (uint32_t)bsel * 65536u;
#pragma unroll
    for (int i = 0; i < 4; i++) {
        int id = tid + i * 256;
        int r = id >> 4, c16 = id & 15, sub = c16 >> 3, c = c16 & 7;
        uint32_t sw = (uint32_t)(sub * 8192 + (r >> 3) * 1024 + (r & 7) * 128 + ((c ^ (r & 7)) << 4));
        size_t so = (size_t)(k0 + r) * KVD + sub * 64 + c * 8;
        CP16(kb + sw,          (const void*)(khb + so));
        CP16(kb + 16384u + sw, (const void*)(klb + so));
        CP16(kb + 32768u + sw, (const void*)(vhb + so));
        CP16(kb + 49152u + sw, (const void*)(vlb + so));
    }
    if (tid < 16)
        CP16(base + SM_LM + (uint32_t)bsel * 256u + (uint32_t)tid * 16u,
             (const void*)(lmb + k0 + tid * 4));
}

__global__ void __launch_bounds__(256) attn_mma_kernel(
    const __nv_bfloat16* __restrict__ qh_g, const __nv_bfloat16* __restrict__ ql_g,
    const __nv_bfloat16* __restrict__ kh_g, const __nv_bfloat16* __restrict__ kl_g,
    const __nv_bfloat16* __restrict__ vh_g, const __nv_bfloat16* __restrict__ vl_g,
    const int* __restrict__ lm,
    __nv_bfloat16* __restrict__ ah_g, __nv_bfloat16* __restrict__ al_g)
{
    extern __shared__ char dsm[];
    uint32_t base = (s2u(dsm) + 1023u) & ~1023u;
    uint32_t pad  = base - s2u(dsm);

    int tid = threadIdx.x, lane = tid & 31, wid = tid >> 5;
    int bh = blockIdx.x;
    int qt = (int)gridDim.y - 1 - (int)blockIdx.y;
    int b = bh >> 3, kvh = bh & 7;
    int q0 = qt * 64;

    const __nv_bfloat16* khb = kh_g + ((size_t)b * SS) * KVD + kvh * DH;
    const __nv_bfloat16* klb = kl_g + ((size_t)b * SS) * KVD + kvh * DH;
    const __nv_bfloat16* vhb = vh_g + ((size_t)b * SS) * KVD + kvh * DH;
    const __nv_bfloat16* vlb = vl_g + ((size_t)b * SS) * KVD + kvh * DH;
    const int* lmb = lm + b * SS;

#pragma unroll
    for (int i = 0; i < 8; i++) {
        int id = tid + i * 256;
        int r = id >> 4, c16 = id & 15, sub = c16 >> 3, c = c16 & 7;
        uint32_t sw = (uint32_t)(sub * 16384 + (r >> 3) * 1024 + (r & 7) * 128 + ((c ^ (r & 7)) << 4));
        size_t so = ((size_t)(b * SS + q0 + (r & 63))) * HIDN
                  + (size_t)(kvh * 2 + (r >> 6)) * DH + sub * 64 + c * 8;
        CP16(base + SM_QH + sw, (const void*)(qh_g + so));
        CP16(base + SM_QL + sw, (const void*)(ql_g + so));
    }
    CP_COMMIT();
    att_load_kv(tid, base, 0, 0, khb, klb, vhb, vlb, lmb);
    CP_COMMIT();

    float m0r = NEGINF, m1r = NEGINF, l0r = 0.0f, l1r = 0.0f;
    float oacc[16][4];
#pragma unroll
    for (int jo = 0; jo < 16; jo++)
#pragma unroll
        for (int e = 0; e < 4; e++) oacc[jo][e] = 0.0f;

    const float scale = 0.08838834764831845f;
    int strip = wid & 3;
    int qg0 = q0 + strip * 16 + (lane >> 2);
    int qg1 = qg0 + 8;
    int qmaxw = q0 + strip * 16 + 15;

    int aR = wid * 16 + (lane & 15);
    uint32_t aOff = (uint32_t)((aR >> 3) * 1024 + (aR & 7) * 128);
    int aSw = aR & 7;
    int bRr = ((lane >> 4) << 3) + (lane & 7);
    int rV0 = (lane & 7) + ((lane >> 3) & 1) * 8;

    CP_WAIT(1);
    __syncthreads();
    uint32_t qfh[8][4], qfl[8][4];
#pragma unroll
    for (int k16 = 0; k16 < 8; k16++) {
        int sub = k16 >> 2;
        int ca = (k16 & 3) * 2 + (lane >> 4);
        uint32_t aaddr = (uint32_t)(sub * 16384) + aOff + (uint32_t)((ca ^ aSw) << 4);
        LDSM4(qfh[k16][0], qfh[k16][1], qfh[k16][2], qfh[k16][3], base + SM_QH + aaddr);
        LDSM4(qfl[k16][0], qfl[k16][1], qfl[k16][2], qfl[k16][3], base + SM_QL + aaddr);
    }

    int nkt = qt + 1;
    for (int kt = 0; kt < nkt; kt++) {
        int k0 = kt * 64, bsel = kt & 1;
        CP_WAIT(0);
        __syncthreads();
        if (kt + 1 < nkt) {
            att_load_kv(tid, base, bsel ^ 1, (kt + 1) * 64, khb, klb, vhb, vlb, lmb);
            CP_COMMIT();
        }

        uint32_t kvb = base + SM_KV + (uint32_t)bsel * 65536u;
        const int* lms = (const int*)(dsm + pad + SM_LM + bsel * 256);
        int kmax = qmaxw - k0;
        int jmax = min(7, kmax >> 3);
        int gmax = jmax >> 1;

        float sacc[8][4];
#pragma unroll
        for (int j = 0; j < 8; j++)
#pragma unroll
            for (int e = 0; e < 4; e++) sacc[j][e] = 0.0f;

        uint32_t kh_s = kvb, kl_s = kvb + 16384u;
#pragma unroll
        for (int k16 = 0; k16 < 8; k16++) {
            int sub = k16 >> 2;
            int cb = (k16 & 3) * 2 + ((lane >> 3) & 1);
            uint32_t bhm[4][4], blm[4][4];
#pragma unroll
            for (int g = 0; g < 4; g++) {
                if (g <= gmax) {
                    int r = g * 16 + bRr;
                    uint32_t off = (uint32_t)(sub * 8192 + (r >> 3) * 1024 + (r & 7) * 128 +
                                              ((cb ^ (r & 7)) << 4));
                    LDSM4(bhm[g][0], bhm[g][1], bhm[g][2], bhm[g][3], kh_s + off);
                    LDSM4(blm[g][0], blm[g][1], blm[g][2], blm[g][3], kl_s + off);
                }
            }
#pragma unroll
            for (int j = 0; j < 8; j++) {
                if (j <= jmax) {
                    int g = j >> 1, p = (j & 1) * 2;
                    MMA16816(sacc[j], qfh[k16][0], qfh[k16][1], qfh[k16][2], qfh[k16][3],
                             bhm[g][p], bhm[g][p + 1]);
                    MMA16816(sacc[j], qfl[k16][0], qfl[k16][1], qfl[k16][2], qfl[k16][3],
                             bhm[g][p], bhm[g][p + 1]);
                    MMA16816(sacc[j], qfh[k16][0], qfh[k16][1], qfh[k16][2], qfh[k16][3],
                             blm[g][p], blm[g][p + 1]);
                }
            }
        }

        float tmax0 = NEGINF, tmax1 = NEGINF;
        int colb = (lane & 3) * 2;
#pragma unroll
        for (int j = 0; j < 8; j++) {
            if (j <= jmax) {
                int kk0 = j * 8 + colb, kk1 = kk0 + 1;
                int kg0 = k0 + kk0, kg1 = kg0 + 1;
                int lmv0 = lms[kk0], lmv1 = lms[kk1];
                float sv;
                bool ok;
                ok = (kg0 <= qg0) && (((qg0 - kg0) < WIN) || lmv0);
                sv = ok ? sacc[j][0] * scale : NEGINF; sacc[j][0] = sv; tmax0 = fmaxf(tmax0, sv);
                ok = (kg1 <= qg0) && (((qg0 - kg1) < WIN) || lmv1);
                sv = ok ? sacc[j][1] * scale : NEGINF; sacc[j][1] = sv; tmax0 = fmaxf(tmax0, sv);
                ok = (kg0 <= qg1) && (((qg1 - kg0) < WIN) || lmv0);
                sv = ok ? sacc[j][2] * scale : NEGINF; sacc[j][2] = sv; tmax1 = fmaxf(tmax1, sv);
                ok = (kg1 <= qg1) && (((qg1 - kg1) < WIN) || lmv1);
                sv = ok ? sacc[j][3] * scale : NEGINF; sacc[j][3] = sv; tmax1 = fmaxf(tmax1, sv);
            }
        }
        tmax0 = fmaxf(tmax0, __shfl_xor_sync(0xffffffffu, tmax0, 1));
        tmax0 = fmaxf(tmax0, __shfl_xor_sync(0xffffffffu, tmax0, 2));
        tmax1 = fmaxf(tmax1, __shfl_xor_sync(0xffffffffu, tmax1, 1));
        tmax1 = fmaxf(tmax1, __shfl_xor_sync(0xffffffffu, tmax1, 2));

        float mn0 = fmaxf(m0r, tmax0), mn1 = fmaxf(m1r, tmax1);
        float alp0 = (m0r == mn0) ? 1.0f : __expf(m0r - mn0);
        float alp1 = (m1r == mn1) ? 1.0f : __expf(m1r - mn1);

        uint32_t ph[8][2], pl[8][2];
        float rs0 = 0.0f, rs1 = 0.0f;
#pragma unroll
        for (int j = 0; j < 8; j++) {
            if (j <= jmax) {
                float p0 = (sacc[j][0] == NEGINF) ? 0.0f : __expf(sacc[j][0] - mn0);
                float p1 = (sacc[j][1] == NEGINF) ? 0.0f : __expf(sacc[j][1] - mn0);
                float p2 = (sacc[j][2] == NEGINF) ? 0.0f : __expf(sacc[j][2] - mn1);
                float p3 = (sacc[j][3] == NEGINF) ? 0.0f : __expf(sacc[j][3] - mn1);
                rs0 += p0 + p1; rs1 += p2 + p3;
                float h0 = __bfloat162float(__float2bfloat16(p0));
                float h1 = __bfloat162float(__float2bfloat16(p1));
                float h2 = __bfloat162float(__float2bfloat16(p2));
                float h3 = __bfloat162float(__float2bfloat16(p3));
                ph[j][0] = pack_bf16(h0, h1);
                ph[j][1] = pack_bf16(h2, h3);
                pl[j][0] = pack_bf16(p0 - h0, p1 - h1);
                pl[j][1] = pack_bf16(p2 - h2, p3 - h3);
            } else {
                ph[j][0] = ph[j][1] = pl[j][0] = pl[j][1] = 0u;
            }
        }
        rs0 += __shfl_xor_sync(0xffffffffu, rs0, 1);
        rs0 += __shfl_xor_sync(0xffffffffu, rs0, 2);
        rs1 += __shfl_xor_sync(0xffffffffu, rs1, 1);
        rs1 += __shfl_xor_sync(0xffffffffu, rs1, 2);

        l0r = l0r * alp0 + rs0;
        l1r = l1r * alp1 + rs1;
        m0r = mn0; m1r = mn1;
#pragma unroll
        for (int jo = 0; jo < 16; jo++) {
            oacc[jo][0] *= alp0; oacc[jo][1] *= alp0;
            oacc[jo][2] *= alp1; oacc[jo][3] *= alp1;
        }

        uint32_t vh_s = kvb + 32768u, vl_s = kvb + 49152u;
#pragma unroll
        for (int t = 0; t < 4; t++) {
            if (t <= gmax) {
                uint32_t a0h = ph[2 * t][0], a1h = ph[2 * t][1];
                uint32_t a2h = ph[2 * t + 1][0], a3h = ph[2 * t + 1][1];
                uint32_t a0l = pl[2 * t][0], a1l = pl[2 * t][1];
                uint32_t a2l = pl[2 * t + 1][0], a3l = pl[2 * t + 1][1];
                int r = t * 16 + rV0;
                int rsw = r & 7;
                uint32_t rbase = (uint32_t)((r >> 3) * 1024 + rsw * 128);
#pragma unroll
                for (int gg = 0; gg < 8; gg++) {
                    int sub = gg >> 2;
                    int c = (gg & 3) * 2 + (lane >> 4);
                    uint32_t off = (uint32_t)(sub * 8192) + rbase + (uint32_t)((c ^ rsw) << 4);
                    uint32_t v0, v1, v2, v3, w0, w1, w2, w3;
                    LDSM4T(v0, v1, v2, v3, vh_s + off);
                    LDSM4T(w0, w1, w2, w3, vl_s + off);
                    MMA16816(oacc[gg * 2],     a0h, a1h, a2h, a3h, v0, v1);
                    MMA16816(oacc[gg * 2],     a0l, a1l, a2l, a3l, v0, v1);
                    MMA16816(oacc[gg * 2],     a0h, a1h, a2h, a3h, w0, w1);
                    MMA16816(oacc[gg * 2 + 1], a0h, a1h, a2h, a3h, v2, v3);
                    MMA16816(oacc[gg * 2 + 1], a0l, a1l, a2l, a3l, v2, v3);
                    MMA16816(oacc[gg * 2 + 1], a0h, a1h, a2h, a3h, w2, w3);
                }
            }
        }
    }

    float inv0 = 1.0f / l0r, inv1 = 1.0f / l1r;
    int h_w = kvh * 2 + (wid >> 2);
    size_t r0 = (size_t)(b * SS + qg0) * HIDN + (size_t)h_w * DH + (lane & 3) * 2;
    size_t r1 = (size_t)(b * SS + qg1) * HIDN + (size_t)h_w * DH + (lane & 3) * 2;
#pragma unroll
    for (int jo = 0; jo < 16; jo++) {
        int cofs = jo * 8;
        store_split2(ah_g + r0 + cofs, al_g + r0 + cofs, oacc[jo][0] * inv0, oacc[jo][1] * inv0);
        store_split2(ah_g + r1 + cofs, al_g + r1 + cofs, oacc[jo][2] * inv1, oacc[jo][3] * inv1);
    }
}

// ---------------- launch ----------------
extern "C" void kernel_launch(void* const* d_in, const int* in_sizes, int n_in,
                              void* d_out, int out_size)
{
    (void)in_sizes; (void)n_in; (void)out_size;
    const float* x  = (const float*)d_in[0];
    const float* Wq = (const float*)d_in[1];
    const float* Wk = (const float*)d_in[2];
    const float* Wv = (const float*)d_in[3];
    const float* Wo = (const float*)d_in[4];
    float* out = (float*)d_out;

    void *lmp, *xh, *xl, *qh, *ql, *kh, *kl, *vh, *vl, *ah, *al;
    void *wch, *wcl, *woh, *wol;
    cudaGetSymbolAddress(&lmp, g_lm);
    cudaGetSymbolAddress(&xh, g_xh);   cudaGetSymbolAddress(&xl, g_xl);
    cudaGetSymbolAddress(&qh, g_qh);   cudaGetSymbolAddress(&ql, g_ql);
    cudaGetSymbolAddress(&kh, g_kh);   cudaGetSymbolAddress(&kl, g_kl);
    cudaGetSymbolAddress(&vh, g_vh);   cudaGetSymbolAddress(&vl, g_vl);
    cudaGetSymbolAddress(&ah, g_ah);   cudaGetSymbolAddress(&al, g_al);
    cudaGetSymbolAddress(&wch, g_wch); cudaGetSymbolAddress(&wcl, g_wcl);
    cudaGetSymbolAddress(&woh, g_woh); cudaGetSymbolAddress(&wol, g_wol);

    static cudaStream_t s_side = nullptr;
    static cudaEvent_t  e_fork = nullptr, e_xsp = nullptr, e_join = nullptr;
    if (s_side == nullptr) {
        cudaStreamCreateWithFlags(&s_side, cudaStreamNonBlocking);
        cudaEventCreateWithFlags(&e_fork, cudaEventDisableTiming);
        cudaEventCreateWithFlags(&e_xsp,  cudaEventDisableTiming);
        cudaEventCreateWithFlags(&e_join, cudaEventDisableTiming);
    }

    cudaFuncSetAttribute((const void*)gemm_kernel<0, 48>, cudaFuncAttributeMaxDynamicSharedMemorySize, GEMM_SMEM_BYTES);
    cudaFuncSetAttribute((const void*)gemm_kernel<1, 96>, cudaFuncAttributeMaxDynamicSharedMemorySize, GEMM_SMEM_BYTES);
    cudaFuncSetAttribute((const void*)attn_mma_kernel,    cudaFuncAttributeMaxDynamicSharedMemorySize, ATT_SMEM);

    // ---- fork: xsplit first (QKV dependency), then Wo prep + TLS chain, on side ----
    cudaEventRecord(e_fork, 0);
    cudaStreamWaitEvent(s_side, e_fork, 0);

    xsplit_kernel<<<(MTOT * HIDN) / 1024, 256, 0, s_side>>>(x, (__nv_bfloat16*)xh, (__nv_bfloat16*)xl);
    cudaEventRecord(e_xsp, s_side);
    wsplit_wo_kernel<<<dim3(64, KDIM / 32), dim3(32, 8), 0, s_side>>>(
        Wo, (__nv_bfloat16*)woh, (__nv_bfloat16*)wol, out);
    meanp_kernel      <<<dim3(HIDN / 256, BB, 8), 256, 0, s_side>>>(x);
    meanf_mnorm_kernel<<<BB, 256, 0, s_side>>>();
    score_kernel      <<<dim3(SS, BB), 256, 0, s_side>>>(x);
    topk_kernel       <<<BB, 1024, 0, s_side>>>();
    cudaEventRecord(e_join, s_side);

    // ---- main stream: QKV weight prep (concurrent with xsplit/TLS) ----
    wsplit_qkv_kernel<<<dim3(64, KDIM / 32, 3), dim3(32, 8)>>>(
        Wq, Wk, Wv, (__nv_bfloat16*)wch, (__nv_bfloat16*)wcl);

    // ---- QKV projection (needs xsplit) ----
    cudaStreamWaitEvent(0, e_xsp, 0);
    gemm_kernel<1, 96><<<dim3(NQKV / 128, MTOT / 128), 256, GEMM_SMEM_BYTES>>>(
        (const __nv_bfloat16*)xh, (const __nv_bfloat16*)xl,
        (__nv_bfloat16*)wch, (__nv_bfloat16*)wcl,
        nullptr,
        (__nv_bfloat16*)qh, (__nv_bfloat16*)ql,
        (__nv_bfloat16*)kh, (__nv_bfloat16*)kl,
        (__nv_bfloat16*)vh, (__nv_bfloat16*)vl);

    // ---- join: attention needs the landmark mask (and out is zeroed by now) ----
    cudaStreamWaitEvent(0, e_join, 0);

    attn_mma_kernel<<<dim3(BB * NKVH, SS / 64), 256, ATT_SMEM>>>(
        (const __nv_bfloat16*)qh, (const __nv_bfloat16*)ql,
        (const __nv_bfloat16*)kh, (const __nv_bfloat16*)kl,
        (const __nv_bfloat16*)vh, (const __nv_bfloat16*)vl,
        (const int*)lmp, (__nv_bfloat16*)ah, (__nv_bfloat16*)al);

    // ---- output projection: split-K2, deterministic vector red.add ----
    gemm_kernel<0, 48><<<dim3(HIDN / 128, MTOT / 128, 2), 256, GEMM_SMEM_BYTES>>>(
        (const __nv_bfloat16*)ah, (const __nv_bfloat16*)al,
        (const __nv_bfloat16*)woh, (const __nv_bfloat16*)wol,
        out, nullptr, nullptr, nullptr, nullptr, nullptr, nullptr);
}

// round 14
// speedup vs baseline: 1.0584x; 1.0013x over previous
#include <cuda_runtime.h>
#include <cuda_bf16.h>
#include <math.h>
#include <stdint.h>

// ---------------- problem constants ----------------
#define BB   2
#define SS   2048
#define HIDN 2048
#define NH   16
#define NKVH 8
#define DH   128
#define KVD  1024
#define WIN  128
#define TOPK 675
#define MTOT (BB * SS)
#define KDIM 2048
#define NQKV 4096

// ---------------- scratch ----------------
__device__ double g_meanp[8 * BB * HIDN];
__device__ float  g_mean[BB * HIDN];
__device__ double g_mnorm[BB];
__device__ float  g_score[BB * SS];
__device__ int    g_lm[BB * SS];

__device__ __nv_bfloat16 g_xh[MTOT * HIDN], g_xl[MTOT * HIDN];
__device__ __nv_bfloat16 g_qh[MTOT * HIDN], g_ql[MTOT * HIDN];
__device__ __nv_bfloat16 g_kh[MTOT * KVD],  g_kl[MTOT * KVD];
__device__ __nv_bfloat16 g_vh[MTOT * KVD],  g_vl[MTOT * KVD];
__device__ __nv_bfloat16 g_ah[MTOT * HIDN], g_al[MTOT * HIDN];
__device__ __nv_bfloat16 g_wch[NQKV * KDIM], g_wcl[NQKV * KDIM];
__device__ __nv_bfloat16 g_woh[HIDN * KDIM], g_wol[HIDN * KDIM];

// ---------------- PTX helpers ----------------
__device__ __forceinline__ uint32_t s2u(const void* p) {
    uint32_t a;
    asm("{ .reg .u64 t; cvta.to.shared.u64 t, %1; cvt.u32.u64 %0, t; }" : "=r"(a) : "l"(p));
    return a;
}
#define CP16(saddr, gptr) \
    asm volatile("cp.async.cg.shared.global [%0], [%1], 16;" :: "r"(saddr), "l"(gptr))
#define CP_COMMIT() asm volatile("cp.async.commit_group;" ::: "memory")
#define CP_WAIT(n)  asm volatile("cp.async.wait_group %0;" :: "n"(n) : "memory")

#define LDSM4(r0, r1, r2, r3, addr) \
    asm volatile("ldmatrix.sync.aligned.m8n8.x4.shared.b16 {%0,%1,%2,%3}, [%4];" \
                 : "=r"(r0), "=r"(r1), "=r"(r2), "=r"(r3) : "r"(addr))
#define LDSM4T(r0, r1, r2, r3, addr) \
    asm volatile("ldmatrix.sync.aligned.m8n8.x4.trans.shared.b16 {%0,%1,%2,%3}, [%4];" \
                 : "=r"(r0), "=r"(r1), "=r"(r2), "=r"(r3) : "r"(addr))

#define MMA16816(D, a0, a1, a2, a3, b0, b1) \
    asm volatile("mma.sync.aligned.m16n8k16.row.col.f32.bf16.bf16.f32 " \
                 "{%0,%1,%2,%3}, {%4,%5,%6,%7}, {%8,%9}, {%0,%1,%2,%3};" \
                 : "+f"((D)[0]), "+f"((D)[1]), "+f"((D)[2]), "+f"((D)[3]) \
                 : "r"(a0), "r"(a1), "r"(a2), "r"(a3), "r"(b0), "r"(b1))

#define REDV2(ptr, v0, v1) \
    asm volatile("red.global.add.v2.f32 [%0], {%1, %2};" \
                 :: "l"(ptr), "f"(v0), "f"(v1) : "memory")

// direct ex2 (scores pre-scaled into log2 domain; saves the implicit FMUL in __expf)
__device__ __forceinline__ float ex2f(float x) {
    float r;
    asm("ex2.approx.f32 %0, %1;" : "=f"(r) : "f"(x));
    return r;
}

__device__ __forceinline__ uint32_t pack_bf16(float lo, float hi) {
    uint32_t r;
    asm("cvt.rn.bf16x2.f32 %0, %1, %2;" : "=r"(r) : "f"(hi), "f"(lo));
    return r;
}
__device__ __forceinline__ void store_split2(__nv_bfloat16* Hp, __nv_bfloat16* Lp,
                                             float v0, float v1) {
    __nv_bfloat16 h0 = __float2bfloat16(v0), h1 = __float2bfloat16(v1);
    __nv_bfloat16 l0 = __float2bfloat16(v0 - __bfloat162float(h0));
    __nv_bfloat16 l1 = __float2bfloat16(v1 - __bfloat162float(h1));
    *(__nv_bfloat162*)Hp = __halves2bfloat162(h0, h1);
    *(__nv_bfloat162*)Lp = __halves2bfloat162(l0, l1);
}

// ---------------- mean stage 1 ----------------
__global__ void meanp_kernel(const float* __restrict__ x) {
    int f = blockIdx.x * 256 + threadIdx.x;
    int b = blockIdx.y, ch = blockIdx.z;
    const float* p = x + ((size_t)b * SS + (size_t)ch * 256) * HIDN + f;
    double a0 = 0, a1 = 0;
    for (int s = 0; s < 256; s += 2) {
        a0 += (double)p[(size_t)s * HIDN];
        a1 += (double)p[(size_t)(s + 1) * HIDN];
    }
    g_meanp[((size_t)ch * BB + b) * HIDN + f] = a0 + a1;
}

// ---------------- mean stage 2 fused with ||mean|| ----------------
__global__ void meanf_mnorm_kernel() {
    int b = blockIdx.x, tid = threadIdx.x;
    __shared__ double red[8];
    double acc = 0;
    for (int f = tid; f < HIDN; f += 256) {
        double t = 0;
        for (int ch = 0; ch < 8; ch++) t += g_meanp[((size_t)ch * BB + b) * HIDN + f];
        float m = (float)(t / (double)SS);
        g_mean[b * HIDN + f] = m;
        acc += (double)m * (double)m;
    }
    for (int off = 16; off > 0; off >>= 1)
        acc += __shfl_down_sync(0xffffffffu, acc, off);
    if ((tid & 31) == 0) red[tid >> 5] = acc;
    __syncthreads();
    if (tid == 0) {
        double t = 0;
        for (int w = 0; w < 8; w++) t += red[w];
        g_mnorm[b] = sqrt(t);
    }
}

// ---------------- score ----------------
__global__ void score_kernel(const float* __restrict__ x) {
    int row = blockIdx.x, b = blockIdx.y, tid = threadIdx.x;
    __shared__ double redn[8], redd[8];
    size_t roff = ((size_t)b * SS + row) * HIDN;
    const float* xr = x + roff;
    const float* mr = g_mean + b * HIDN;
    double n2 = 0, dt = 0;
    for (int c = tid; c < HIDN; c += 256) {
        float xv = xr[c];
        n2 += (double)xv * (double)xv;
        dt += (double)xv * (double)mr[c];
    }
    for (int off = 16; off > 0; off >>= 1) {
        n2 += __shfl_down_sync(0xffffffffu, n2, off);
        dt += __shfl_down_sync(0xffffffffu, dt, off);
    }
    if ((tid & 31) == 0) { redn[tid >> 5] = n2; redd[tid >> 5] = dt; }
    __syncthreads();
    if (tid == 0) {
        double tn = 0, td = 0;
        for (int w = 0; w < 8; w++) { tn += redn[w]; td += redd[w]; }
        double nrm = sqrt(tn);
        double div = -td / (nrm * g_mnorm[b] + 1e-6);
        g_score[b * SS + row] = (float)(0.7 * nrm + 0.3 * div);
    }
}

// ---------------- exact top-k (bitonic) + dilation ----------------
__global__ void topk_kernel() {
    int b = blockIdx.x, tid = threadIdx.x;
    __shared__ unsigned long long sd[SS];
    __shared__ unsigned char l0[SS], l1[SS];
    for (int i = tid; i < SS; i += 1024) {
        unsigned fb = __float_as_uint(g_score[b * SS + i]);
        unsigned key = (fb & 0x80000000u) ? ~fb : (fb | 0x80000000u);
        sd[i] = ((unsigned long long)key << 32) | (0xFFFFFFFFu - (unsigned)i);
    }
    __syncthreads();
    for (int k2 = 2; k2 <= SS; k2 <<= 1) {
        for (int j = k2 >> 1; j > 0; j >>= 1) {
            for (int i = tid; i < SS; i += 1024) {
                int ixj = i ^ j;
                if (ixj > i) {
                    bool asc = ((i & k2) == 0);
                    unsigned long long a = sd[i], c = sd[ixj];
                    if ((a > c) == asc) { sd[i] = c; sd[ixj] = a; }
                }
            }
            __syncthreads();
        }
    }
    unsigned long long kth = sd[SS - TOPK];
    __syncthreads();
    for (int i = tid; i < SS; i += 1024) {
        unsigned fb = __float_as_uint(g_score[b * SS + i]);
        unsigned key = (fb & 0x80000000u) ? ~fb : (fb | 0x80000000u);
        unsigned long long comp = ((unsigned long long)key << 32) | (0xFFFFFFFFu - (unsigned)i);
        l0[i] = (comp >= kth) ? 1 : 0;
    }
    __syncthreads();
    for (int i = tid; i < SS; i += 1024) {
        unsigned char v = l0[i];
        if (i > 0)      v |= l0[i - 1];
        if (i < SS - 1) v |= l0[i + 1];
        l1[i] = v;
    }
    __syncthreads();
    for (int i = tid; i < SS; i += 1024) {
        unsigned char v = l1[i];
        if (i > 0)      v |= l1[i - 1];
        if (i < SS - 1) v |= l1[i + 1];
        g_lm[b * SS + i] = (int)v;
    }
}

// ---------------- split fp32 -> (bf16 hi, bf16 lo) ----------------
__global__ void xsplit_kernel(const float* __restrict__ X,
                              __nv_bfloat16* __restrict__ Xh,
                              __nv_bfloat16* __restrict__ Xl) {
    int i = (blockIdx.x * 256 + threadIdx.x) * 4;
#pragma unroll
    for (int j = 0; j < 4; j++) {
        float v = X[i + j];
        __nv_bfloat16 h = __float2bfloat16(v);
        Xh[i + j] = h;
        Xl[i + j] = __float2bfloat16(v - __bfloat162float(h));
    }
}

// ---------------- transpose+split: QKV weights (main stream, z in 0..2) --------
__global__ void wsplit_qkv_kernel(const float* __restrict__ W0, const float* __restrict__ W1,
                                  const float* __restrict__ W2,
                                  __nv_bfloat16* __restrict__ wch, __nv_bfloat16* __restrict__ wcl)
{
    __shared__ float t[32][33];
    int z = blockIdx.z;
    const float* W; __nv_bfloat16 *Th, *Tl; int N;
    if (z == 0)      { W = W0; Th = wch;                       Tl = wcl;                       N = 2048; }
    else if (z == 1) { W = W1; Th = wch + (size_t)2048 * KDIM; Tl = wcl + (size_t)2048 * KDIM; N = 1024; }
    else             { W = W2; Th = wch + (size_t)3072 * KDIM; Tl = wcl + (size_t)3072 * KDIM; N = 1024; }
    int n0 = blockIdx.x * 32, k0 = blockIdx.y * 32;
    if (n0 >= N) return;
    int tx = threadIdx.x, ty = threadIdx.y;
#pragma unroll
    for (int i = 0; i < 32; i += 8)
        t[ty + i][tx] = W[(size_t)(k0 + ty + i) * N + n0 + tx];
    __syncthreads();
#pragma unroll
    for (int i = 0; i < 32; i += 8) {
        float v = t[tx][ty + i];
        __nv_bfloat16 h = __float2bfloat16(v);
        __nv_bfloat16 l = __float2bfloat16(v - __bfloat162float(h));
        size_t o = (size_t)(n0 + ty + i) * KDIM + k0 + tx;
        Th[o] = h;
        Tl[o] = l;
    }
}

// ---------------- transpose+split: Wo + zero out (side stream) ------------------
// zero coverage: grid 64x64, 256 thr, 8 floats/thr = 8,388,608 = MTOT*HIDN exactly.
__global__ void wsplit_wo_kernel(const float* __restrict__ W3,
                                 __nv_bfloat16* __restrict__ woh, __nv_bfloat16* __restrict__ wol,
                                 float* __restrict__ out_zero)
{
    __shared__ float t[32][33];
    int n0 = blockIdx.x * 32, k0 = blockIdx.y * 32;
    int tid1 = threadIdx.y * 32 + threadIdx.x;
    {
        size_t id = (((size_t)blockIdx.y * 64 + blockIdx.x) * 256 + tid1) * 8;
        float4 zz = make_float4(0.f, 0.f, 0.f, 0.f);
        *(float4*)(out_zero + id)     = zz;
        *(float4*)(out_zero + id + 4) = zz;
    }
    int tx = threadIdx.x, ty = threadIdx.y;
#pragma unroll
    for (int i = 0; i < 32; i += 8)
        t[ty + i][tx] = W3[(size_t)(k0 + ty + i) * HIDN + n0 + tx];
    __syncthreads();
#pragma unroll
    for (int i = 0; i < 32; i += 8) {
        float v = t[tx][ty + i];
        __nv_bfloat16 h = __float2bfloat16(v);
        __nv_bfloat16 l = __float2bfloat16(v - __bfloat162float(h));
        size_t o = (size_t)(n0 + ty + i) * KDIM + k0 + tx;
        woh[o] = h;
        wol[o] = l;
    }
}

// ---------------- mma.sync split GEMM (128x128, 3-stage) -----------
#define GBK 64
#define TILEB 16384u
#define BUFB  32768u
#define GEMM_SMEM_BYTES (3 * 32768 + 1024)

template<int NST>
__device__ __forceinline__ void load_tiles_async(
    int tid, int s, int m0, int n0, int koff,
    const __nv_bfloat16* __restrict__ Ah, const __nv_bfloat16* __restrict__ Al,
    const __nv_bfloat16* __restrict__ Bh, const __nv_bfloat16* __restrict__ Bl,
    uint32_t bufA)
{
    constexpr int SEGL = NST / 3;
    int seg = s / SEGL;
    int kk  = (s % SEGL) * GBK + koff;
    const __nv_bfloat16* Ap = (seg == 1) ? Al : Ah;
    const __nv_bfloat16* Bp = (seg == 2) ? Bl : Bh;
    uint32_t bufB = bufA + TILEB;
#pragma unroll
    for (int j = 0; j < 4; j++) {
        int id = tid + j * 256;
        int row = id >> 3, c = id & 7;
        uint32_t sw = (uint32_t)((row >> 3) * 1024 + (row & 7) * 128 + ((c ^ (row & 7)) << 4));
        CP16(bufA + sw, (const void*)(Ap + (size_t)(m0 + row) * KDIM + kk + c * 8));
        CP16(bufB + sw, (const void*)(Bp + (size_t)(n0 + row) * KDIM + kk + c * 8));
    }
}

template<int MODE, int NST>
__global__ void __launch_bounds__(256) gemm_kernel(
    const __nv_bfloat16* __restrict__ Ah, const __nv_bfloat16* __restrict__ Al,
    const __nv_bfloat16* __restrict__ Bh, const __nv_bfloat16* __restrict__ Bl,
    float* __restrict__ Cf,
    __nv_bfloat16* __restrict__ qh, __nv_bfloat16* __restrict__ ql,
    __nv_bfloat16* __restrict__ kh, __nv_bfloat16* __restrict__ kl,
    __nv_bfloat16* __restrict__ vh, __nv_bfloat16* __restrict__ vl)
{
    extern __shared__ char dsm[];
    uint32_t tbase = (s2u(dsm) + 1023u) & ~1023u;

    int tid = threadIdx.x, lane = tid & 31, wid = tid >> 5;
    int wm = wid >> 2, wn = wid & 3;
    int m0 = blockIdx.y * 128, n0 = blockIdx.x * 128;
    int koff = (int)blockIdx.z * ((NST / 3) * GBK);

    int aR = lane & 15, aC = lane >> 4;
    int bR = ((lane >> 4) << 3) + (lane & 7);
    int bC = (lane >> 3) & 1;

    uint32_t aOff[4]; int aSw[4];
#pragma unroll
    for (int f = 0; f < 4; f++) {
        int r = wm * 64 + f * 16 + aR;
        aOff[f] = (uint32_t)((r >> 3) * 1024 + (r & 7) * 128);
        aSw[f]  = r & 7;
    }
    uint32_t bOff[2]; int bSw[2];
#pragma unroll
    for (int g = 0; g < 2; g++) {
        int r = wn * 32 + g * 16 + bR;
        bOff[g] = (uint32_t)((r >> 3) * 1024 + (r & 7) * 128);
        bSw[g]  = r & 7;
    }

    float acc[4][4][4];
#pragma unroll
    for (int f = 0; f < 4; f++)
#pragma unroll
        for (int n8 = 0; n8 < 4; n8++)
#pragma unroll
            for (int e = 0; e < 4; e++) acc[f][n8][e] = 0.0f;

    load_tiles_async<NST>(tid, 0, m0, n0, koff, Ah, Al, Bh, Bl, tbase);
    CP_COMMIT();
    load_tiles_async<NST>(tid, 1, m0, n0, koff, Ah, Al, Bh, Bl, tbase + BUFB);
    CP_COMMIT();

    int bidx = 0, pre = 2;
    for (int s = 0; s < NST; s++) {
        if (s == NST - 1) { CP_WAIT(0); } else { CP_WAIT(1); }
        __syncthreads();
        if (s + 2 < NST) {
            load_tiles_async<NST>(tid, s + 2, m0, n0, koff, Ah, Al, Bh, Bl,
                                  tbase + (uint32_t)pre * BUFB);
            CP_COMMIT();
        }

        uint32_t bufA = tbase + (uint32_t)bidx * BUFB;
        uint32_t bufB = bufA + TILEB;
#pragma unroll
        for (int k16 = 0; k16 < 4; k16++) {
            int ca = k16 * 2 + aC, cb = k16 * 2 + bC;
            uint32_t a[4][4], b[2][4];
#pragma unroll
            for (int f = 0; f < 4; f++)
                LDSM4(a[f][0], a[f][1], a[f][2], a[f][3],
                      bufA + aOff[f] + (uint32_t)((ca ^ aSw[f]) << 4));
#pragma unroll
            for (int g = 0; g < 2; g++)
                LDSM4(b[g][0], b[g][1], b[g][2], b[g][3],
                      bufB + bOff[g] + (uint32_t)((cb ^ bSw[g]) << 4));
#pragma unroll
            for (int f = 0; f < 4; f++)
#pragma unroll
                for (int n8 = 0; n8 < 4; n8++) {
                    int g = n8 >> 1, p = (n8 & 1) * 2;
                    MMA16816(acc[f][n8], a[f][0], a[f][1], a[f][2], a[f][3],
                             b[g][p], b[g][p + 1]);
                }
        }
        if (++bidx == 3) bidx = 0;
        if (++pre == 3) pre = 0;
    }

    int row0 = m0 + wm * 64 + (lane >> 2);
    int col0 = wn * 32 + (lane & 3) * 2;
    if (MODE == 0) {
        // split-K accumulate: 2 commutative vector adds per element pair onto 0
#pragma unroll
        for (int f = 0; f < 4; f++)
#pragma unroll
            for (int n8 = 0; n8 < 4; n8++) {
                int r = row0 + f * 16, c = n0 + col0 + n8 * 8;
                REDV2(Cf + (size_t)r * HIDN + c,       acc[f][n8][0], acc[f][n8][1]);
                REDV2(Cf + (size_t)(r + 8) * HIDN + c, acc[f][n8][2], acc[f][n8][3]);
            }
    } else {
        __nv_bfloat16 *Hp, *Lp; int Nout, cb;
        if (n0 < 2048)      { Hp = qh; Lp = ql; Nout = HIDN; cb = n0 + col0; }
        else if (n0 < 3072) { Hp = kh; Lp = kl; Nout = KVD;  cb = n0 - 2048 + col0; }
        else                { Hp = vh; Lp = vl; Nout = KVD;  cb = n0 - 3072 + col0; }
#pragma unroll
        for (int f = 0; f < 4; f++)
#pragma unroll
            for (int n8 = 0; n8 < 4; n8++) {
                int r = row0 + f * 16, c = cb + n8 * 8;
                store_split2(Hp + (size_t)r * Nout + c, Lp + (size_t)r * Nout + c,
                             acc[f][n8][0], acc[f][n8][1]);
                store_split2(Hp + (size_t)(r + 8) * Nout + c, Lp + (size_t)(r + 8) * Nout + c,
                             acc[f][n8][2], acc[f][n8][3]);
            }
    }
}

// ---------------- split-bf16 mma flash attention, GQA head-paired, LPT order ----
#define SM_QH 0u
#define SM_QL 32768u
#define SM_KV 65536u
#define SM_LM 196608u
#define ATT_SMEM (196608 + 512 + 1024)
#define NEGINF __int_as_float(0xff800000)

__device__ __forceinline__ void att_load_kv(
    int tid, uint32_t base, int bsel, int k0,
    const __nv_bfloat16* __restrict__ khb, const __nv_bfloat16* __restrict__ klb,
    const __nv_bfloat16* __restrict__ vhb, const __nv_bfloat16* __restrict__ vlb,
    const int* __restrict__ lmb)
{
    uint32_t kb = base + SM_KV + (uint32_t)bsel * 65536u;
#pragma unroll
    for (int i = 0; i < 4; i++) {
        int id = tid + i * 256;
        int r = id >> 4, c16 = id & 15, sub = c16 >> 3, c = c16 & 7;
        uint32_t sw = (uint32_t)(sub * 8192 + (r >> 3) * 1024 + (r & 7) * 128 + ((c ^ (r & 7)) << 4));
        size_t so = (size_t)(k0 + r) * KVD + sub * 64 + c * 8;
        CP16(kb + sw,          (const void*)(khb + so));
        CP16(kb + 16384u + sw, (const void*)(klb + so));
        CP16(kb + 32768u + sw, (const void*)(vhb + so));
        CP16(kb + 49152u + sw, (const void*)(vlb + so));
    }
    if (tid < 16)
        CP16(base + SM_LM + (uint32_t)bsel * 256u + (uint32_t)tid * 16u,
             (const void*)(lmb + k0 + tid * 4));
}

__global__ void __launch_bounds__(256) attn_mma_kernel(
    const __nv_bfloat16* __restrict__ qh_g, const __nv_bfloat16* __restrict__ ql_g,
    const __nv_bfloat16* __restrict__ kh_g, const __nv_bfloat16* __restrict__ kl_g,
    const __nv_bfloat16* __restrict__ vh_g, const __nv_bfloat16* __restrict__ vl_g,
    const int* __restrict__ lm,
    __nv_bfloat16* __restrict__ ah_g, __nv_bfloat16* __restrict__ al_g)
{
    extern __shared__ char dsm[];
    uint32_t base = (s2u(dsm) + 1023u) & ~1023u;
    uint32_t pad  = base - s2u(dsm);

    int tid = threadIdx.x, lane = tid & 31, wid = tid >> 5;
    int bh = blockIdx.x;
    int qt = (int)gridDim.y - 1 - (int)blockIdx.y;
    int b = bh >> 3, kvh = bh & 7;
    int q0 = qt * 64;

    const __nv_bfloat16* khb = kh_g + ((size_t)b * SS) * KVD + kvh * DH;
    const __nv_bfloat16* klb = kl_g + ((size_t)b * SS) * KVD + kvh * DH;
    const __nv_bfloat16* vhb = vh_g + ((size_t)b * SS) * KVD + kvh * DH;
    const __nv_bfloat16* vlb = vl_g + ((size_t)b * SS) * KVD + kvh * DH;
    const int* lmb = lm + b * SS;

#pragma unroll
    for (int i = 0; i < 8; i++) {
        int id = tid + i * 256;
        int r = id >> 4, c16 = id & 15, sub = c16 >> 3, c = c16 & 7;
        uint32_t sw = (uint32_t)(sub * 16384 + (r >> 3) * 1024 + (r & 7) * 128 + ((c ^ (r & 7)) << 4));
        size_t so = ((size_t)(b * SS + q0 + (r & 63))) * HIDN
                  + (size_t)(kvh * 2 + (r >> 6)) * DH + sub * 64 + c * 8;
        CP16(base + SM_QH + sw, (const void*)(qh_g + so));
        CP16(base + SM_QL + sw, (const void*)(ql_g + so));
    }
    CP_COMMIT();
    att_load_kv(tid, base, 0, 0, khb, klb, vhb, vlb, lmb);
    CP_COMMIT();

    float m0r = NEGINF, m1r = NEGINF, l0r = 0.0f, l1r = 0.0f;
    float oacc[16][4];
#pragma unroll
    for (int jo = 0; jo < 16; jo++)
#pragma unroll
        for (int e = 0; e < 4; e++) oacc[jo][e] = 0.0f;

    // scores pre-scaled into log2 domain: scale * log2(e)
    const float scale = 0.08838834764831845f * 1.4426950408889634f;
    int strip = wid & 3;
    int qg0 = q0 + strip * 16 + (lane >> 2);
    int qg1 = qg0 + 8;
    int qmaxw = q0 + strip * 16 + 15;

    int aR = wid * 16 + (lane & 15);
    uint32_t aOff = (uint32_t)((aR >> 3) * 1024 + (aR & 7) * 128);
    int aSw = aR & 7;
    int bRr = ((lane >> 4) << 3) + (lane & 7);
    int rV0 = (lane & 7) + ((lane >> 3) & 1) * 8;

    CP_WAIT(1);
    __syncthreads();
    uint32_t qfh[8][4], qfl[8][4];
#pragma unroll
    for (int k16 = 0; k16 < 8; k16++) {
        int sub = k16 >> 2;
        int ca = (k16 & 3) * 2 + (lane >> 4);
        uint32_t aaddr = (uint32_t)(sub * 16384) + aOff + (uint32_t)((ca ^ aSw) << 4);
        LDSM4(qfh[k16][0], qfh[k16][1], qfh[k16][2], qfh[k16][3], base + SM_QH + aaddr);
        LDSM4(qfl[k16][0], qfl[k16][1], qfl[k16][2], qfl[k16][3], base + SM_QL + aaddr);
    }

    int nkt = qt + 1;
    for (int kt = 0; kt < nkt; kt++) {
        int k0 = kt * 64, bsel = kt & 1;
        CP_WAIT(0);
        __syncthreads();
        if (kt + 1 < nkt) {
            att_load_kv(tid, base, bsel ^ 1, (kt + 1) * 64, khb, klb, vhb, vlb, lmb);
            CP_COMMIT();
        }

        uint32_t kvb = base + SM_KV + (uint32_t)bsel * 65536u;
        const int* lms = (const int*)(dsm + pad + SM_LM + bsel * 256);
        int kmax = qmaxw - k0;
        int jmax = min(7, kmax >> 3);
        int gmax = jmax >> 1;

        float sacc[8][4];
#pragma unroll
        for (int j = 0; j < 8; j++)
#pragma unroll
            for (int e = 0; e < 4; e++) sacc[j][e] = 0.0f;

        uint32_t kh_s = kvb, kl_s = kvb + 16384u;
#pragma unroll
        for (int k16 = 0; k16 < 8; k16++) {
            int sub = k16 >> 2;
            int cb = (k16 & 3) * 2 + ((lane >> 3) & 1);
            uint32_t bhm[4][4], blm[4][4];
#pragma unroll
            for (int g = 0; g < 4; g++) {
                if (g <= gmax) {
                    int r = g * 16 + bRr;
                    uint32_t off = (uint32_t)(sub * 8192 + (r >> 3) * 1024 + (r & 7) * 128 +
                                              ((cb ^ (r & 7)) << 4));
                    LDSM4(bhm[g][0], bhm[g][1], bhm[g][2], bhm[g][3], kh_s + off);
                    LDSM4(blm[g][0], blm[g][1], blm[g][2], blm[g][3], kl_s + off);
                }
            }
#pragma unroll
            for (int j = 0; j < 8; j++) {
                if (j <= jmax) {
                    int g = j >> 1, p = (j & 1) * 2;
                    MMA16816(sacc[j], qfh[k16][0], qfh[k16][1], qfh[k16][2], qfh[k16][3],
                             bhm[g][p], bhm[g][p + 1]);
                    MMA16816(sacc[j], qfl[k16][0], qfl[k16][1], qfl[k16][2], qfl[k16][3],
                             bhm[g][p], bhm[g][p + 1]);
                    MMA16816(sacc[j], qfh[k16][0], qfh[k16][1], qfh[k16][2], qfh[k16][3],
                             blm[g][p], blm[g][p + 1]);
                }
            }
        }

        float tmax0 = NEGINF, tmax1 = NEGINF;
        int colb = (lane & 3) * 2;
#pragma unroll
        for (int j = 0; j < 8; j++) {
            if (j <= jmax) {
                int kk0 = j * 8 + colb, kk1 = kk0 + 1;
                int kg0 = k0 + kk0, kg1 = kg0 + 1;
                int lmv0 = lms[kk0], lmv1 = lms[kk1];
                float sv;
                bool ok;
                ok = (kg0 <= qg0) && (((qg0 - kg0) < WIN) || lmv0);
                sv = ok ? sacc[j][0] * scale : NEGINF; sacc[j][0] = sv; tmax0 = fmaxf(tmax0, sv);
                ok = (kg1 <= qg0) && (((qg0 - kg1) < WIN) || lmv1);
                sv = ok ? sacc[j][1] * scale : NEGINF; sacc[j][1] = sv; tmax0 = fmaxf(tmax0, sv);
                ok = (kg0 <= qg1) && (((qg1 - kg0) < WIN) || lmv0);
                sv = ok ? sacc[j][2] * scale : NEGINF; sacc[j][2] = sv; tmax1 = fmaxf(tmax1, sv);
                ok = (kg1 <= qg1) && (((qg1 - kg1) < WIN) || lmv1);
                sv = ok ? sacc[j][3] * scale : NEGINF; sacc[j][3] = sv; tmax1 = fmaxf(tmax1, sv);
            }
        }
        tmax0 = fmaxf(tmax0, __shfl_xor_sync(0xffffffffu, tmax0, 1));
        tmax0 = fmaxf(tmax0, __shfl_xor_sync(0xffffffffu, tmax0, 2));
        tmax1 = fmaxf(tmax1, __shfl_xor_sync(0xffffffffu, tmax1, 1));
        tmax1 = fmaxf(tmax1, __shfl_xor_sync(0xffffffffu, tmax1, 2));

        float mn0 = fmaxf(m0r, tmax0), mn1 = fmaxf(m1r, tmax1);
        float alp0 = (m0r == mn0) ? 1.0f : ex2f(m0r - mn0);
        float alp1 = (m1r == mn1) ? 1.0f : ex2f(m1r - mn1);

        uint32_t ph[8][2], pl[8][2];
        float rs0 = 0.0f, rs1 = 0.0f;
#pragma unroll
        for (int j = 0; j < 8; j++) {
            if (j <= jmax) {
                float p0 = (sacc[j][0] == NEGINF) ? 0.0f : ex2f(sacc[j][0] - mn0);
                float p1 = (sacc[j][1] == NEGINF) ? 0.0f : ex2f(sacc[j][1] - mn0);
                float p2 = (sacc[j][2] == NEGINF) ? 0.0f : ex2f(sacc[j][2] - mn1);
                float p3 = (sacc[j][3] == NEGINF) ? 0.0f : ex2f(sacc[j][3] - mn1);
                rs0 += p0 + p1; rs1 += p2 + p3;
                float h0 = __bfloat162float(__float2bfloat16(p0));
                float h1 = __bfloat162float(__float2bfloat16(p1));
                float h2 = __bfloat162float(__float2bfloat16(p2));
                float h3 = __bfloat162float(__float2bfloat16(p3));
                ph[j][0] = pack_bf16(h0, h1);
                ph[j][1] = pack_bf16(h2, h3);
                pl[j][0] = pack_bf16(p0 - h0, p1 - h1);
                pl[j][1] = pack_bf16(p2 - h2, p3 - h3);
            } else {
                ph[j][0] = ph[j][1] = pl[j][0] = pl[j][1] = 0u;
            }
        }
        rs0 += __shfl_xor_sync(0xffffffffu, rs0, 1);
        rs0 += __shfl_xor_sync(0xffffffffu, rs0, 2);
        rs1 += __shfl_xor_sync(0xffffffffu, rs1, 1);
        rs1 += __shfl_xor_sync(0xffffffffu, rs1, 2);

        l0r = l0r * alp0 + rs0;
        l1r = l1r * alp1 + rs1;
        m0r = mn0; m1r = mn1;
#pragma unroll
        for (int jo = 0; jo < 16; jo++) {
            oacc[jo][0] *= alp0; oacc[jo][1] *= alp0;
            oacc[jo][2] *= alp1; oacc[jo][3] *= alp1;
        }

        uint32_t vh_s = kvb + 32768u, vl_s = kvb + 49152u;
#pragma unroll
        for (int t = 0; t < 4; t++) {
            if (t <= gmax) {
                uint32_t a0h = ph[2 * t][0], a1h = ph[2 * t][1];
                uint32_t a2h = ph[2 * t + 1][0], a3h = ph[2 * t + 1][1];
                uint32_t a0l = pl[2 * t][0], a1l = pl[2 * t][1];
                uint32_t a2l = pl[2 * t + 1][0], a3l = pl[2 * t + 1][1];
                int r = t * 16 + rV0;
                int rsw = r & 7;
                uint32_t rbase = (uint32_t)((r >> 3) * 1024 + rsw * 128);
#pragma unroll
                for (int gg = 0; gg < 8; gg++) {
                    int sub = gg >> 2;
                    int c = (gg & 3) * 2 + (lane >> 4);
                    uint32_t off = (uint32_t)(sub * 8192) + rbase + (uint32_t)((c ^ rsw) << 4);
                    uint32_t v0, v1, v2, v3, w0, w1, w2, w3;
                    LDSM4T(v0, v1, v2, v3, vh_s + off);
                    LDSM4T(w0, w1, w2, w3, vl_s + off);
                    MMA16816(oacc[gg * 2],     a0h, a1h, a2h, a3h, v0, v1);
                    MMA16816(oacc[gg * 2],     a0l, a1l, a2l, a3l, v0, v1);
                    MMA16816(oacc[gg * 2],     a0h, a1h, a2h, a3h, w0, w1);
                    MMA16816(oacc[gg * 2 + 1], a0h, a1h, a2h, a3h, v2, v3);
                    MMA16816(oacc[gg * 2 + 1], a0l, a1l, a2l, a3l, v2, v3);
                    MMA16816(oacc[gg * 2 + 1], a0h, a1h, a2h, a3h, w2, w3);
                }
            }
        }
    }

    float inv0 = 1.0f / l0r, inv1 = 1.0f / l1r;
    int h_w = kvh * 2 + (wid >> 2);
    size_t r0 = (size_t)(b * SS + qg0) * HIDN + (size_t)h_w * DH + (lane & 3) * 2;
    size_t r1 = (size_t)(b * SS + qg1) * HIDN + (size_t)h_w * DH + (lane & 3) * 2;
#pragma unroll
    for (int jo = 0; jo < 16; jo++) {
        int cofs = jo * 8;
        store_split2(ah_g + r0 + cofs, al_g + r0 + cofs, oacc[jo][0] * inv0, oacc[jo][1] * inv0);
        store_split2(ah_g + r1 + cofs, al_g + r1 + cofs, oacc[jo][2] * inv1, oacc[jo][3] * inv1);
    }
}

// ---------------- launch ----------------
extern "C" void kernel_launch(void* const* d_in, const int* in_sizes, int n_in,
                              void* d_out, int out_size)
{
    (void)in_sizes; (void)n_in; (void)out_size;
    const float* x  = (const float*)d_in[0];
    const float* Wq = (const float*)d_in[1];
    const float* Wk = (const float*)d_in[2];
    const float* Wv = (const float*)d_in[3];
    const float* Wo = (const float*)d_in[4];
    float* out = (float*)d_out;

    void *lmp, *xh, *xl, *qh, *ql, *kh, *kl, *vh, *vl, *ah, *al;
    void *wch, *wcl, *woh, *wol;
    cudaGetSymbolAddress(&lmp, g_lm);
    cudaGetSymbolAddress(&xh, g_xh);   cudaGetSymbolAddress(&xl, g_xl);
    cudaGetSymbolAddress(&qh, g_qh);   cudaGetSymbolAddress(&ql, g_ql);
    cudaGetSymbolAddress(&kh, g_kh);   cudaGetSymbolAddress(&kl, g_kl);
    cudaGetSymbolAddress(&vh, g_vh);   cudaGetSymbolAddress(&vl, g_vl);
    cudaGetSymbolAddress(&ah, g_ah);   cudaGetSymbolAddress(&al, g_al);
    cudaGetSymbolAddress(&wch, g_wch); cudaGetSymbolAddress(&wcl, g_wcl);
    cudaGetSymbolAddress(&woh, g_woh); cudaGetSymbolAddress(&wol, g_wol);

    static cudaStream_t s_side = nullptr;
    static cudaEvent_t  e_fork = nullptr, e_xsp = nullptr, e_join = nullptr;
    if (s_side == nullptr) {
        cudaStreamCreateWithFlags(&s_side, cudaStreamNonBlocking);
        cudaEventCreateWithFlags(&e_fork, cudaEventDisableTiming);
        cudaEventCreateWithFlags(&e_xsp,  cudaEventDisableTiming);
        cudaEventCreateWithFlags(&e_join, cudaEventDisableTiming);
    }

    cudaFuncSetAttribute((const void*)gemm_kernel<0, 48>, cudaFuncAttributeMaxDynamicSharedMemorySize, GEMM_SMEM_BYTES);
    cudaFuncSetAttribute((const void*)gemm_kernel<1, 96>, cudaFuncAttributeMaxDynamicSharedMemorySize, GEMM_SMEM_BYTES);
    cudaFuncSetAttribute((const void*)attn_mma_kernel,    cudaFuncAttributeMaxDynamicSharedMemorySize, ATT_SMEM);

    // ---- fork: xsplit first (QKV dependency), then Wo prep + TLS chain, on side ----
    cudaEventRecord(e_fork, 0);
    cudaStreamWaitEvent(s_side, e_fork, 0);

    xsplit_kernel<<<(MTOT * HIDN) / 1024, 256, 0, s_side>>>(x, (__nv_bfloat16*)xh, (__nv_bfloat16*)xl);
    cudaEventRecord(e_xsp, s_side);
    wsplit_wo_kernel<<<dim3(64, KDIM / 32), dim3(32, 8), 0, s_side>>>(
        Wo, (__nv_bfloat16*)woh, (__nv_bfloat16*)wol, out);
    meanp_kernel      <<<dim3(HIDN / 256, BB, 8), 256, 0, s_side>>>(x);
    meanf_mnorm_kernel<<<BB, 256, 0, s_side>>>();
    score_kernel      <<<dim3(SS, BB), 256, 0, s_side>>>(x);
    topk_kernel       <<<BB, 1024, 0, s_side>>>();
    cudaEventRecord(e_join, s_side);

    // ---- main stream: QKV weight prep (concurrent with xsplit/TLS) ----
    wsplit_qkv_kernel<<<dim3(64, KDIM / 32, 3), dim3(32, 8)>>>(
        Wq, Wk, Wv, (__nv_bfloat16*)wch, (__nv_bfloat16*)wcl);

    // ---- QKV projection (needs xsplit) ----
    cudaStreamWaitEvent(0, e_xsp, 0);
    gemm_kernel<1, 96><<<dim3(NQKV / 128, MTOT / 128), 256, GEMM_SMEM_BYTES>>>(
        (const __nv_bfloat16*)xh, (const __nv_bfloat16*)xl,
        (__nv_bfloat16*)wch, (__nv_bfloat16*)wcl,
        nullptr,
        (__nv_bfloat16*)qh, (__nv_bfloat16*)ql,
        (__nv_bfloat16*)kh, (__nv_bfloat16*)kl,
        (__nv_bfloat16*)vh, (__nv_bfloat16*)vl);

    // ---- join: attention needs the landmark mask (and out is zeroed by now) ----
    cudaStreamWaitEvent(0, e_join, 0);

    attn_mma_kernel<<<dim3(BB * NKVH, SS / 64), 256, ATT_SMEM>>>(
        (const __nv_bfloat16*)qh, (const __nv_bfloat16*)ql,
        (const __nv_bfloat16*)kh, (const __nv_bfloat16*)kl,
        (const __nv_bfloat16*)vh, (const __nv_bfloat16*)vl,
        (const int*)lmp, (__nv_bfloat16*)ah, (__nv_bfloat16*)al);

    // ---- output projection: split-K2, deterministic vector red.add ----
    gemm_kernel<0, 48><<<dim3(HIDN / 128, MTOT / 128, 2), 256, GEMM_SMEM_BYTES>>>(
        (const __nv_bfloat16*)ah, (const __nv_bfloat16*)al,
        (const __nv_bfloat16*)woh, (const __nv_bfloat16*)wol,
        out, nullptr, nullptr, nullptr, nullptr, nullptr, nullptr);
}

// round 15
// speedup vs baseline: 1.0615x; 1.0029x over previous
#include <cuda_runtime.h>
#include <cuda_bf16.h>
#include <math.h>
#include <stdint.h>

// ---------------- problem constants ----------------
#define BB   2
#define SS   2048
#define HIDN 2048
#define NH   16
#define NKVH 8
#define DH   128
#define KVD  1024
#define WIN  128
#define TOPK 675
#define MTOT (BB * SS)
#define KDIM 2048
#define NQKV 4096

// ---------------- scratch ----------------
__device__ double g_meanp[8 * BB * HIDN];
__device__ float  g_mean[BB * HIDN];
__device__ double g_mnorm[BB];
__device__ float  g_score[BB * SS];
__device__ int    g_lm[BB * SS];

__device__ __nv_bfloat16 g_xh[MTOT * HIDN], g_xl[MTOT * HIDN];
__device__ __nv_bfloat16 g_qh[MTOT * HIDN], g_ql[MTOT * HIDN];
__device__ __nv_bfloat16 g_kh[MTOT * KVD],  g_kl[MTOT * KVD];
__device__ __nv_bfloat16 g_vh[MTOT * KVD],  g_vl[MTOT * KVD];
__device__ __nv_bfloat16 g_ah[MTOT * HIDN], g_al[MTOT * HIDN];
__device__ __nv_bfloat16 g_wch[NQKV * KDIM], g_wcl[NQKV * KDIM];
__device__ __nv_bfloat16 g_woh[HIDN * KDIM], g_wol[HIDN * KDIM];

// ---------------- PTX helpers ----------------
__device__ __forceinline__ uint32_t s2u(const void* p) {
    uint32_t a;
    asm("{ .reg .u64 t; cvta.to.shared.u64 t, %1; cvt.u32.u64 %0, t; }" : "=r"(a) : "l"(p));
    return a;
}
#define CP16(saddr, gptr) \
    asm volatile("cp.async.cg.shared.global [%0], [%1], 16;" :: "r"(saddr), "l"(gptr))
#define CP_COMMIT() asm volatile("cp.async.commit_group;" ::: "memory")
#define CP_WAIT(n)  asm volatile("cp.async.wait_group %0;" :: "n"(n) : "memory")

#define LDSM4(r0, r1, r2, r3, addr) \
    asm volatile("ldmatrix.sync.aligned.m8n8.x4.shared.b16 {%0,%1,%2,%3}, [%4];" \
                 : "=r"(r0), "=r"(r1), "=r"(r2), "=r"(r3) : "r"(addr))
#define LDSM4T(r0, r1, r2, r3, addr) \
    asm volatile("ldmatrix.sync.aligned.m8n8.x4.trans.shared.b16 {%0,%1,%2,%3}, [%4];" \
                 : "=r"(r0), "=r"(r1), "=r"(r2), "=r"(r3) : "r"(addr))

#define MMA16816(D, a0, a1, a2, a3, b0, b1) \
    asm volatile("mma.sync.aligned.m16n8k16.row.col.f32.bf16.bf16.f32 " \
                 "{%0,%1,%2,%3}, {%4,%5,%6,%7}, {%8,%9}, {%0,%1,%2,%3};" \
                 : "+f"((D)[0]), "+f"((D)[1]), "+f"((D)[2]), "+f"((D)[3]) \
                 : "r"(a0), "r"(a1), "r"(a2), "r"(a3), "r"(b0), "r"(b1))

#define REDV2(ptr, v0, v1) \
    asm volatile("red.global.add.v2.f32 [%0], {%1, %2};" \
                 :: "l"(ptr), "f"(v0), "f"(v1) : "memory")

__device__ __forceinline__ float ex2f(float x) {
    float r;
    asm("ex2.approx.f32 %0, %1;" : "=f"(r) : "f"(x));
    return r;
}

__device__ __forceinline__ uint32_t pack_bf16(float lo, float hi) {
    uint32_t r;
    asm("cvt.rn.bf16x2.f32 %0, %1, %2;" : "=r"(r) : "f"(hi), "f"(lo));
    return r;
}
__device__ __forceinline__ void store_split2(__nv_bfloat16* Hp, __nv_bfloat16* Lp,
                                             float v0, float v1) {
    __nv_bfloat16 h0 = __float2bfloat16(v0), h1 = __float2bfloat16(v1);
    __nv_bfloat16 l0 = __float2bfloat16(v0 - __bfloat162float(h0));
    __nv_bfloat16 l1 = __float2bfloat16(v1 - __bfloat162float(h1));
    *(__nv_bfloat162*)Hp = __halves2bfloat162(h0, h1);
    *(__nv_bfloat162*)Lp = __halves2bfloat162(l0, l1);
}

// ---------------- mean stage 1 ----------------
__global__ void meanp_kernel(const float* __restrict__ x) {
    int f = blockIdx.x * 256 + threadIdx.x;
    int b = blockIdx.y, ch = blockIdx.z;
    const float* p = x + ((size_t)b * SS + (size_t)ch * 256) * HIDN + f;
    double a0 = 0, a1 = 0;
    for (int s = 0; s < 256; s += 2) {
        a0 += (double)p[(size_t)s * HIDN];
        a1 += (double)p[(size_t)(s + 1) * HIDN];
    }
    g_meanp[((size_t)ch * BB + b) * HIDN + f] = a0 + a1;
}

// ---------------- mean stage 2 fused with ||mean|| ----------------
__global__ void meanf_mnorm_kernel() {
    int b = blockIdx.x, tid = threadIdx.x;
    __shared__ double red[8];
    double acc = 0;
    for (int f = tid; f < HIDN; f += 256) {
        double t = 0;
        for (int ch = 0; ch < 8; ch++) t += g_meanp[((size_t)ch * BB + b) * HIDN + f];
        float m = (float)(t / (double)SS);
        g_mean[b * HIDN + f] = m;
        acc += (double)m * (double)m;
    }
    for (int off = 16; off > 0; off >>= 1)
        acc += __shfl_down_sync(0xffffffffu, acc, off);
    if ((tid & 31) == 0) red[tid >> 5] = acc;
    __syncthreads();
    if (tid == 0) {
        double t = 0;
        for (int w = 0; w < 8; w++) t += red[w];
        g_mnorm[b] = sqrt(t);
    }
}

// ---------------- score ----------------
__global__ void score_kernel(const float* __restrict__ x) {
    int row = blockIdx.x, b = blockIdx.y, tid = threadIdx.x;
    __shared__ double redn[8], redd[8];
    size_t roff = ((size_t)b * SS + row) * HIDN;
    const float* xr = x + roff;
    const float* mr = g_mean + b * HIDN;
    double n2 = 0, dt = 0;
    for (int c = tid; c < HIDN; c += 256) {
        float xv = xr[c];
        n2 += (double)xv * (double)xv;
        dt += (double)xv * (double)mr[c];
    }
    for (int off = 16; off > 0; off >>= 1) {
        n2 += __shfl_down_sync(0xffffffffu, n2, off);
        dt += __shfl_down_sync(0xffffffffu, dt, off);
    }
    if ((tid & 31) == 0) { redn[tid >> 5] = n2; redd[tid >> 5] = dt; }
    __syncthreads();
    if (tid == 0) {
        double tn = 0, td = 0;
        for (int w = 0; w < 8; w++) { tn += redn[w]; td += redd[w]; }
        double nrm = sqrt(tn);
        double div = -td / (nrm * g_mnorm[b] + 1e-6);
        g_score[b * SS + row] = (float)(0.7 * nrm + 0.3 * div);
    }
}

// ---------------- exact top-k (bitonic) + dilation ----------------
__global__ void topk_kernel() {
    int b = blockIdx.x, tid = threadIdx.x;
    __shared__ unsigned long long sd[SS];
    __shared__ unsigned char l0[SS], l1[SS];
    for (int i = tid; i < SS; i += 1024) {
        unsigned fb = __float_as_uint(g_score[b * SS + i]);
        unsigned key = (fb & 0x80000000u) ? ~fb : (fb | 0x80000000u);
        sd[i] = ((unsigned long long)key << 32) | (0xFFFFFFFFu - (unsigned)i);
    }
    __syncthreads();
    for (int k2 = 2; k2 <= SS; k2 <<= 1) {
        for (int j = k2 >> 1; j > 0; j >>= 1) {
            for (int i = tid; i < SS; i += 1024) {
                int ixj = i ^ j;
                if (ixj > i) {
                    bool asc = ((i & k2) == 0);
                    unsigned long long a = sd[i], c = sd[ixj];
                    if ((a > c) == asc) { sd[i] = c; sd[ixj] = a; }
                }
            }
            __syncthreads();
        }
    }
    unsigned long long kth = sd[SS - TOPK];
    __syncthreads();
    for (int i = tid; i < SS; i += 1024) {
        unsigned fb = __float_as_uint(g_score[b * SS + i]);
        unsigned key = (fb & 0x80000000u) ? ~fb : (fb | 0x80000000u);
        unsigned long long comp = ((unsigned long long)key << 32) | (0xFFFFFFFFu - (unsigned)i);
        l0[i] = (comp >= kth) ? 1 : 0;
    }
    __syncthreads();
    for (int i = tid; i < SS; i += 1024) {
        unsigned char v = l0[i];
        if (i > 0)      v |= l0[i - 1];
        if (i < SS - 1) v |= l0[i + 1];
        l1[i] = v;
    }
    __syncthreads();
    for (int i = tid; i < SS; i += 1024) {
        unsigned char v = l1[i];
        if (i > 0)      v |= l1[i - 1];
        if (i < SS - 1) v |= l1[i + 1];
        g_lm[b * SS + i] = (int)v;
    }
}

// ---------------- split fp32 -> (bf16 hi, bf16 lo) ----------------
__global__ void xsplit_kernel(const float* __restrict__ X,
                              __nv_bfloat16* __restrict__ Xh,
                              __nv_bfloat16* __restrict__ Xl) {
    int i = (blockIdx.x * 256 + threadIdx.x) * 4;
#pragma unroll
    for (int j = 0; j < 4; j++) {
        float v = X[i + j];
        __nv_bfloat16 h = __float2bfloat16(v);
        Xh[i + j] = h;
        Xl[i + j] = __float2bfloat16(v - __bfloat162float(h));
    }
}

// ---------------- transpose+split: QKV weights (main stream, z in 0..2) --------
__global__ void wsplit_qkv_kernel(const float* __restrict__ W0, const float* __restrict__ W1,
                                  const float* __restrict__ W2,
                                  __nv_bfloat16* __restrict__ wch, __nv_bfloat16* __restrict__ wcl)
{
    __shared__ float t[32][33];
    int z = blockIdx.z;
    const float* W; __nv_bfloat16 *Th, *Tl; int N;
    if (z == 0)      { W = W0; Th = wch;                       Tl = wcl;                       N = 2048; }
    else if (z == 1) { W = W1; Th = wch + (size_t)2048 * KDIM; Tl = wcl + (size_t)2048 * KDIM; N = 1024; }
    else             { W = W2; Th = wch + (size_t)3072 * KDIM; Tl = wcl + (size_t)3072 * KDIM; N = 1024; }
    int n0 = blockIdx.x * 32, k0 = blockIdx.y * 32;
    if (n0 >= N) return;
    int tx = threadIdx.x, ty = threadIdx.y;
#pragma unroll
    for (int i = 0; i < 32; i += 8)
        t[ty + i][tx] = W[(size_t)(k0 + ty + i) * N + n0 + tx];
    __syncthreads();
#pragma unroll
    for (int i = 0; i < 32; i += 8) {
        float v = t[tx][ty + i];
        __nv_bfloat16 h = __float2bfloat16(v);
        __nv_bfloat16 l = __float2bfloat16(v - __bfloat162float(h));
        size_t o = (size_t)(n0 + ty + i) * KDIM + k0 + tx;
        Th[o] = h;
        Tl[o] = l;
    }
}

// ---------------- transpose+split: Wo + zero out (side stream) ------------------
// zero coverage: grid 64x64, 256 thr, 8 floats/thr = 8,388,608 = MTOT*HIDN exactly.
__global__ void wsplit_wo_kernel(const float* __restrict__ W3,
                                 __nv_bfloat16* __restrict__ woh, __nv_bfloat16* __restrict__ wol,
                                 float* __restrict__ out_zero)
{
    __shared__ float t[32][33];
    int n0 = blockIdx.x * 32, k0 = blockIdx.y * 32;
    int tid1 = threadIdx.y * 32 + threadIdx.x;
    {
        size_t id = (((size_t)blockIdx.y * 64 + blockIdx.x) * 256 + tid1) * 8;
        float4 zz = make_float4(0.f, 0.f, 0.f, 0.f);
        *(float4*)(out_zero + id)     = zz;
        *(float4*)(out_zero + id + 4) = zz;
    }
    int tx = threadIdx.x, ty = threadIdx.y;
#pragma unroll
    for (int i = 0; i < 32; i += 8)
        t[ty + i][tx] = W3[(size_t)(k0 + ty + i) * HIDN + n0 + tx];
    __syncthreads();
#pragma unroll
    for (int i = 0; i < 32; i += 8) {
        float v = t[tx][ty + i];
        __nv_bfloat16 h = __float2bfloat16(v);
        __nv_bfloat16 l = __float2bfloat16(v - __bfloat162float(h));
        size_t o = (size_t)(n0 + ty + i) * KDIM + k0 + tx;
        woh[o] = h;
        wol[o] = l;
    }
}

// ---------------- mma.sync split GEMM (128x128, 3-stage) -----------
#define GBK 64
#define TILEB 16384u
#define BUFB  32768u
#define GEMM_SMEM_BYTES (3 * 32768 + 1024)

template<int NST>
__device__ __forceinline__ void load_tiles_async(
    int tid, int s, int m0, int n0, int koff,
    const __nv_bfloat16* __restrict__ Ah, const __nv_bfloat16* __restrict__ Al,
    const __nv_bfloat16* __restrict__ Bh, const __nv_bfloat16* __restrict__ Bl,
    uint32_t bufA)
{
    constexpr int SEGL = NST / 3;
    int seg = s / SEGL;
    int kk  = (s % SEGL) * GBK + koff;
    const __nv_bfloat16* Ap = (seg == 1) ? Al : Ah;
    const __nv_bfloat16* Bp = (seg == 2) ? Bl : Bh;
    uint32_t bufB = bufA + TILEB;
#pragma unroll
    for (int j = 0; j < 4; j++) {
        int id = tid + j * 256;
        int row = id >> 3, c = id & 7;
        uint32_t sw = (uint32_t)((row >> 3) * 1024 + (row & 7) * 128 + ((c ^ (row & 7)) << 4));
        CP16(bufA + sw, (const void*)(Ap + (size_t)(m0 + row) * KDIM + kk + c * 8));
        CP16(bufB + sw, (const void*)(Bp + (size_t)(n0 + row) * KDIM + kk + c * 8));
    }
}

template<int MODE, int NST>
__global__ void __launch_bounds__(256) gemm_kernel(
    const __nv_bfloat16* __restrict__ Ah, const __nv_bfloat16* __restrict__ Al,
    const __nv_bfloat16* __restrict__ Bh, const __nv_bfloat16* __restrict__ Bl,
    float* __restrict__ Cf,
    __nv_bfloat16* __restrict__ qh, __nv_bfloat16* __restrict__ ql,
    __nv_bfloat16* __restrict__ kh, __nv_bfloat16* __restrict__ kl,
    __nv_bfloat16* __restrict__ vh, __nv_bfloat16* __restrict__ vl)
{
    extern __shared__ char dsm[];
    uint32_t tbase = (s2u(dsm) + 1023u) & ~1023u;

    int tid = threadIdx.x, lane = tid & 31, wid = tid >> 5;
    int wm = wid >> 2, wn = wid & 3;
    int m0 = blockIdx.y * 128, n0 = blockIdx.x * 128;
    int koff = (int)blockIdx.z * ((NST / 3) * GBK);

    int aR = lane & 15, aC = lane >> 4;
    int bR = ((lane >> 4) << 3) + (lane & 7);
    int bC = (lane >> 3) & 1;

    uint32_t aOff[4]; int aSw[4];
#pragma unroll
    for (int f = 0; f < 4; f++) {
        int r = wm * 64 + f * 16 + aR;
        aOff[f] = (uint32_t)((r >> 3) * 1024 + (r & 7) * 128);
        aSw[f]  = r & 7;
    }
    uint32_t bOff[2]; int bSw[2];
#pragma unroll
    for (int g = 0; g < 2; g++) {
        int r = wn * 32 + g * 16 + bR;
        bOff[g] = (uint32_t)((r >> 3) * 1024 + (r & 7) * 128);
        bSw[g]  = r & 7;
    }

    float acc[4][4][4];
#pragma unroll
    for (int f = 0; f < 4; f++)
#pragma unroll
        for (int n8 = 0; n8 < 4; n8++)
#pragma unroll
            for (int e = 0; e < 4; e++) acc[f][n8][e] = 0.0f;

    load_tiles_async<NST>(tid, 0, m0, n0, koff, Ah, Al, Bh, Bl, tbase);
    CP_COMMIT();
    load_tiles_async<NST>(tid, 1, m0, n0, koff, Ah, Al, Bh, Bl, tbase + BUFB);
    CP_COMMIT();

    int bidx = 0, pre = 2;
    for (int s = 0; s < NST; s++) {
        if (s == NST - 1) { CP_WAIT(0); } else { CP_WAIT(1); }
        __syncthreads();
        if (s + 2 < NST) {
            load_tiles_async<NST>(tid, s + 2, m0, n0, koff, Ah, Al, Bh, Bl,
                                  tbase + (uint32_t)pre * BUFB);
            CP_COMMIT();
        }

        uint32_t bufA = tbase + (uint32_t)bidx * BUFB;
        uint32_t bufB = bufA + TILEB;
#pragma unroll
        for (int k16 = 0; k16 < 4; k16++) {
            int ca = k16 * 2 + aC, cb = k16 * 2 + bC;
            uint32_t a[4][4], b[2][4];
#pragma unroll
            for (int f = 0; f < 4; f++)
                LDSM4(a[f][0], a[f][1], a[f][2], a[f][3],
                      bufA + aOff[f] + (uint32_t)((ca ^ aSw[f]) << 4));
#pragma unroll
            for (int g = 0; g < 2; g++)
                LDSM4(b[g][0], b[g][1], b[g][2], b[g][3],
                      bufB + bOff[g] + (uint32_t)((cb ^ bSw[g]) << 4));
#pragma unroll
            for (int f = 0; f < 4; f++)
#pragma unroll
                for (int n8 = 0; n8 < 4; n8++) {
                    int g = n8 >> 1, p = (n8 & 1) * 2;
                    MMA16816(acc[f][n8], a[f][0], a[f][1], a[f][2], a[f][3],
                             b[g][p], b[g][p + 1]);
                }
        }
        if (++bidx == 3) bidx = 0;
        if (++pre == 3) pre = 0;
    }

    int row0 = m0 + wm * 64 + (lane >> 2);
    int col0 = wn * 32 + (lane & 3) * 2;
    if (MODE == 0) {
#pragma unroll
        for (int f = 0; f < 4; f++)
#pragma unroll
            for (int n8 = 0; n8 < 4; n8++) {
                int r = row0 + f * 16, c = n0 + col0 + n8 * 8;
                REDV2(Cf + (size_t)r * HIDN + c,       acc[f][n8][0], acc[f][n8][1]);
                REDV2(Cf + (size_t)(r + 8) * HIDN + c, acc[f][n8][2], acc[f][n8][3]);
            }
    } else {
        __nv_bfloat16 *Hp, *Lp; int Nout, cb;
        if (n0 < 2048)      { Hp = qh; Lp = ql; Nout = HIDN; cb = n0 + col0; }
        else if (n0 < 3072) { Hp = kh; Lp = kl; Nout = KVD;  cb = n0 - 2048 + col0; }
        else                { Hp = vh; Lp = vl; Nout = KVD;  cb = n0 - 3072 + col0; }
#pragma unroll
        for (int f = 0; f < 4; f++)
#pragma unroll
            for (int n8 = 0; n8 < 4; n8++) {
                int r = row0 + f * 16, c = cb + n8 * 8;
                store_split2(Hp + (size_t)r * Nout + c, Lp + (size_t)r * Nout + c,
                             acc[f][n8][0], acc[f][n8][1]);
                store_split2(Hp + (size_t)(r + 8) * Nout + c, Lp + (size_t)(r + 8) * Nout + c,
                             acc[f][n8][2], acc[f][n8][3]);
            }
    }
}

// ---------------- split-bf16 mma flash attention, GQA head-paired, LPT order ----
#define SM_QH 0u
#define SM_QL 32768u
#define SM_KV 65536u
#define SM_LM 196608u
#define ATT_SMEM (196608 + 512 + 1024)
#define NEGINF __int_as_float(0xff800000)

__device__ __forceinline__ void att_load_kv(
    int tid, uint32_t base, int bsel, int k0,
    const __nv_bfloat16* __restrict__ khb, const __nv_bfloat16* __restrict__ klb,
    const __nv_bfloat16* __restrict__ vhb, const __nv_bfloat16* __restrict__ vlb,
    const int* __restrict__ lmb)
{
    uint32_t kb = base + SM_KV + (uint32_t)bsel * 65536u;
#pragma unroll
    for (int i = 0; i < 4; i++) {
        int id = tid + i * 256;
        int r = id >> 4, c16 = id & 15, sub = c16 >> 3, c = c16 & 7;
        uint32_t sw = (uint32_t)(sub * 8192 + (r >> 3) * 1024 + (r & 7) * 128 + ((c ^ (r & 7)) << 4));
        size_t so = (size_t)(k0 + r) * KVD + sub * 64 + c * 8;
        CP16(kb + sw,          (const void*)(khb + so));
        CP16(kb + 16384u + sw, (const void*)(klb + so));
        CP16(kb + 32768u + sw, (const void*)(vhb + so));
        CP16(kb + 49152u + sw, (const void*)(vlb + so));
    }
    if (tid < 16)
        CP16(base + SM_LM + (uint32_t)bsel * 256u + (uint32_t)tid * 16u,
             (const void*)(lmb + k0 + tid * 4));
}

__global__ void __launch_bounds__(256) attn_mma_kernel(
    const __nv_bfloat16* __restrict__ qh_g, const __nv_bfloat16* __restrict__ ql_g,
    const __nv_bfloat16* __restrict__ kh_g, const __nv_bfloat16* __restrict__ kl_g,
    const __nv_bfloat16* __restrict__ vh_g, const __nv_bfloat16* __restrict__ vl_g,
    const int* __restrict__ lm,
    __nv_bfloat16* __restrict__ ah_g, __nv_bfloat16* __restrict__ al_g)
{
    extern __shared__ char dsm[];
    uint32_t base = (s2u(dsm) + 1023u) & ~1023u;
    uint32_t pad  = base - s2u(dsm);

    int tid = threadIdx.x, lane = tid & 31, wid = tid >> 5;
    int bh = blockIdx.x;
    int qt = (int)gridDim.y - 1 - (int)blockIdx.y;
    int b = bh >> 3, kvh = bh & 7;
    int q0 = qt * 64;

    const __nv_bfloat16* khb = kh_g + ((size_t)b * SS) * KVD + kvh * DH;
    const __nv_bfloat16* klb = kl_g + ((size_t)b * SS) * KVD + kvh * DH;
    const __nv_bfloat16* vhb = vh_g + ((size_t)b * SS) * KVD + kvh * DH;
    const __nv_bfloat16* vlb = vl_g + ((size_t)b * SS) * KVD + kvh * DH;
    const int* lmb = lm + b * SS;

#pragma unroll
    for (int i = 0; i < 8; i++) {
        int id = tid + i * 256;
        int r = id >> 4, c16 = id & 15, sub = c16 >> 3, c = c16 & 7;
        uint32_t sw = (uint32_t)(sub * 16384 + (r >> 3) * 1024 + (r & 7) * 128 + ((c ^ (r & 7)) << 4));
        size_t so = ((size_t)(b * SS + q0 + (r & 63))) * HIDN
                  + (size_t)(kvh * 2 + (r >> 6)) * DH + sub * 64 + c * 8;
        CP16(base + SM_QH + sw, (const void*)(qh_g + so));
        CP16(base + SM_QL + sw, (const void*)(ql_g + so));
    }
    CP_COMMIT();
    att_load_kv(tid, base, 0, 0, khb, klb, vhb, vlb, lmb);
    CP_COMMIT();

    float m0r = NEGINF, m1r = NEGINF, l0r = 0.0f, l1r = 0.0f;
    float oacc[16][4];
#pragma unroll
    for (int jo = 0; jo < 16; jo++)
#pragma unroll
        for (int e = 0; e < 4; e++) oacc[jo][e] = 0.0f;

    const float scale = 0.08838834764831845f * 1.4426950408889634f;  // log2 domain
    int strip = wid & 3;
    int qg0 = q0 + strip * 16 + (lane >> 2);
    int qg1 = qg0 + 8;
    int qmaxw = q0 + strip * 16 + 15;

    int aR = wid * 16 + (lane & 15);
    uint32_t aOff = (uint32_t)((aR >> 3) * 1024 + (aR & 7) * 128);
    int aSw = aR & 7;
    int bRr = ((lane >> 4) << 3) + (lane & 7);
    int rV0 = (lane & 7) + ((lane >> 3) & 1) * 8;

    CP_WAIT(1);
    __syncthreads();
    uint32_t qfh[8][4], qfl[8][4];
#pragma unroll
    for (int k16 = 0; k16 < 8; k16++) {
        int sub = k16 >> 2;
        int ca = (k16 & 3) * 2 + (lane >> 4);
        uint32_t aaddr = (uint32_t)(sub * 16384) + aOff + (uint32_t)((ca ^ aSw) << 4);
        LDSM4(qfh[k16][0], qfh[k16][1], qfh[k16][2], qfh[k16][3], base + SM_QH + aaddr);
        LDSM4(qfl[k16][0], qfl[k16][1], qfl[k16][2], qfl[k16][3], base + SM_QL + aaddr);
    }

    int nkt = qt + 1;
    for (int kt = 0; kt < nkt; kt++) {
        int k0 = kt * 64, bsel = kt & 1;
        CP_WAIT(0);
        __syncthreads();
        if (kt + 1 < nkt) {
            att_load_kv(tid, base, bsel ^ 1, (kt + 1) * 64, khb, klb, vhb, vlb, lmb);
            CP_COMMIT();
        }

        uint32_t kvb = base + SM_KV + (uint32_t)bsel * 65536u;
        const int* lms = (const int*)(dsm + pad + SM_LM + bsel * 256);
        int kmax = qmaxw - k0;
        int jmax = min(7, kmax >> 3);
        int gmax = jmax >> 1;

        float sacc[8][4];
#pragma unroll
        for (int j = 0; j < 8; j++)
#pragma unroll
            for (int e = 0; e < 4; e++) sacc[j][e] = 0.0f;

        uint32_t kh_s = kvb, kl_s = kvb + 16384u;
#pragma unroll
        for (int k16 = 0; k16 < 8; k16++) {
            int sub = k16 >> 2;
            int cb = (k16 & 3) * 2 + ((lane >> 3) & 1);
            uint32_t bhm[4][4], blm[4][4];
#pragma unroll
            for (int g = 0; g < 4; g++) {
                if (g <= gmax) {
                    int r = g * 16 + bRr;
                    uint32_t off = (uint32_t)(sub * 8192 + (r >> 3) * 1024 + (r & 7) * 128 +
                                              ((cb ^ (r & 7)) << 4));
                    LDSM4(bhm[g][0], bhm[g][1], bhm[g][2], bhm[g][3], kh_s + off);
                    LDSM4(blm[g][0], blm[g][1], blm[g][2], blm[g][3], kl_s + off);
                }
            }
#pragma unroll
            for (int j = 0; j < 8; j++) {
                if (j <= jmax) {
                    int g = j >> 1, p = (j & 1) * 2;
                    MMA16816(sacc[j], qfh[k16][0], qfh[k16][1], qfh[k16][2], qfh[k16][3],
                             bhm[g][p], bhm[g][p + 1]);
                    MMA16816(sacc[j], qfl[k16][0], qfl[k16][1], qfl[k16][2], qfl[k16][3],
                             bhm[g][p], bhm[g][p + 1]);
                    MMA16816(sacc[j], qfh[k16][0], qfh[k16][1], qfh[k16][2], qfh[k16][3],
                             blm[g][p], blm[g][p + 1]);
                }
            }
        }

        float tmax0 = NEGINF, tmax1 = NEGINF;
        int colb = (lane & 3) * 2;
        if (kt == qt - 1) {
            // fully-attendable tile: max(qg-kg) = 127 < WIN and max(kg) < min(qg)
            // => every position passes the mask; skip lms loads + predicates.
#pragma unroll
            for (int j = 0; j < 8; j++) {
                sacc[j][0] *= scale; tmax0 = fmaxf(tmax0, sacc[j][0]);
                sacc[j][1] *= scale; tmax0 = fmaxf(tmax0, sacc[j][1]);
                sacc[j][2] *= scale; tmax1 = fmaxf(tmax1, sacc[j][2]);
                sacc[j][3] *= scale; tmax1 = fmaxf(tmax1, sacc[j][3]);
            }
        } else {
#pragma unroll
            for (int j = 0; j < 8; j++) {
                if (j <= jmax) {
                    int kk0 = j * 8 + colb, kk1 = kk0 + 1;
                    int kg0 = k0 + kk0, kg1 = kg0 + 1;
                    int lmv0 = lms[kk0], lmv1 = lms[kk1];
                    float sv;
                    bool ok;
                    ok = (kg0 <= qg0) && (((qg0 - kg0) < WIN) || lmv0);
                    sv = ok ? sacc[j][0] * scale : NEGINF; sacc[j][0] = sv; tmax0 = fmaxf(tmax0, sv);
                    ok = (kg1 <= qg0) && (((qg0 - kg1) < WIN) || lmv1);
                    sv = ok ? sacc[j][1] * scale : NEGINF; sacc[j][1] = sv; tmax0 = fmaxf(tmax0, sv);
                    ok = (kg0 <= qg1) && (((qg1 - kg0) < WIN) || lmv0);
                    sv = ok ? sacc[j][2] * scale : NEGINF; sacc[j][2] = sv; tmax1 = fmaxf(tmax1, sv);
                    ok = (kg1 <= qg1) && (((qg1 - kg1) < WIN) || lmv1);
                    sv = ok ? sacc[j][3] * scale : NEGINF; sacc[j][3] = sv; tmax1 = fmaxf(tmax1, sv);
                }
            }
        }
        tmax0 = fmaxf(tmax0, __shfl_xor_sync(0xffffffffu, tmax0, 1));
        tmax0 = fmaxf(tmax0, __shfl_xor_sync(0xffffffffu, tmax0, 2));
        tmax1 = fmaxf(tmax1, __shfl_xor_sync(0xffffffffu, tmax1, 1));
        tmax1 = fmaxf(tmax1, __shfl_xor_sync(0xffffffffu, tmax1, 2));

        float mn0 = fmaxf(m0r, tmax0), mn1 = fmaxf(m1r, tmax1);
        float alp0 = (m0r == mn0) ? 1.0f : ex2f(m0r - mn0);
        float alp1 = (m1r == mn1) ? 1.0f : ex2f(m1r - mn1);

        uint32_t ph[8][2], pl[8][2];
        float rs0 = 0.0f, rs1 = 0.0f;
#pragma unroll
        for (int j = 0; j < 8; j++) {
            if (j <= jmax) {
                float p0 = (sacc[j][0] == NEGINF) ? 0.0f : ex2f(sacc[j][0] - mn0);
                float p1 = (sacc[j][1] == NEGINF) ? 0.0f : ex2f(sacc[j][1] - mn0);
                float p2 = (sacc[j][2] == NEGINF) ? 0.0f : ex2f(sacc[j][2] - mn1);
                float p3 = (sacc[j][3] == NEGINF) ? 0.0f : ex2f(sacc[j][3] - mn1);
                rs0 += p0 + p1; rs1 += p2 + p3;
                float h0 = __bfloat162float(__float2bfloat16(p0));
                float h1 = __bfloat162float(__float2bfloat16(p1));
                float h2 = __bfloat162float(__float2bfloat16(p2));
                float h3 = __bfloat162float(__float2bfloat16(p3));
                ph[j][0] = pack_bf16(h0, h1);
                ph[j][1] = pack_bf16(h2, h3);
                pl[j][0] = pack_bf16(p0 - h0, p1 - h1);
                pl[j][1] = pack_bf16(p2 - h2, p3 - h3);
            } else {
                ph[j][0] = ph[j][1] = pl[j][0] = pl[j][1] = 0u;
            }
        }
        rs0 += __shfl_xor_sync(0xffffffffu, rs0, 1);
        rs0 += __shfl_xor_sync(0xffffffffu, rs0, 2);
        rs1 += __shfl_xor_sync(0xffffffffu, rs1, 1);
        rs1 += __shfl_xor_sync(0xffffffffu, rs1, 2);

        l0r = l0r * alp0 + rs0;
        l1r = l1r * alp1 + rs1;
        m0r = mn0; m1r = mn1;
#pragma unroll
        for (int jo = 0; jo < 16; jo++) {
            oacc[jo][0] *= alp0; oacc[jo][1] *= alp0;
            oacc[jo][2] *= alp1; oacc[jo][3] *= alp1;
        }

        uint32_t vh_s = kvb + 32768u, vl_s = kvb + 49152u;
#pragma unroll
        for (int t = 0; t < 4; t++) {
            if (t <= gmax) {
                uint32_t a0h = ph[2 * t][0], a1h = ph[2 * t][1];
                uint32_t a2h = ph[2 * t + 1][0], a3h = ph[2 * t + 1][1];
                uint32_t a0l = pl[2 * t][0], a1l = pl[2 * t][1];
                uint32_t a2l = pl[2 * t + 1][0], a3l = pl[2 * t + 1][1];
                int r = t * 16 + rV0;
                int rsw = r & 7;
                uint32_t rbase = (uint32_t)((r >> 3) * 1024 + rsw * 128);
#pragma unroll
                for (int gg = 0; gg < 8; gg++) {
                    int sub = gg >> 2;
                    int c = (gg & 3) * 2 + (lane >> 4);
                    uint32_t off = (uint32_t)(sub * 8192) + rbase + (uint32_t)((c ^ rsw) << 4);
                    uint32_t v0, v1, v2, v3, w0, w1, w2, w3;
                    LDSM4T(v0, v1, v2, v3, vh_s + off);
                    LDSM4T(w0, w1, w2, w3, vl_s + off);
                    MMA16816(oacc[gg * 2],     a0h, a1h, a2h, a3h, v0, v1);
                    MMA16816(oacc[gg * 2],     a0l, a1l, a2l, a3l, v0, v1);
                    MMA16816(oacc[gg * 2],     a0h, a1h, a2h, a3h, w0, w1);
                    MMA16816(oacc[gg * 2 + 1], a0h, a1h, a2h, a3h, v2, v3);
                    MMA16816(oacc[gg * 2 + 1], a0l, a1l, a2l, a3l, v2, v3);
                    MMA16816(oacc[gg * 2 + 1], a0h, a1h, a2h, a3h, w2, w3);
                }
            }
        }
    }

    float inv0 = 1.0f / l0r, inv1 = 1.0f / l1r;
    int h_w = kvh * 2 + (wid >> 2);
    size_t r0 = (size_t)(b * SS + qg0) * HIDN + (size_t)h_w * DH + (lane & 3) * 2;
    size_t r1 = (size_t)(b * SS + qg1) * HIDN + (size_t)h_w * DH + (lane & 3) * 2;
#pragma unroll
    for (int jo = 0; jo < 16; jo++) {
        int cofs = jo * 8;
        store_split2(ah_g + r0 + cofs, al_g + r0 + cofs, oacc[jo][0] * inv0, oacc[jo][1] * inv0);
        store_split2(ah_g + r1 + cofs, al_g + r1 + cofs, oacc[jo][2] * inv1, oacc[jo][3] * inv1);
    }
}

// ---------------- launch ----------------
extern "C" void kernel_launch(void* const* d_in, const int* in_sizes, int n_in,
                              void* d_out, int out_size)
{
    (void)in_sizes; (void)n_in; (void)out_size;
    const float* x  = (const float*)d_in[0];
    const float* Wq = (const float*)d_in[1];
    const float* Wk = (const float*)d_in[2];
    const float* Wv = (const float*)d_in[3];
    const float* Wo = (const float*)d_in[4];
    float* out = (float*)d_out;

    void *lmp, *xh, *xl, *qh, *ql, *kh, *kl, *vh, *vl, *ah, *al;
    void *wch, *wcl, *woh, *wol;
    cudaGetSymbolAddress(&lmp, g_lm);
    cudaGetSymbolAddress(&xh, g_xh);   cudaGetSymbolAddress(&xl, g_xl);
    cudaGetSymbolAddress(&qh, g_qh);   cudaGetSymbolAddress(&ql, g_ql);
    cudaGetSymbolAddress(&kh, g_kh);   cudaGetSymbolAddress(&kl, g_kl);
    cudaGetSymbolAddress(&vh, g_vh);   cudaGetSymbolAddress(&vl, g_vl);
    cudaGetSymbolAddress(&ah, g_ah);   cudaGetSymbolAddress(&al, g_al);
    cudaGetSymbolAddress(&wch, g_wch); cudaGetSymbolAddress(&wcl, g_wcl);
    cudaGetSymbolAddress(&woh, g_woh); cudaGetSymbolAddress(&wol, g_wol);

    static cudaStream_t s_side = nullptr;
    static cudaEvent_t  e_fork = nullptr, e_xsp = nullptr, e_join = nullptr;
    if (s_side == nullptr) {
        cudaStreamCreateWithFlags(&s_side, cudaStreamNonBlocking);
        cudaEventCreateWithFlags(&e_fork, cudaEventDisableTiming);
        cudaEventCreateWithFlags(&e_xsp,  cudaEventDisableTiming);
        cudaEventCreateWithFlags(&e_join, cudaEventDisableTiming);
    }

    cudaFuncSetAttribute((const void*)gemm_kernel<0, 48>, cudaFuncAttributeMaxDynamicSharedMemorySize, GEMM_SMEM_BYTES);
    cudaFuncSetAttribute((const void*)gemm_kernel<1, 96>, cudaFuncAttributeMaxDynamicSharedMemorySize, GEMM_SMEM_BYTES);
    cudaFuncSetAttribute((const void*)attn_mma_kernel,    cudaFuncAttributeMaxDynamicSharedMemorySize, ATT_SMEM);

    // ---- fork: xsplit first (QKV dependency), then Wo prep + TLS chain, on side ----
    cudaEventRecord(e_fork, 0);
    cudaStreamWaitEvent(s_side, e_fork, 0);

    xsplit_kernel<<<(MTOT * HIDN) / 1024, 256, 0, s_side>>>(x, (__nv_bfloat16*)xh, (__nv_bfloat16*)xl);
    cudaEventRecord(e_xsp, s_side);
    wsplit_wo_kernel<<<dim3(64, KDIM / 32), dim3(32, 8), 0, s_side>>>(
        Wo, (__nv_bfloat16*)woh, (__nv_bfloat16*)wol, out);
    meanp_kernel      <<<dim3(HIDN / 256, BB, 8), 256, 0, s_side>>>(x);
    meanf_mnorm_kernel<<<BB, 256, 0, s_side>>>();
    score_kernel      <<<dim3(SS, BB), 256, 0, s_side>>>(x);
    topk_kernel       <<<BB, 1024, 0, s_side>>>();
    cudaEventRecord(e_join, s_side);

    // ---- main stream: QKV weight prep (concurrent with xsplit/TLS) ----
    wsplit_qkv_kernel<<<dim3(64, KDIM / 32, 3), dim3(32, 8)>>>(
        Wq, Wk, Wv, (__nv_bfloat16*)wch, (__nv_bfloat16*)wcl);

    // ---- QKV projection (needs xsplit) ----
    cudaStreamWaitEvent(0, e_xsp, 0);
    gemm_kernel<1, 96><<<dim3(NQKV / 128, MTOT / 128), 256, GEMM_SMEM_BYTES>>>(
        (const __nv_bfloat16*)xh, (const __nv_bfloat16*)xl,
        (__nv_bfloat16*)wch, (__nv_bfloat16*)wcl,
        nullptr,
        (__nv_bfloat16*)qh, (__nv_bfloat16*)ql,
        (__nv_bfloat16*)kh, (__nv_bfloat16*)kl,
        (__nv_bfloat16*)vh, (__nv_bfloat16*)vl);

    // ---- join: attention needs the landmark mask (and out is zeroed by now) ----
    cudaStreamWaitEvent(0, e_join, 0);

    attn_mma_kernel<<<dim3(BB * NKVH, SS / 64), 256, ATT_SMEM>>>(
        (const __nv_bfloat16*)qh, (const __nv_bfloat16*)ql,
        (const __nv_bfloat16*)kh, (const __nv_bfloat16*)kl,
        (const __nv_bfloat16*)vh, (const __nv_bfloat16*)vl,
        (const int*)lmp, (__nv_bfloat16*)ah, (__nv_bfloat16*)al);

    // ---- output projection: split-K2, deterministic vector red.add ----
    gemm_kernel<0, 48><<<dim3(HIDN / 128, MTOT / 128, 2), 256, GEMM_SMEM_BYTES>>>(
        (const __nv_bfloat16*)ah, (const __nv_bfloat16*)al,
        (const __nv_bfloat16*)woh, (const __nv_bfloat16*)wol,
        out, nullptr, nullptr, nullptr, nullptr, nullptr, nullptr);
}

// round 16
// speedup vs baseline: 1.0812x; 1.0185x over previous
#include <cuda_runtime.h>
#include <cuda_bf16.h>
#include <math.h>
#include <stdint.h>

// ---------------- problem constants ----------------
#define BB   2
#define SS   2048
#define HIDN 2048
#define NH   16
#define NKVH 8
#define DH   128
#define KVD  1024
#define WIN  128
#define TOPK 675
#define MTOT (BB * SS)
#define KDIM 2048
#define NQKV 4096

// ---------------- scratch ----------------
__device__ double g_meanp[8 * BB * HIDN];
__device__ float  g_mean[BB * HIDN];
__device__ double g_mnorm[BB];
__device__ float  g_score[BB * SS];
__device__ int    g_lm[BB * SS];

__device__ __nv_bfloat16 g_xh[MTOT * HIDN], g_xl[MTOT * HIDN];
__device__ __nv_bfloat16 g_qh[MTOT * HIDN], g_ql[MTOT * HIDN];
__device__ __nv_bfloat16 g_kh[MTOT * KVD],  g_kl[MTOT * KVD];
__device__ __nv_bfloat16 g_vh[MTOT * KVD],  g_vl[MTOT * KVD];
__device__ __nv_bfloat16 g_ah[MTOT * HIDN], g_al[MTOT * HIDN];
__device__ __nv_bfloat16 g_wch[NQKV * KDIM], g_wcl[NQKV * KDIM];
__device__ __nv_bfloat16 g_woh[HIDN * KDIM], g_wol[HIDN * KDIM];

// ---------------- PTX helpers ----------------
__device__ __forceinline__ uint32_t s2u(const void* p) {
    uint32_t a;
    asm("{ .reg .u64 t; cvta.to.shared.u64 t, %1; cvt.u32.u64 %0, t; }" : "=r"(a) : "l"(p));
    return a;
}
#define CP16(saddr, gptr) \
    asm volatile("cp.async.cg.shared.global [%0], [%1], 16;" :: "r"(saddr), "l"(gptr))
#define CP_COMMIT() asm volatile("cp.async.commit_group;" ::: "memory")
#define CP_WAIT(n)  asm volatile("cp.async.wait_group %0;" :: "n"(n) : "memory")

#define LDSM4(r0, r1, r2, r3, addr) \
    asm volatile("ldmatrix.sync.aligned.m8n8.x4.shared.b16 {%0,%1,%2,%3}, [%4];" \
                 : "=r"(r0), "=r"(r1), "=r"(r2), "=r"(r3) : "r"(addr))
#define LDSM4T(r0, r1, r2, r3, addr) \
    asm volatile("ldmatrix.sync.aligned.m8n8.x4.trans.shared.b16 {%0,%1,%2,%3}, [%4];" \
                 : "=r"(r0), "=r"(r1), "=r"(r2), "=r"(r3) : "r"(addr))

#define MMA16816(D, a0, a1, a2, a3, b0, b1) \
    asm volatile("mma.sync.aligned.m16n8k16.row.col.f32.bf16.bf16.f32 " \
                 "{%0,%1,%2,%3}, {%4,%5,%6,%7}, {%8,%9}, {%0,%1,%2,%3};" \
                 : "+f"((D)[0]), "+f"((D)[1]), "+f"((D)[2]), "+f"((D)[3]) \
                 : "r"(a0), "r"(a1), "r"(a2), "r"(a3), "r"(b0), "r"(b1))

#define REDV2(ptr, v0, v1) \
    asm volatile("red.global.add.v2.f32 [%0], {%1, %2};" \
                 :: "l"(ptr), "f"(v0), "f"(v1) : "memory")

__device__ __forceinline__ float ex2f(float x) {
    float r;
    asm("ex2.approx.f32 %0, %1;" : "=f"(r) : "f"(x));
    return r;
}

__device__ __forceinline__ uint32_t pack_bf16(float lo, float hi) {
    uint32_t r;
    asm("cvt.rn.bf16x2.f32 %0, %1, %2;" : "=r"(r) : "f"(hi), "f"(lo));
    return r;
}
__device__ __forceinline__ void store_split2(__nv_bfloat16* Hp, __nv_bfloat16* Lp,
                                             float v0, float v1) {
    __nv_bfloat16 h0 = __float2bfloat16(v0), h1 = __float2bfloat16(v1);
    __nv_bfloat16 l0 = __float2bfloat16(v0 - __bfloat162float(h0));
    __nv_bfloat16 l1 = __float2bfloat16(v1 - __bfloat162float(h1));
    *(__nv_bfloat162*)Hp = __halves2bfloat162(h0, h1);
    *(__nv_bfloat162*)Lp = __halves2bfloat162(l0, l1);
}

// ---------------- mean stage 1 ----------------
__global__ void meanp_kernel(const float* __restrict__ x) {
    int f = blockIdx.x * 256 + threadIdx.x;
    int b = blockIdx.y, ch = blockIdx.z;
    const float* p = x + ((size_t)b * SS + (size_t)ch * 256) * HIDN + f;
    double a0 = 0, a1 = 0;
    for (int s = 0; s < 256; s += 2) {
        a0 += (double)p[(size_t)s * HIDN];
        a1 += (double)p[(size_t)(s + 1) * HIDN];
    }
    g_meanp[((size_t)ch * BB + b) * HIDN + f] = a0 + a1;
}

// ---------------- mean stage 2 fused with ||mean|| ----------------
__global__ void meanf_mnorm_kernel() {
    int b = blockIdx.x, tid = threadIdx.x;
    __shared__ double red[8];
    double acc = 0;
    for (int f = tid; f < HIDN; f += 256) {
        double t = 0;
        for (int ch = 0; ch < 8; ch++) t += g_meanp[((size_t)ch * BB + b) * HIDN + f];
        float m = (float)(t / (double)SS);
        g_mean[b * HIDN + f] = m;
        acc += (double)m * (double)m;
    }
    for (int off = 16; off > 0; off >>= 1)
        acc += __shfl_down_sync(0xffffffffu, acc, off);
    if ((tid & 31) == 0) red[tid >> 5] = acc;
    __syncthreads();
    if (tid == 0) {
        double t = 0;
        for (int w = 0; w < 8; w++) t += red[w];
        g_mnorm[b] = sqrt(t);
    }
}

// ---------------- score ----------------
__global__ void score_kernel(const float* __restrict__ x) {
    int row = blockIdx.x, b = blockIdx.y, tid = threadIdx.x;
    __shared__ double redn[8], redd[8];
    size_t roff = ((size_t)b * SS + row) * HIDN;
    const float* xr = x + roff;
    const float* mr = g_mean + b * HIDN;
    double n2 = 0, dt = 0;
    for (int c = tid; c < HIDN; c += 256) {
        float xv = xr[c];
        n2 += (double)xv * (double)xv;
        dt += (double)xv * (double)mr[c];
    }
    for (int off = 16; off > 0; off >>= 1) {
        n2 += __shfl_down_sync(0xffffffffu, n2, off);
        dt += __shfl_down_sync(0xffffffffu, dt, off);
    }
    if ((tid & 31) == 0) { redn[tid >> 5] = n2; redd[tid >> 5] = dt; }
    __syncthreads();
    if (tid == 0) {
        double tn = 0, td = 0;
        for (int w = 0; w < 8; w++) { tn += redn[w]; td += redd[w]; }
        double nrm = sqrt(tn);
        double div = -td / (nrm * g_mnorm[b] + 1e-6);
        g_score[b * SS + row] = (float)(0.7 * nrm + 0.3 * div);
    }
}

// ---------------- exact top-k (bitonic) + dilation ----------------
__global__ void topk_kernel() {
    int b = blockIdx.x, tid = threadIdx.x;
    __shared__ unsigned long long sd[SS];
    __shared__ unsigned char l0[SS], l1[SS];
    for (int i = tid; i < SS; i += 1024) {
        unsigned fb = __float_as_uint(g_score[b * SS + i]);
        unsigned key = (fb & 0x80000000u) ? ~fb : (fb | 0x80000000u);
        sd[i] = ((unsigned long long)key << 32) | (0xFFFFFFFFu - (unsigned)i);
    }
    __syncthreads();
    for (int k2 = 2; k2 <= SS; k2 <<= 1) {
        for (int j = k2 >> 1; j > 0; j >>= 1) {
            for (int i = tid; i < SS; i += 1024) {
                int ixj = i ^ j;
                if (ixj > i) {
                    bool asc = ((i & k2) == 0);
                    unsigned long long a = sd[i], c = sd[ixj];
                    if ((a > c) == asc) { sd[i] = c; sd[ixj] = a; }
                }
            }
            __syncthreads();
        }
    }
    unsigned long long kth = sd[SS - TOPK];
    __syncthreads();
    for (int i = tid; i < SS; i += 1024) {
        unsigned fb = __float_as_uint(g_score[b * SS + i]);
        unsigned key = (fb & 0x80000000u) ? ~fb : (fb | 0x80000000u);
        unsigned long long comp = ((unsigned long long)key << 32) | (0xFFFFFFFFu - (unsigned)i);
        l0[i] = (comp >= kth) ? 1 : 0;
    }
    __syncthreads();
    for (int i = tid; i < SS; i += 1024) {
        unsigned char v = l0[i];
        if (i > 0)      v |= l0[i - 1];
        if (i < SS - 1) v |= l0[i + 1];
        l1[i] = v;
    }
    __syncthreads();
    for (int i = tid; i < SS; i += 1024) {
        unsigned char v = l1[i];
        if (i > 0)      v |= l1[i - 1];
        if (i < SS - 1) v |= l1[i + 1];
        g_lm[b * SS + i] = (int)v;
    }
}

// ---------------- split fp32 -> (bf16 hi, bf16 lo) ----------------
__global__ void xsplit_kernel(const float* __restrict__ X,
                              __nv_bfloat16* __restrict__ Xh,
                              __nv_bfloat16* __restrict__ Xl) {
    int i = (blockIdx.x * 256 + threadIdx.x) * 4;
#pragma unroll
    for (int j = 0; j < 4; j++) {
        float v = X[i + j];
        __nv_bfloat16 h = __float2bfloat16(v);
        Xh[i + j] = h;
        Xl[i + j] = __float2bfloat16(v - __bfloat162float(h));
    }
}

// ---------------- transpose+split: QKV weights (main stream, z in 0..2) --------
__global__ void wsplit_qkv_kernel(const float* __restrict__ W0, const float* __restrict__ W1,
                                  const float* __restrict__ W2,
                                  __nv_bfloat16* __restrict__ wch, __nv_bfloat16* __restrict__ wcl)
{
    __shared__ float t[32][33];
    int z = blockIdx.z;
    const float* W; __nv_bfloat16 *Th, *Tl; int N;
    if (z == 0)      { W = W0; Th = wch;                       Tl = wcl;                       N = 2048; }
    else if (z == 1) { W = W1; Th = wch + (size_t)2048 * KDIM; Tl = wcl + (size_t)2048 * KDIM; N = 1024; }
    else             { W = W2; Th = wch + (size_t)3072 * KDIM; Tl = wcl + (size_t)3072 * KDIM; N = 1024; }
    int n0 = blockIdx.x * 32, k0 = blockIdx.y * 32;
    if (n0 >= N) return;
    int tx = threadIdx.x, ty = threadIdx.y;
#pragma unroll
    for (int i = 0; i < 32; i += 8)
        t[ty + i][tx] = W[(size_t)(k0 + ty + i) * N + n0 + tx];
    __syncthreads();
#pragma unroll
    for (int i = 0; i < 32; i += 8) {
        float v = t[tx][ty + i];
        __nv_bfloat16 h = __float2bfloat16(v);
        __nv_bfloat16 l = __float2bfloat16(v - __bfloat162float(h));
        size_t o = (size_t)(n0 + ty + i) * KDIM + k0 + tx;
        Th[o] = h;
        Tl[o] = l;
    }
}

// ---------------- transpose+split: Wo + zero out (side stream) ------------------
// zero coverage: grid 64x64, 256 thr, 8 floats/thr = 8,388,608 = MTOT*HIDN exactly.
__global__ void wsplit_wo_kernel(const float* __restrict__ W3,
                                 __nv_bfloat16* __restrict__ woh, __nv_bfloat16* __restrict__ wol,
                                 float* __restrict__ out_zero)
{
    __shared__ float t[32][33];
    int n0 = blockIdx.x * 32, k0 = blockIdx.y * 32;
    int tid1 = threadIdx.y * 32 + threadIdx.x;
    {
        size_t id = (((size_t)blockIdx.y * 64 + blockIdx.x) * 256 + tid1) * 8;
        float4 zz = make_float4(0.f, 0.f, 0.f, 0.f);
        *(float4*)(out_zero + id)     = zz;
        *(float4*)(out_zero + id + 4) = zz;
    }
    int tx = threadIdx.x, ty = threadIdx.y;
#pragma unroll
    for (int i = 0; i < 32; i += 8)
        t[ty + i][tx] = W3[(size_t)(k0 + ty + i) * HIDN + n0 + tx];
    __syncthreads();
#pragma unroll
    for (int i = 0; i < 32; i += 8) {
        float v = t[tx][ty + i];
        __nv_bfloat16 h = __float2bfloat16(v);
        __nv_bfloat16 l = __float2bfloat16(v - __bfloat162float(h));
        size_t o = (size_t)(n0 + ty + i) * KDIM + k0 + tx;
        woh[o] = h;
        wol[o] = l;
    }
}

// ---------------- mma.sync split GEMM (128x128, 3-stage) -----------
#define GBK 64
#define TILEB 16384u
#define BUFB  32768u
#define GEMM_SMEM_BYTES (3 * 32768 + 1024)

template<int NST>
__device__ __forceinline__ void load_tiles_async(
    int tid, int s, int m0, int n0, int koff,
    const __nv_bfloat16* __restrict__ Ah, const __nv_bfloat16* __restrict__ Al,
    const __nv_bfloat16* __restrict__ Bh, const __nv_bfloat16* __restrict__ Bl,
    uint32_t bufA)
{
    constexpr int SEGL = NST / 3;
    int seg = s / SEGL;
    int kk  = (s % SEGL) * GBK + koff;
    const __nv_bfloat16* Ap = (seg == 1) ? Al : Ah;
    const __nv_bfloat16* Bp = (seg == 2) ? Bl : Bh;
    uint32_t bufB = bufA + TILEB;
#pragma unroll
    for (int j = 0; j < 4; j++) {
        int id = tid + j * 256;
        int row = id >> 3, c = id & 7;
        uint32_t sw = (uint32_t)((row >> 3) * 1024 + (row & 7) * 128 + ((c ^ (row & 7)) << 4));
        CP16(bufA + sw, (const void*)(Ap + (size_t)(m0 + row) * KDIM + kk + c * 8));
        CP16(bufB + sw, (const void*)(Bp + (size_t)(n0 + row) * KDIM + kk + c * 8));
    }
}

template<int MODE, int NST>
__global__ void __launch_bounds__(256) gemm_kernel(
    const __nv_bfloat16* __restrict__ Ah, const __nv_bfloat16* __restrict__ Al,
    const __nv_bfloat16* __restrict__ Bh, const __nv_bfloat16* __restrict__ Bl,
    float* __restrict__ Cf,
    __nv_bfloat16* __restrict__ qh, __nv_bfloat16* __restrict__ ql,
    __nv_bfloat16* __restrict__ kh, __nv_bfloat16* __restrict__ kl,
    __nv_bfloat16* __restrict__ vh, __nv_bfloat16* __restrict__ vl)
{
    extern __shared__ char dsm[];
    uint32_t tbase = (s2u(dsm) + 1023u) & ~1023u;

    int tid = threadIdx.x, lane = tid & 31, wid = tid >> 5;
    int wm = wid >> 2, wn = wid & 3;
    int m0 = blockIdx.y * 128, n0 = blockIdx.x * 128;
    int koff = (int)blockIdx.z * ((NST / 3) * GBK);

    int aR = lane & 15, aC = lane >> 4;
    int bR = ((lane >> 4) << 3) + (lane & 7);
    int bC = (lane >> 3) & 1;

    uint32_t aOff[4]; int aSw[4];
#pragma unroll
    for (int f = 0; f < 4; f++) {
        int r = wm * 64 + f * 16 + aR;
        aOff[f] = (uint32_t)((r >> 3) * 1024 + (r & 7) * 128);
        aSw[f]  = r & 7;
    }
    uint32_t bOff[2]; int bSw[2];
#pragma unroll
    for (int g = 0; g < 2; g++) {
        int r = wn * 32 + g * 16 + bR;
        bOff[g] = (uint32_t)((r >> 3) * 1024 + (r & 7) * 128);
        bSw[g]  = r & 7;
    }

    float acc[4][4][4];
#pragma unroll
    for (int f = 0; f < 4; f++)
#pragma unroll
        for (int n8 = 0; n8 < 4; n8++)
#pragma unroll
            for (int e = 0; e < 4; e++) acc[f][n8][e] = 0.0f;

    load_tiles_async<NST>(tid, 0, m0, n0, koff, Ah, Al, Bh, Bl, tbase);
    CP_COMMIT();
    load_tiles_async<NST>(tid, 1, m0, n0, koff, Ah, Al, Bh, Bl, tbase + BUFB);
    CP_COMMIT();

    int bidx = 0, pre = 2;
    for (int s = 0; s < NST; s++) {
        if (s == NST - 1) { CP_WAIT(0); } else { CP_WAIT(1); }
        __syncthreads();
        if (s + 2 < NST) {
            load_tiles_async<NST>(tid, s + 2, m0, n0, koff, Ah, Al, Bh, Bl,
                                  tbase + (uint32_t)pre * BUFB);
            CP_COMMIT();
        }

        uint32_t bufA = tbase + (uint32_t)bidx * BUFB;
        uint32_t bufB = bufA + TILEB;
#pragma unroll
        for (int k16 = 0; k16 < 4; k16++) {
            int ca = k16 * 2 + aC, cb = k16 * 2 + bC;
            uint32_t a[4][4], b[2][4];
#pragma unroll
            for (int f = 0; f < 4; f++)
                LDSM4(a[f][0], a[f][1], a[f][2], a[f][3],
                      bufA + aOff[f] + (uint32_t)((ca ^ aSw[f]) << 4));
#pragma unroll
            for (int g = 0; g < 2; g++)
                LDSM4(b[g][0], b[g][1], b[g][2], b[g][3],
                      bufB + bOff[g] + (uint32_t)((cb ^ bSw[g]) << 4));
#pragma unroll
            for (int f = 0; f < 4; f++)
#pragma unroll
                for (int n8 = 0; n8 < 4; n8++) {
                    int g = n8 >> 1, p = (n8 & 1) * 2;
                    MMA16816(acc[f][n8], a[f][0], a[f][1], a[f][2], a[f][3],
                             b[g][p], b[g][p + 1]);
                }
        }
        if (++bidx == 3) bidx = 0;
        if (++pre == 3) pre = 0;
    }

    int row0 = m0 + wm * 64 + (lane >> 2);
    int col0 = wn * 32 + (lane & 3) * 2;
    if (MODE == 0) {
#pragma unroll
        for (int f = 0; f < 4; f++)
#pragma unroll
            for (int n8 = 0; n8 < 4; n8++) {
                int r = row0 + f * 16, c = n0 + col0 + n8 * 8;
                REDV2(Cf + (size_t)r * HIDN + c,       acc[f][n8][0], acc[f][n8][1]);
                REDV2(Cf + (size_t)(r + 8) * HIDN + c, acc[f][n8][2], acc[f][n8][3]);
            }
    } else {
        __nv_bfloat16 *Hp, *Lp; int Nout, cb;
        if (n0 < 2048)      { Hp = qh; Lp = ql; Nout = HIDN; cb = n0 + col0; }
        else if (n0 < 3072) { Hp = kh; Lp = kl; Nout = KVD;  cb = n0 - 2048 + col0; }
        else                { Hp = vh; Lp = vl; Nout = KVD;  cb = n0 - 3072 + col0; }
#pragma unroll
        for (int f = 0; f < 4; f++)
#pragma unroll
            for (int n8 = 0; n8 < 4; n8++) {
                int r = row0 + f * 16, c = cb + n8 * 8;
                store_split2(Hp + (size_t)r * Nout + c, Lp + (size_t)r * Nout + c,
                             acc[f][n8][0], acc[f][n8][1]);
                store_split2(Hp + (size_t)(r + 8) * Nout + c, Lp + (size_t)(r + 8) * Nout + c,
                             acc[f][n8][2], acc[f][n8][3]);
            }
    }
}

// ---------------- split-bf16 mma flash attention, GQA head-paired, LPT order ----
#define SM_QH 0u
#define SM_QL 32768u
#define SM_KV 65536u
#define SM_LM 196608u
#define ATT_SMEM (196608 + 512 + 1024)
#define NEGINF __int_as_float(0xff800000)

__device__ __forceinline__ void att_load_kv(
    int tid, uint32_t base, int bsel, int k0,
    const __nv_bfloat16* __restrict__ khb, const __nv_bfloat16* __restrict__ klb,
    const __nv_bfloat16* __restrict__ vhb, const __nv_bfloat16* __restrict__ vlb,
    const int* __restrict__ lmb)
{
    uint32_t kb = base + SM_KV + (uint32_t)bsel * 65536u;
#pragma unroll
    for (int i = 0; i < 4; i++) {
        int id = tid + i * 256;
        int r = id >> 4, c16 = id & 15, sub = c16 >> 3, c = c16 & 7;
        uint32_t sw = (uint32_t)(sub * 8192 + (r >> 3) * 1024 + (r & 7) * 128 + ((c ^ (r & 7)) << 4));
        size_t so = (size_t)(k0 + r) * KVD + sub * 64 + c * 8;
        CP16(kb + sw,          (const void*)(khb + so));
        CP16(kb + 16384u + sw, (const void*)(klb + so));
        CP16(kb + 32768u + sw, (const void*)(vhb + so));
        CP16(kb + 49152u + sw, (const void*)(vlb + so));
    }
    if (tid < 16)
        CP16(base + SM_LM + (uint32_t)bsel * 256u + (uint32_t)tid * 16u,
             (const void*)(lmb + k0 + tid * 4));
}

__global__ void __launch_bounds__(256) attn_mma_kernel(
    const __nv_bfloat16* __restrict__ qh_g, const __nv_bfloat16* __restrict__ ql_g,
    const __nv_bfloat16* __restrict__ kh_g, const __nv_bfloat16* __restrict__ kl_g,
    const __nv_bfloat16* __restrict__ vh_g, const __nv_bfloat16* __restrict__ vl_g,
    const int* __restrict__ lm,
    __nv_bfloat16* __restrict__ ah_g, __nv_bfloat16* __restrict__ al_g)
{
    extern __shared__ char dsm[];
    uint32_t base = (s2u(dsm) + 1023u) & ~1023u;
    uint32_t pad  = base - s2u(dsm);

    int tid = threadIdx.x, lane = tid & 31, wid = tid >> 5;
    int bh = blockIdx.x;
    int qt = (int)gridDim.y - 1 - (int)blockIdx.y;
    int b = bh >> 3, kvh = bh & 7;
    int q0 = qt * 64;

    const __nv_bfloat16* khb = kh_g + ((size_t)b * SS) * KVD + kvh * DH;
    const __nv_bfloat16* klb = kl_g + ((size_t)b * SS) * KVD + kvh * DH;
    const __nv_bfloat16* vhb = vh_g + ((size_t)b * SS) * KVD + kvh * DH;
    const __nv_bfloat16* vlb = vl_g + ((size_t)b * SS) * KVD + kvh * DH;
    const int* lmb = lm + b * SS;

#pragma unroll
    for (int i = 0; i < 8; i++) {
        int id = tid + i * 256;
        int r = id >> 4, c16 = id & 15, sub = c16 >> 3, c = c16 & 7;
        uint32_t sw = (uint32_t)(sub * 16384 + (r >> 3) * 1024 + (r & 7) * 128 + ((c ^ (r & 7)) << 4));
        size_t so = ((size_t)(b * SS + q0 + (r & 63))) * HIDN
                  + (size_t)(kvh * 2 + (r >> 6)) * DH + sub * 64 + c * 8;
        CP16(base + SM_QH + sw, (const void*)(qh_g + so));
        CP16(base + SM_QL + sw, (const void*)(ql_g + so));
    }
    CP_COMMIT();
    att_load_kv(tid, base, 0, 0, khb, klb, vhb, vlb, lmb);
    CP_COMMIT();

    float m0r = NEGINF, m1r = NEGINF, l0r = 0.0f, l1r = 0.0f;
    float oacc[16][4];
#pragma unroll
    for (int jo = 0; jo < 16; jo++)
#pragma unroll
        for (int e = 0; e < 4; e++) oacc[jo][e] = 0.0f;

    const float scale = 0.08838834764831845f * 1.4426950408889634f;  // log2 domain
    int strip = wid & 3;
    int qg0 = q0 + strip * 16 + (lane >> 2);
    int qg1 = qg0 + 8;
    int qmaxw = q0 + strip * 16 + 15;

    int aR = wid * 16 + (lane & 15);
    uint32_t aOff = (uint32_t)((aR >> 3) * 1024 + (aR & 7) * 128);
    int aSw = aR & 7;
    int bRr = ((lane >> 4) << 3) + (lane & 7);
    int rV0 = (lane & 7) + ((lane >> 3) & 1) * 8;

    CP_WAIT(1);
    __syncthreads();
    uint32_t qfh[8][4], qfl[8][4];
#pragma unroll
    for (int k16 = 0; k16 < 8; k16++) {
        int sub = k16 >> 2;
        int ca = (k16 & 3) * 2 + (lane >> 4);
        uint32_t aaddr = (uint32_t)(sub * 16384) + aOff + (uint32_t)((ca ^ aSw) << 4);
        LDSM4(qfh[k16][0], qfh[k16][1], qfh[k16][2], qfh[k16][3], base + SM_QH + aaddr);
        LDSM4(qfl[k16][0], qfl[k16][1], qfl[k16][2], qfl[k16][3], base + SM_QL + aaddr);
    }

    int nkt = qt + 1;
    for (int kt = 0; kt < nkt; kt++) {
        int k0 = kt * 64, bsel = kt & 1;
        CP_WAIT(0);
        __syncthreads();
        if (kt + 1 < nkt) {
            att_load_kv(tid, base, bsel ^ 1, (kt + 1) * 64, khb, klb, vhb, vlb, lmb);
            CP_COMMIT();
        }

        uint32_t kvb = base + SM_KV + (uint32_t)bsel * 65536u;
        const int* lms = (const int*)(dsm + pad + SM_LM + bsel * 256);
        int kmax = qmaxw - k0;
        int jmax = min(7, kmax >> 3);
        int gmax = jmax >> 1;

        float sacc[8][4];
#pragma unroll
        for (int j = 0; j < 8; j++)
#pragma unroll
            for (int e = 0; e < 4; e++) sacc[j][e] = 0.0f;

        uint32_t kh_s = kvb, kl_s = kvb + 16384u;
#pragma unroll
        for (int k16 = 0; k16 < 8; k16++) {
            int sub = k16 >> 2;
            int cb = (k16 & 3) * 2 + ((lane >> 3) & 1);
            uint32_t bhm[4][4], blm[4][4];
#pragma unroll
            for (int g = 0; g < 4; g++) {
                if (g <= gmax) {
                    int r = g * 16 + bRr;
                    uint32_t off = (uint32_t)(sub * 8192 + (r >> 3) * 1024 + (r & 7) * 128 +
                                              ((cb ^ (r & 7)) << 4));
                    LDSM4(bhm[g][0], bhm[g][1], bhm[g][2], bhm[g][3], kh_s + off);
                    LDSM4(blm[g][0], blm[g][1], blm[g][2], blm[g][3], kl_s + off);
                }
            }
#pragma unroll
            for (int j = 0; j < 8; j++) {
                if (j <= jmax) {
                    int g = j >> 1, p = (j & 1) * 2;
                    MMA16816(sacc[j], qfh[k16][0], qfh[k16][1], qfh[k16][2], qfh[k16][3],
                             bhm[g][p], bhm[g][p + 1]);
                    MMA16816(sacc[j], qfl[k16][0], qfl[k16][1], qfl[k16][2], qfl[k16][3],
                             bhm[g][p], bhm[g][p + 1]);
                    MMA16816(sacc[j], qfh[k16][0], qfh[k16][1], qfh[k16][2], qfh[k16][3],
                             blm[g][p], blm[g][p + 1]);
                }
            }
        }

        // ---- mask taxonomy (all cases provably exact) ----
        // kt <= qt-3: causal true (kg <= qt*64-129 < q0 <= qg), window false
        //             (qg-kg >= 129 >= WIN)        => ok = lm only
        // kt == qt-2: causal true                  => ok = window || lm
        // kt == qt-1: fully attendable             => no mask
        // kt == qt  : causal => qg-kg in [0,63] < WIN (local true) => ok = causal only
        float tmax0 = NEGINF, tmax1 = NEGINF;
        int colb = (lane & 3) * 2;
        if (kt == qt - 1) {
#pragma unroll
            for (int j = 0; j < 8; j++) {
                sacc[j][0] *= scale; tmax0 = fmaxf(tmax0, sacc[j][0]);
                sacc[j][1] *= scale; tmax0 = fmaxf(tmax0, sacc[j][1]);
                sacc[j][2] *= scale; tmax1 = fmaxf(tmax1, sacc[j][2]);
                sacc[j][3] *= scale; tmax1 = fmaxf(tmax1, sacc[j][3]);
            }
        } else if (kt == qt) {
            // diagonal: causal only, no landmark loads
#pragma unroll
            for (int j = 0; j < 8; j++) {
                if (j <= jmax) {
                    int kg0 = k0 + j * 8 + colb, kg1 = kg0 + 1;
                    float sv;
                    sv = (kg0 <= qg0) ? sacc[j][0] * scale : NEGINF; sacc[j][0] = sv; tmax0 = fmaxf(tmax0, sv);
                    sv = (kg1 <= qg0) ? sacc[j][1] * scale : NEGINF; sacc[j][1] = sv; tmax0 = fmaxf(tmax0, sv);
                    sv = (kg0 <= qg1) ? sacc[j][2] * scale : NEGINF; sacc[j][2] = sv; tmax1 = fmaxf(tmax1, sv);
                    sv = (kg1 <= qg1) ? sacc[j][3] * scale : NEGINF; sacc[j][3] = sv; tmax1 = fmaxf(tmax1, sv);
                }
            }
        } else if (kt == qt - 2) {
            // window || lm (causal dropped)
#pragma unroll
            for (int j = 0; j < 8; j++) {
                int kk0 = j * 8 + colb, kk1 = kk0 + 1;
                int kg0 = k0 + kk0, kg1 = kg0 + 1;
                int lmv0 = lms[kk0], lmv1 = lms[kk1];
                float sv;
                bool ok;
                ok = ((qg0 - kg0) < WIN) || lmv0;
                sv = ok ? sacc[j][0] * scale : NEGINF; sacc[j][0] = sv; tmax0 = fmaxf(tmax0, sv);
                ok = ((qg0 - kg1) < WIN) || lmv1;
                sv = ok ? sacc[j][1] * scale : NEGINF; sacc[j][1] = sv; tmax0 = fmaxf(tmax0, sv);
                ok = ((qg1 - kg0) < WIN) || lmv0;
                sv = ok ? sacc[j][2] * scale : NEGINF; sacc[j][2] = sv; tmax1 = fmaxf(tmax1, sv);
                ok = ((qg1 - kg1) < WIN) || lmv1;
                sv = ok ? sacc[j][3] * scale : NEGINF; sacc[j][3] = sv; tmax1 = fmaxf(tmax1, sv);
            }
        } else {
            // lm only (causal true, window false)
#pragma unroll
            for (int j = 0; j < 8; j++) {
                int kk0 = j * 8 + colb, kk1 = kk0 + 1;
                int lmv0 = lms[kk0], lmv1 = lms[kk1];
                float sv;
                sv = lmv0 ? sacc[j][0] * scale : NEGINF; sacc[j][0] = sv; tmax0 = fmaxf(tmax0, sv);
                sv = lmv1 ? sacc[j][1] * scale : NEGINF; sacc[j][1] = sv; tmax0 = fmaxf(tmax0, sv);
                sv = lmv0 ? sacc[j][2] * scale : NEGINF; sacc[j][2] = sv; tmax1 = fmaxf(tmax1, sv);
                sv = lmv1 ? sacc[j][3] * scale : NEGINF; sacc[j][3] = sv; tmax1 = fmaxf(tmax1, sv);
            }
        }
        tmax0 = fmaxf(tmax0, __shfl_xor_sync(0xffffffffu, tmax0, 1));
        tmax0 = fmaxf(tmax0, __shfl_xor_sync(0xffffffffu, tmax0, 2));
        tmax1 = fmaxf(tmax1, __shfl_xor_sync(0xffffffffu, tmax1, 1));
        tmax1 = fmaxf(tmax1, __shfl_xor_sync(0xffffffffu, tmax1, 2));

        float mn0 = fmaxf(m0r, tmax0), mn1 = fmaxf(m1r, tmax1);
        float alp0 = (m0r == mn0) ? 1.0f : ex2f(m0r - mn0);
        float alp1 = (m1r == mn1) ? 1.0f : ex2f(m1r - mn1);

        uint32_t ph[8][2], pl[8][2];
        float rs0 = 0.0f, rs1 = 0.0f;
#pragma unroll
        for (int j = 0; j < 8; j++) {
            if (j <= jmax) {
                float p0 = (sacc[j][0] == NEGINF) ? 0.0f : ex2f(sacc[j][0] - mn0);
                float p1 = (sacc[j][1] == NEGINF) ? 0.0f : ex2f(sacc[j][1] - mn0);
                float p2 = (sacc[j][2] == NEGINF) ? 0.0f : ex2f(sacc[j][2] - mn1);
                float p3 = (sacc[j][3] == NEGINF) ? 0.0f : ex2f(sacc[j][3] - mn1);
                rs0 += p0 + p1; rs1 += p2 + p3;
                float h0 = __bfloat162float(__float2bfloat16(p0));
                float h1 = __bfloat162float(__float2bfloat16(p1));
                float h2 = __bfloat162float(__float2bfloat16(p2));
                float h3 = __bfloat162float(__float2bfloat16(p3));
                ph[j][0] = pack_bf16(h0, h1);
                ph[j][1] = pack_bf16(h2, h3);
                pl[j][0] = pack_bf16(p0 - h0, p1 - h1);
                pl[j][1] = pack_bf16(p2 - h2, p3 - h3);
            } else {
                ph[j][0] = ph[j][1] = pl[j][0] = pl[j][1] = 0u;
            }
        }
        rs0 += __shfl_xor_sync(0xffffffffu, rs0, 1);
        rs0 += __shfl_xor_sync(0xffffffffu, rs0, 2);
        rs1 += __shfl_xor_sync(0xffffffffu, rs1, 1);
        rs1 += __shfl_xor_sync(0xffffffffu, rs1, 2);

        l0r = l0r * alp0 + rs0;
        l1r = l1r * alp1 + rs1;
        m0r = mn0; m1r = mn1;
#pragma unroll
        for (int jo = 0; jo < 16; jo++) {
            oacc[jo][0] *= alp0; oacc[jo][1] *= alp0;
            oacc[jo][2] *= alp1; oacc[jo][3] *= alp1;
        }

        uint32_t vh_s = kvb + 32768u, vl_s = kvb + 49152u;
#pragma unroll
        for (int t = 0; t < 4; t++) {
            if (t <= gmax) {
                uint32_t a0h = ph[2 * t][0], a1h = ph[2 * t][1];
                uint32_t a2h = ph[2 * t + 1][0], a3h = ph[2 * t + 1][1];
                uint32_t a0l = pl[2 * t][0], a1l = pl[2 * t][1];
                uint32_t a2l = pl[2 * t + 1][0], a3l = pl[2 * t + 1][1];
                int r = t * 16 + rV0;
                int rsw = r & 7;
                uint32_t rbase = (uint32_t)((r >> 3) * 1024 + rsw * 128);
#pragma unroll
                for (int gg = 0; gg < 8; gg++) {
                    int sub = gg >> 2;
                    int c = (gg & 3) * 2 + (lane >> 4);
                    uint32_t off = (uint32_t)(sub * 8192) + rbase + (uint32_t)((c ^ rsw) << 4);
                    uint32_t v0, v1, v2, v3, w0, w1, w2, w3;
                    LDSM4T(v0, v1, v2, v3, vh_s + off);
                    LDSM4T(w0, w1, w2, w3, vl_s + off);
                    MMA16816(oacc[gg * 2],     a0h, a1h, a2h, a3h, v0, v1);
                    MMA16816(oacc[gg * 2],     a0l, a1l, a2l, a3l, v0, v1);
                    MMA16816(oacc[gg * 2],     a0h, a1h, a2h, a3h, w0, w1);
                    MMA16816(oacc[gg * 2 + 1], a0h, a1h, a2h, a3h, v2, v3);
                    MMA16816(oacc[gg * 2 + 1], a0l, a1l, a2l, a3l, v2, v3);
                    MMA16816(oacc[gg * 2 + 1], a0h, a1h, a2h, a3h, w2, w3);
                }
            }
        }
    }

    float inv0 = 1.0f / l0r, inv1 = 1.0f / l1r;
    int h_w = kvh * 2 + (wid >> 2);
    size_t r0 = (size_t)(b * SS + qg0) * HIDN + (size_t)h_w * DH + (lane & 3) * 2;
    size_t r1 = (size_t)(b * SS + qg1) * HIDN + (size_t)h_w * DH + (lane & 3) * 2;
#pragma unroll
    for (int jo = 0; jo < 16; jo++) {
        int cofs = jo * 8;
        store_split2(ah_g + r0 + cofs, al_g + r0 + cofs, oacc[jo][0] * inv0, oacc[jo][1] * inv0);
        store_split2(ah_g + r1 + cofs, al_g + r1 + cofs, oacc[jo][2] * inv1, oacc[jo][3] * inv1);
    }
}

// ---------------- launch ----------------
extern "C" void kernel_launch(void* const* d_in, const int* in_sizes, int n_in,
                              void* d_out, int out_size)
{
    (void)in_sizes; (void)n_in; (void)out_size;
    const float* x  = (const float*)d_in[0];
    const float* Wq = (const float*)d_in[1];
    const float* Wk = (const float*)d_in[2];
    const float* Wv = (const float*)d_in[3];
    const float* Wo = (const float*)d_in[4];
    float* out = (float*)d_out;

    void *lmp, *xh, *xl, *qh, *ql, *kh, *kl, *vh, *vl, *ah, *al;
    void *wch, *wcl, *woh, *wol;
    cudaGetSymbolAddress(&lmp, g_lm);
    cudaGetSymbolAddress(&xh, g_xh);   cudaGetSymbolAddress(&xl, g_xl);
    cudaGetSymbolAddress(&qh, g_qh);   cudaGetSymbolAddress(&ql, g_ql);
    cudaGetSymbolAddress(&kh, g_kh);   cudaGetSymbolAddress(&kl, g_kl);
    cudaGetSymbolAddress(&vh, g_vh);   cudaGetSymbolAddress(&vl, g_vl);
    cudaGetSymbolAddress(&ah, g_ah);   cudaGetSymbolAddress(&al, g_al);
    cudaGetSymbolAddress(&wch, g_wch); cudaGetSymbolAddress(&wcl, g_wcl);
    cudaGetSymbolAddress(&woh, g_woh); cudaGetSymbolAddress(&wol, g_wol);

    static cudaStream_t s_side = nullptr;
    static cudaEvent_t  e_fork = nullptr, e_xsp = nullptr, e_join = nullptr;
    if (s_side == nullptr) {
        cudaStreamCreateWithFlags(&s_side, cudaStreamNonBlocking);
        cudaEventCreateWithFlags(&e_fork, cudaEventDisableTiming);
        cudaEventCreateWithFlags(&e_xsp,  cudaEventDisableTiming);
        cudaEventCreateWithFlags(&e_join, cudaEventDisableTiming);
    }

    cudaFuncSetAttribute((const void*)gemm_kernel<0, 48>, cudaFuncAttributeMaxDynamicSharedMemorySize, GEMM_SMEM_BYTES);
    cudaFuncSetAttribute((const void*)gemm_kernel<1, 96>, cudaFuncAttributeMaxDynamicSharedMemorySize, GEMM_SMEM_BYTES);
    cudaFuncSetAttribute((const void*)attn_mma_kernel,    cudaFuncAttributeMaxDynamicSharedMemorySize, ATT_SMEM);

    // ---- fork: xsplit first (QKV dependency), then Wo prep + TLS chain, on side ----
    cudaEventRecord(e_fork, 0);
    cudaStreamWaitEvent(s_side, e_fork, 0);

    xsplit_kernel<<<(MTOT * HIDN) / 1024, 256, 0, s_side>>>(x, (__nv_bfloat16*)xh, (__nv_bfloat16*)xl);
    cudaEventRecord(e_xsp, s_side);
    wsplit_wo_kernel<<<dim3(64, KDIM / 32), dim3(32, 8), 0, s_side>>>(
        Wo, (__nv_bfloat16*)woh, (__nv_bfloat16*)wol, out);
    meanp_kernel      <<<dim3(HIDN / 256, BB, 8), 256, 0, s_side>>>(x);
    meanf_mnorm_kernel<<<BB, 256, 0, s_side>>>();
    score_kernel      <<<dim3(SS, BB), 256, 0, s_side>>>(x);
    topk_kernel       <<<BB, 1024, 0, s_side>>>();
    cudaEventRecord(e_join, s_side);

    // ---- main stream: QKV weight prep (concurrent with xsplit/TLS) ----
    wsplit_qkv_kernel<<<dim3(64, KDIM / 32, 3), dim3(32, 8)>>>(
        Wq, Wk, Wv, (__nv_bfloat16*)wch, (__nv_bfloat16*)wcl);

    // ---- QKV projection (needs xsplit) ----
    cudaStreamWaitEvent(0, e_xsp, 0);
    gemm_kernel<1, 96><<<dim3(NQKV / 128, MTOT / 128), 256, GEMM_SMEM_BYTES>>>(
        (const __nv_bfloat16*)xh, (const __nv_bfloat16*)xl,
        (__nv_bfloat16*)wch, (__nv_bfloat16*)wcl,
        nullptr,
        (__nv_bfloat16*)qh, (__nv_bfloat16*)ql,
        (__nv_bfloat16*)kh, (__nv_bfloat16*)kl,
        (__nv_bfloat16*)vh, (__nv_bfloat16*)vl);

    // ---- join: attention needs the landmark mask (and out is zeroed by now) ----
    cudaStreamWaitEvent(0, e_join, 0);

    attn_mma_kernel<<<dim3(BB * NKVH, SS / 64), 256, ATT_SMEM>>>(
        (const __nv_bfloat16*)qh, (const __nv_bfloat16*)ql,
        (const __nv_bfloat16*)kh, (const __nv_bfloat16*)kl,
        (const __nv_bfloat16*)vh, (const __nv_bfloat16*)vl,
        (const int*)lmp, (__nv_bfloat16*)ah, (__nv_bfloat16*)al);

    // ---- output projection: split-K2, deterministic vector red.add ----
    gemm_kernel<0, 48><<<dim3(HIDN / 128, MTOT / 128, 2), 256, GEMM_SMEM_BYTES>>>(
        (const __nv_bfloat16*)ah, (const __nv_bfloat16*)al,
        (const __nv_bfloat16*)woh, (const __nv_bfloat16*)wol,
        out, nullptr, nullptr, nullptr, nullptr, nullptr, nullptr);
}